// round 6
// baseline (speedup 1.0000x reference)
#include <cuda_runtime.h>
#include <math.h>
#include <stdint.h>

#define N_    4096
#define E_    131072
#define FEAT_ 64
#define HID_  256
#define NEG_  (-1e9f)
#define KCHUNKS_ 4
#define KCHUNK_  (N_ / KCHUNKS_)

// ---------------- scratch ----------------
__device__ float g_h0 [N_*HID_];
__device__ float g_x  [N_*HID_];
__device__ float g_hl [N_*HID_];
__device__ float g_xg [N_*HID_];
__device__ float g_sup[N_*2*HID_];
__device__ float g_q  [N_*HID_];
__device__ float g_k  [N_*HID_];
__device__ float g_v  [N_*HID_];
__device__ float g_vt [HID_*N_];
__device__ float g_qb [N_*HID_], g_qs [N_*HID_];
__device__ float g_kb [N_*HID_], g_ks [N_*HID_];
__device__ float g_vtb[HID_*N_], g_vts[HID_*N_];
__device__ float g_hms[N_*HID_];
__device__ float g_part[(size_t)KCHUNKS_*N_*HID_];
__device__ float g_S  [(size_t)N_*N_];
__device__ float g_Sb [(size_t)N_*N_];
__device__ float g_Ss [(size_t)N_*N_];
__device__ float g_el [N_*4];
__device__ float g_er [N_*4];
__device__ float g_y  [N_];
__device__ float g_xyz0[N_*3];
__device__ float g_xyz1[N_*3];
__device__ float g_xs[N_], g_ys[N_], g_zs[N_];
__device__ int   g_cnt[N_];
__device__ int   g_rowptr[N_+1];
__device__ int   g_cur[N_];
__device__ int   g_psrc[E_];
__device__ int   g_maskmode;

// ---------------- helpers ----------------
__device__ __forceinline__ uint32_t f2tf(float f) {
    uint32_t r; asm("cvt.rna.tf32.f32 %0, %1;" : "=r"(r) : "f"(f)); return r;
}
__device__ __forceinline__ void mma8(float* c, const uint32_t* a, const uint32_t* b) {
    asm volatile("mma.sync.aligned.m16n8k8.row.col.f32.tf32.tf32.f32 "
        "{%0,%1,%2,%3}, {%4,%5,%6,%7}, {%8,%9}, {%0,%1,%2,%3};"
        : "+f"(c[0]), "+f"(c[1]), "+f"(c[2]), "+f"(c[3])
        : "r"(a[0]), "r"(a[1]), "r"(a[2]), "r"(a[3]), "r"(b[0]), "r"(b[1]));
}

__global__ void detect_mask_mode(const unsigned int* __restrict__ m) {
    bool allbin = true, anyfloat = false;
    for (int i = 0; i < 1024; i++) {
        unsigned int w = m[i];
        if (w == 0x3f800000u) anyfloat = true;
        if (w > 1u) allbin = false;
    }
    g_maskmode = anyfloat ? 2 : (allbin ? 1 : 0);
}
__device__ __forceinline__ bool mask_at(const void* p, size_t i, int mode) {
    if (mode == 0) return ((const unsigned char*)p)[i] != 0;
    if (mode == 1) return ((const int*)p)[i] != 0;
    return ((const float*)p)[i] != 0.0f;
}

// split X into tf32 big + small parts (exact count = grid*256*4 elements)
__global__ void split_tf32(const float* __restrict__ X, float* __restrict__ Xb,
                           float* __restrict__ Xs)
{
    int i = blockIdx.x * blockDim.x + threadIdx.x;
    float4 x = *(const float4*)&X[(size_t)i*4];
    float4 xb, xs;
    uint32_t u;
    u = f2tf(x.x); xb.x = __uint_as_float(u); xs.x = __uint_as_float(f2tf(x.x - xb.x));
    u = f2tf(x.y); xb.y = __uint_as_float(u); xs.y = __uint_as_float(f2tf(x.y - xb.y));
    u = f2tf(x.z); xb.z = __uint_as_float(u); xs.z = __uint_as_float(f2tf(x.z - xb.z));
    u = f2tf(x.w); xb.w = __uint_as_float(u); xs.w = __uint_as_float(f2tf(x.w - xb.w));
    *(float4*)&Xb[(size_t)i*4] = xb;
    *(float4*)&Xs[(size_t)i*4] = xs;
}

// ================= 64x64x16 SGEMM (small-N GEMMs; full epilogue + opt transpose) ========
__global__ void sgemm64(const float* __restrict__ A, const float* __restrict__ B,
                        float* __restrict__ C, float* __restrict__ CT,
                        int M, int Nc, int K,
                        const float* __restrict__ bias, int relu, float cacc,
                        const float* __restrict__ X1, float c1,
                        const float* __restrict__ X2, float c2,
                        const float* __restrict__ X3, float c3,
                        float* __restrict__ C2)
{
    __shared__ __align__(16) float As[16][68];
    __shared__ __align__(16) float Bs[16][68];
    const int t  = threadIdx.x;
    const int tx = t & 15, ty = t >> 4;
    const int m0 = blockIdx.y * 64, n0 = blockIdx.x * 64;
    const int ra = t >> 2, kq = t & 3;
    const int kr = t >> 4, nq = t & 15;

    float acc[4][4] = {};
    for (int k0 = 0; k0 < K; k0 += 16) {
        float4 a = *(const float4*)&A[(size_t)(m0 + ra) * K + k0 + kq * 4];
        As[kq*4+0][ra] = a.x; As[kq*4+1][ra] = a.y; As[kq*4+2][ra] = a.z; As[kq*4+3][ra] = a.w;
        float4 b = *(const float4*)&B[(size_t)(k0 + kr) * Nc + n0 + nq * 4];
        *(float4*)&Bs[kr][nq*4] = b;
        __syncthreads();
#pragma unroll
        for (int kk = 0; kk < 16; kk++) {
            float4 av = *(float4*)&As[kk][ty*4];
            float4 bv = *(float4*)&Bs[kk][tx*4];
            acc[0][0]=fmaf(av.x,bv.x,acc[0][0]); acc[0][1]=fmaf(av.x,bv.y,acc[0][1]);
            acc[0][2]=fmaf(av.x,bv.z,acc[0][2]); acc[0][3]=fmaf(av.x,bv.w,acc[0][3]);
            acc[1][0]=fmaf(av.y,bv.x,acc[1][0]); acc[1][1]=fmaf(av.y,bv.y,acc[1][1]);
            acc[1][2]=fmaf(av.y,bv.z,acc[1][2]); acc[1][3]=fmaf(av.y,bv.w,acc[1][3]);
            acc[2][0]=fmaf(av.z,bv.x,acc[2][0]); acc[2][1]=fmaf(av.z,bv.y,acc[2][1]);
            acc[2][2]=fmaf(av.z,bv.z,acc[2][2]); acc[2][3]=fmaf(av.z,bv.w,acc[2][3]);
            acc[3][0]=fmaf(av.w,bv.x,acc[3][0]); acc[3][1]=fmaf(av.w,bv.y,acc[3][1]);
            acc[3][2]=fmaf(av.w,bv.z,acc[3][2]); acc[3][3]=fmaf(av.w,bv.w,acc[3][3]);
        }
        __syncthreads();
    }
#pragma unroll
    for (int i = 0; i < 4; i++) {
        int m = m0 + ty*4 + i;
#pragma unroll
        for (int j = 0; j < 4; j++) {
            int n = n0 + tx*4 + j;
            size_t idx = (size_t)m * Nc + n;
            float v = cacc * acc[i][j];
            if (bias) v += bias[n];
            if (X1) v += c1 * X1[idx];
            if (X2) v += c2 * X2[idx];
            if (X3) v += c3 * X3[idx];
            if (relu) v = fmaxf(v, 0.0f);
            C[idx] = v;
            if (C2) C2[idx] = v;
            if (CT) CT[(size_t)n * M + m] = v;
        }
    }
}

// ================= tensor-core 128x128 3xTF32 core ==========================
// 256 thr = 8 warps (2 M x 4 N); warp tile 64x32; per-warp 4x4 m16n8k8 tiles.
#define TC_STAGE(ASB, BSB)                                                \
    _Pragma("unroll")                                                     \
    for (int kk = 0; kk < 16; kk += 8) {                                  \
        uint32_t af[4][4], bf[4][2];                                      \
        _Pragma("unroll")                                                 \
        for (int mt = 0; mt < 4; mt++) {                                  \
            const int r0 = wm64 + mt*16 + g;                              \
            af[mt][0] = __float_as_uint(ASB[r0  ][kk+tg  ]);              \
            af[mt][1] = __float_as_uint(ASB[r0+8][kk+tg  ]);              \
            af[mt][2] = __float_as_uint(ASB[r0  ][kk+tg+4]);              \
            af[mt][3] = __float_as_uint(ASB[r0+8][kk+tg+4]);              \
        }                                                                 \
        _Pragma("unroll")                                                 \
        for (int nt = 0; nt < 4; nt++) {                                  \
            const int c0 = wn32 + nt*8 + g;                               \
            bf[nt][0] = __float_as_uint(BSB[c0][kk+tg  ]);                \
            bf[nt][1] = __float_as_uint(BSB[c0][kk+tg+4]);                \
        }                                                                 \
        _Pragma("unroll")                                                 \
        for (int mt = 0; mt < 4; mt++)                                    \
            _Pragma("unroll")                                             \
            for (int nt = 0; nt < 4; nt++)                                \
                mma8(cacc[mt][nt], af[mt], bf[nt]);                       \
    }

// scores: S = mask ? ((Q.K^T)/16 - |dy|) : NEG  via 3xTF32
__global__ __launch_bounds__(256) void scores_tc(
    const float* __restrict__ qb, const float* __restrict__ qs,
    const float* __restrict__ kb, const float* __restrict__ ks,
    const float* __restrict__ xyz,
    const void* __restrict__ dmask, const void* __restrict__ bmask,
    float* __restrict__ S)
{
    __shared__ __align__(16) float As[2][128][20];
    __shared__ __align__(16) float Bs[2][128][20];
    __shared__ float xj3[128][3], sqi[128], sqj[128], yi[128], yj[128];
    __shared__ float xi3[128][3];
    const int t = threadIdx.x;
    const int lane = t & 31, wid = t >> 5;
    const int g = lane >> 2, tg = lane & 3;
    const int wm64 = (wid >> 2) * 64, wn32 = (wid & 3) * 32;
    const int i0 = blockIdx.y * 128, j0 = blockIdx.x * 128;
    const int lr = t >> 2, lc4 = (t & 3) * 4;

    if (t < 128) {
        float a = xyz[(i0+t)*3+0], b = xyz[(i0+t)*3+1], c = xyz[(i0+t)*3+2];
        xi3[t][0]=a; xi3[t][1]=b; xi3[t][2]=c;
        sqi[t] = fmaf(c,c,fmaf(b,b,a*a));
        yi[t]  = g_y[i0+t];
    } else {
        int u = t - 128;
        float a = xyz[(j0+u)*3+0], b = xyz[(j0+u)*3+1], c = xyz[(j0+u)*3+2];
        xj3[u][0]=a; xj3[u][1]=b; xj3[u][2]=c;
        sqj[u] = fmaf(c,c,fmaf(b,b,a*a));
        yj[u]  = g_y[j0+u];
    }

    float cacc[4][4][4] = {};

    const float* Aps[3] = { qb, qb, qs };
    const float* Bps[3] = { kb, ks, kb };
#pragma unroll 1
    for (int p = 0; p < 3; p++) {
        const float* Ap = Aps[p];
        const float* Bp = Bps[p];
        float4 ra0 = *(const float4*)&Ap[(size_t)(i0 + lr) * HID_ + lc4];
        float4 ra1 = *(const float4*)&Ap[(size_t)(i0 + lr + 64) * HID_ + lc4];
        float4 rb0 = *(const float4*)&Bp[(size_t)(j0 + lr) * HID_ + lc4];
        float4 rb1 = *(const float4*)&Bp[(size_t)(j0 + lr + 64) * HID_ + lc4];
        *(float4*)&As[0][lr][lc4] = ra0; *(float4*)&As[0][lr+64][lc4] = ra1;
        *(float4*)&Bs[0][lr][lc4] = rb0; *(float4*)&Bs[0][lr+64][lc4] = rb1;
        __syncthreads();
        for (int s = 0; s < 16; s++) {
            const int buf = s & 1;
            if (s + 1 < 16) {
                const int k0 = (s + 1) * 16;
                ra0 = *(const float4*)&Ap[(size_t)(i0 + lr) * HID_ + k0 + lc4];
                ra1 = *(const float4*)&Ap[(size_t)(i0 + lr + 64) * HID_ + k0 + lc4];
                rb0 = *(const float4*)&Bp[(size_t)(j0 + lr) * HID_ + k0 + lc4];
                rb1 = *(const float4*)&Bp[(size_t)(j0 + lr + 64) * HID_ + k0 + lc4];
            }
            TC_STAGE(As[buf], Bs[buf]);
            if (s + 1 < 16) {
                const int nb = buf ^ 1;
                *(float4*)&As[nb][lr][lc4] = ra0; *(float4*)&As[nb][lr+64][lc4] = ra1;
                *(float4*)&Bs[nb][lr][lc4] = rb0; *(float4*)&Bs[nb][lr+64][lc4] = rb1;
                __syncthreads();
            }
        }
        __syncthreads();
    }

    const int mode = g_maskmode;
#pragma unroll
    for (int mt = 0; mt < 4; mt++) {
#pragma unroll
        for (int hh = 0; hh < 2; hh++) {
            const int li = wm64 + mt*16 + g + 8*hh;
            const int gi = i0 + li;
            const float xa = xi3[li][0], xb = xi3[li][1], xc = xi3[li][2];
            const float sqa = sqi[li], ya = yi[li];
            const size_t rb = (size_t)gi * N_;
#pragma unroll
            for (int nt = 0; nt < 4; nt++) {
                const int lj = wn32 + nt*8 + 2*tg;
                float2 r;
#pragma unroll
                for (int e = 0; e < 2; e++) {
                    const int ljj = lj + e;
                    const size_t idx = rb + j0 + ljj;
                    float dot = fmaf(xc, xj3[ljj][2], fmaf(xb, xj3[ljj][1], xa * xj3[ljj][0]));
                    float dist2 = (sqa + sqj[ljj]) - 2.0f * dot;
                    bool ok = mask_at(dmask, idx, mode) && mask_at(bmask, idx, mode) && (dist2 <= 100.0f);
                    float av = cacc[mt][nt][2*hh + e];
                    float sc = ok ? (av * 0.0625f - fabsf(ya - yj[ljj])) : NEG_;
                    if (e == 0) r.x = sc; else r.y = sc;
                }
                *(float2*)&S[rb + j0 + lj] = r;
            }
        }
    }
}

// attn@V partials via 3xTF32, split-K (blockIdx.z)
__global__ __launch_bounds__(256) void attnv_tc(
    const float* __restrict__ Sb, const float* __restrict__ Ss,
    const float* __restrict__ Vtb, const float* __restrict__ Vts,
    float* __restrict__ Cpart)
{
    __shared__ __align__(16) float As[2][128][20];
    __shared__ __align__(16) float Bs[2][128][20];
    const int t = threadIdx.x;
    const int lane = t & 31, wid = t >> 5;
    const int g = lane >> 2, tg = lane & 3;
    const int wm64 = (wid >> 2) * 64, wn32 = (wid & 3) * 32;
    const int m0 = blockIdx.y * 128, n0 = blockIdx.x * 128;
    const int kbase = blockIdx.z * KCHUNK_;
    const int lr = t >> 2, lc4 = (t & 3) * 4;

    float cacc[4][4][4] = {};

    const float* Aps[3] = { Sb, Sb, Ss };
    const float* Bps[3] = { Vtb, Vts, Vtb };
#pragma unroll 1
    for (int p = 0; p < 3; p++) {
        const float* Ap = Aps[p];
        const float* Bp = Bps[p];
        float4 ra0 = *(const float4*)&Ap[(size_t)(m0 + lr) * N_ + kbase + lc4];
        float4 ra1 = *(const float4*)&Ap[(size_t)(m0 + lr + 64) * N_ + kbase + lc4];
        float4 rb0 = *(const float4*)&Bp[(size_t)(n0 + lr) * N_ + kbase + lc4];
        float4 rb1 = *(const float4*)&Bp[(size_t)(n0 + lr + 64) * N_ + kbase + lc4];
        *(float4*)&As[0][lr][lc4] = ra0; *(float4*)&As[0][lr+64][lc4] = ra1;
        *(float4*)&Bs[0][lr][lc4] = rb0; *(float4*)&Bs[0][lr+64][lc4] = rb1;
        __syncthreads();
        const int nst = KCHUNK_ / 16;
        for (int s = 0; s < nst; s++) {
            const int buf = s & 1;
            if (s + 1 < nst) {
                const int k0 = kbase + (s + 1) * 16;
                ra0 = *(const float4*)&Ap[(size_t)(m0 + lr) * N_ + k0 + lc4];
                ra1 = *(const float4*)&Ap[(size_t)(m0 + lr + 64) * N_ + k0 + lc4];
                rb0 = *(const float4*)&Bp[(size_t)(n0 + lr) * N_ + k0 + lc4];
                rb1 = *(const float4*)&Bp[(size_t)(n0 + lr + 64) * N_ + k0 + lc4];
            }
            TC_STAGE(As[buf], Bs[buf]);
            if (s + 1 < nst) {
                const int nb = buf ^ 1;
                *(float4*)&As[nb][lr][lc4] = ra0; *(float4*)&As[nb][lr+64][lc4] = ra1;
                *(float4*)&Bs[nb][lr][lc4] = rb0; *(float4*)&Bs[nb][lr+64][lc4] = rb1;
                __syncthreads();
            }
        }
        __syncthreads();
    }

    float* Cz = Cpart + (size_t)blockIdx.z * N_ * HID_;
#pragma unroll
    for (int mt = 0; mt < 4; mt++) {
#pragma unroll
        for (int hh = 0; hh < 2; hh++) {
            const int m = m0 + wm64 + mt*16 + g + 8*hh;
            const size_t rb = (size_t)m * HID_;
#pragma unroll
            for (int nt = 0; nt < 4; nt++) {
                const int n = n0 + wn32 + nt*8 + 2*tg;
                float2 r = { cacc[mt][nt][2*hh], cacc[mt][nt][2*hh + 1] };
                *(float2*)&Cz[rb + n] = r;
            }
        }
    }
}

__global__ void combine_parts(const float* __restrict__ P, float* __restrict__ C)
{
    int i = blockIdx.x * blockDim.x + threadIdx.x;
    const size_t n = (size_t)N_ * HID_;
    float4 a = *(const float4*)&P[(size_t)i*4];
    float4 b = *(const float4*)&P[n + (size_t)i*4];
    float4 c = *(const float4*)&P[2*n + (size_t)i*4];
    float4 d = *(const float4*)&P[3*n + (size_t)i*4];
    float4 r = { a.x+b.x+c.x+d.x, a.y+b.y+c.y+d.y, a.z+b.z+c.z+d.z, a.w+b.w+c.w+d.w };
    *(float4*)&C[(size_t)i*4] = r;
}

// ---------------- softmax + attn@xyz fused + tf32 split of attn ----------------
__global__ void softmax_xyz(const float* __restrict__ S,
                            float* __restrict__ Sb, float* __restrict__ Ss,
                            const float* __restrict__ xs, const float* __restrict__ ys,
                            const float* __restrict__ zs, float* __restrict__ out)
{
    __shared__ float r0[256], r1[256], r2[256];
    const int row = blockIdx.x, t = threadIdx.x;
    const float* p = S + (size_t)row * N_;
    float4 v[4];
    float mx = -1e30f;
#pragma unroll
    for (int c = 0; c < 4; c++) {
        v[c] = *(const float4*)&p[c*1024 + t*4];
        mx = fmaxf(mx, fmaxf(fmaxf(v[c].x, v[c].y), fmaxf(v[c].z, v[c].w)));
    }
    r0[t] = mx; __syncthreads();
    for (int s = 128; s > 0; s >>= 1) { if (t < s) r0[t] = fmaxf(r0[t], r0[t+s]); __syncthreads(); }
    mx = r0[0]; __syncthreads();
    float sum = 0.0f;
#pragma unroll
    for (int c = 0; c < 4; c++) {
        v[c].x = expf(v[c].x - mx); v[c].y = expf(v[c].y - mx);
        v[c].z = expf(v[c].z - mx); v[c].w = expf(v[c].w - mx);
        sum += v[c].x + v[c].y + v[c].z + v[c].w;
    }
    r0[t] = sum; __syncthreads();
    for (int s = 128; s > 0; s >>= 1) { if (t < s) r0[t] += r0[t+s]; __syncthreads(); }
    const float inv = 1.0f / r0[0];
    __syncthreads();
    float a0 = 0.f, a1 = 0.f, a2 = 0.f;
#pragma unroll
    for (int c = 0; c < 4; c++) {
        v[c].x *= inv; v[c].y *= inv; v[c].z *= inv; v[c].w *= inv;
        // split into tf32 big/small and store
        float4 vb, vs;
        vb.x = __uint_as_float(f2tf(v[c].x)); vs.x = __uint_as_float(f2tf(v[c].x - vb.x));
        vb.y = __uint_as_float(f2tf(v[c].y)); vs.y = __uint_as_float(f2tf(v[c].y - vb.y));
        vb.z = __uint_as_float(f2tf(v[c].z)); vs.z = __uint_as_float(f2tf(v[c].z - vb.z));
        vb.w = __uint_as_float(f2tf(v[c].w)); vs.w = __uint_as_float(f2tf(v[c].w - vb.w));
        const size_t off = (size_t)row * N_ + c*1024 + t*4;
        *(float4*)&Sb[off] = vb;
        *(float4*)&Ss[off] = vs;
        const int j = c*1024 + t*4;
        a0 = fmaf(v[c].x, xs[j], fmaf(v[c].y, xs[j+1], fmaf(v[c].z, xs[j+2], fmaf(v[c].w, xs[j+3], a0))));
        a1 = fmaf(v[c].x, ys[j], fmaf(v[c].y, ys[j+1], fmaf(v[c].z, ys[j+2], fmaf(v[c].w, ys[j+3], a1))));
        a2 = fmaf(v[c].x, zs[j], fmaf(v[c].y, zs[j+1], fmaf(v[c].z, zs[j+2], fmaf(v[c].w, zs[j+3], a2))));
    }
    r0[t]=a0; r1[t]=a1; r2[t]=a2; __syncthreads();
    for (int s = 128; s > 0; s >>= 1) {
        if (t < s) { r0[t]+=r0[t+s]; r1[t]+=r1[t+s]; r2[t]+=r2[t+s]; }
        __syncthreads();
    }
    if (t == 0) { out[row*3+0]=r0[0]; out[row*3+1]=r1[0]; out[row*3+2]=r2[0]; }
}

__global__ void xyz2soa(const float* __restrict__ xyz, float* __restrict__ xs,
                        float* __restrict__ ys, float* __restrict__ zs)
{
    int i = blockIdx.x * blockDim.x + threadIdx.x;
    if (i < N_) { xs[i] = xyz[3*i]; ys[i] = xyz[3*i+1]; zs[i] = xyz[3*i+2]; }
}

// ---------------- GAT pieces ----------------
__global__ void compute_elr(const float* __restrict__ hl, const float* __restrict__ al,
                            const float* __restrict__ ar)
{
    int idx = blockIdx.x * blockDim.x + threadIdx.x;
    if (idx >= N_*4) return;
    int node = idx >> 2, h = idx & 3;
    const float* row = hl + (size_t)node * HID_ + h * 64;
    float sl = 0.f, sr = 0.f;
#pragma unroll 8
    for (int d = 0; d < 64; d++) {
        float v = row[d];
        sl = fmaf(v, al[h*64+d], sl);
        sr = fmaf(v, ar[h*64+d], sr);
    }
    g_el[idx] = sl; g_er[idx] = sr;
}

__global__ void zero_cnt() { int i = blockIdx.x*blockDim.x + threadIdx.x; if (i < N_) g_cnt[i] = 0; }
__global__ void count_edges(const int* __restrict__ dst) {
    int e = blockIdx.x*blockDim.x + threadIdx.x; if (e < E_) atomicAdd(&g_cnt[dst[e]], 1);
}
__global__ void scan4096() {
    __shared__ int part[1024];
    int t = threadIdx.x, base = t * 4;
    int a0 = g_cnt[base], a1 = g_cnt[base+1], a2 = g_cnt[base+2], a3 = g_cnt[base+3];
    int s = a0 + a1 + a2 + a3;
    part[t] = s; __syncthreads();
    for (int off = 1; off < 1024; off <<= 1) {
        int v = (t >= off) ? part[t-off] : 0;
        __syncthreads();
        part[t] += v;
        __syncthreads();
    }
    int excl = part[t] - s;
    g_rowptr[base+0] = excl;           g_cur[base+0] = excl;
    g_rowptr[base+1] = excl+a0;        g_cur[base+1] = excl+a0;
    g_rowptr[base+2] = excl+a0+a1;     g_cur[base+2] = excl+a0+a1;
    g_rowptr[base+3] = excl+a0+a1+a2;  g_cur[base+3] = excl+a0+a1+a2;
    if (t == 1023) g_rowptr[4096] = part[1023];
}
__global__ void scatter_edges(const int* __restrict__ src, const int* __restrict__ dst) {
    int e = blockIdx.x*blockDim.x + threadIdx.x;
    if (e < E_) { int p = atomicAdd(&g_cur[dst[e]], 1); g_psrc[p] = src[e]; }
}

__global__ void gat_aggregate(const float* __restrict__ hl, float* __restrict__ xg)
{
    const int node = (blockIdx.x * blockDim.x + threadIdx.x) >> 5;
    const int lane = threadIdx.x & 31;
    if (node >= N_) return;
    const int beg = g_rowptr[node], end = g_rowptr[node+1];
    const float er_i = (lane < 4) ? g_er[node*4 + lane] : 0.f;
    float m = -1e30f;
    for (int p = beg; p < end; p++) {
        int s = g_psrc[p];
        if (lane < 4) {
            float v = g_el[s*4 + lane] + er_i;
            float e = (v > 0.f) ? v : 0.2f * v;
            m = fmaxf(m, e);
        }
    }
    float m0 = __shfl_sync(0xffffffffu, m, 0), m1 = __shfl_sync(0xffffffffu, m, 1);
    float m2 = __shfl_sync(0xffffffffu, m, 2), m3 = __shfl_sync(0xffffffffu, m, 3);
    const int myh = lane >> 3;
    float4 acc0 = {0,0,0,0}, acc1 = {0,0,0,0};
    float z = 0.f;
    for (int p = beg; p < end; p++) {
        int s = g_psrc[p];
        float w = 0.f;
        if (lane < 4) {
            float v = g_el[s*4 + lane] + er_i;
            float e = (v > 0.f) ? v : 0.2f * v;
            float mm = (lane==0)?m0:(lane==1)?m1:(lane==2)?m2:m3;
            w = expf(e - mm);
            z += w;
        }
        float w0 = __shfl_sync(0xffffffffu, w, 0), w1 = __shfl_sync(0xffffffffu, w, 1);
        float w2 = __shfl_sync(0xffffffffu, w, 2), w3 = __shfl_sync(0xffffffffu, w, 3);
        float wm = (myh==0)?w0:(myh==1)?w1:(myh==2)?w2:w3;
        const float4* hp = (const float4*)(hl + (size_t)s * HID_ + lane * 8);
        float4 hv0 = hp[0], hv1 = hp[1];
        acc0.x=fmaf(wm,hv0.x,acc0.x); acc0.y=fmaf(wm,hv0.y,acc0.y);
        acc0.z=fmaf(wm,hv0.z,acc0.z); acc0.w=fmaf(wm,hv0.w,acc0.w);
        acc1.x=fmaf(wm,hv1.x,acc1.x); acc1.y=fmaf(wm,hv1.y,acc1.y);
        acc1.z=fmaf(wm,hv1.z,acc1.z); acc1.w=fmaf(wm,hv1.w,acc1.w);
    }
    float z0 = __shfl_sync(0xffffffffu, z, 0), z1 = __shfl_sync(0xffffffffu, z, 1);
    float z2 = __shfl_sync(0xffffffffu, z, 2), z3 = __shfl_sync(0xffffffffu, z, 3);
    float zm = (myh==0)?z0:(myh==1)?z1:(myh==2)?z2:z3;
    float inv = 1.0f / (zm + 1e-9f);
    acc0.x*=inv; acc0.y*=inv; acc0.z*=inv; acc0.w*=inv;
    acc1.x*=inv; acc1.y*=inv; acc1.z*=inv; acc1.w*=inv;
    float4* op = (float4*)(xg + (size_t)node * HID_ + lane * 8);
    op[0] = acc0; op[1] = acc1;
}

__global__ void pack_support(const float* __restrict__ xg, const float* __restrict__ h0,
                             float* __restrict__ sup)
{
    int i = blockIdx.x * blockDim.x + threadIdx.x;
    if (i >= N_ * 512) return;
    int r = i >> 9, c = i & 511;
    sup[i] = (c < 256) ? xg[(size_t)r*256 + c] : h0[(size_t)r*256 + (c-256)];
}

__global__ void yhat_k(const float* __restrict__ x, const float* __restrict__ W,
                       const float* __restrict__ b)
{
    int i = blockIdx.x * blockDim.x + threadIdx.x;
    if (i >= N_) return;
    const float* r = x + (size_t)i * HID_;
    float l0 = b[0], l1 = b[1];
#pragma unroll 8
    for (int d = 0; d < HID_; d++) {
        float v = r[d];
        l0 = fmaf(v, W[2*d+0], l0);
        l1 = fmaf(v, W[2*d+1], l1);
    }
    g_y[i] = 1.0f / (1.0f + expf(l0 - l1));
}

__global__ void cls_k(const float* __restrict__ x, const float* __restrict__ W,
                      const float* __restrict__ b, float* __restrict__ out)
{
    int i = blockIdx.x * blockDim.x + threadIdx.x;
    if (i >= N_) return;
    const float* r = x + (size_t)i * HID_;
    float l0 = b[0], l1 = b[1];
#pragma unroll 8
    for (int d = 0; d < HID_; d++) {
        float v = r[d];
        l0 = fmaf(v, W[2*d+0], l0);
        l1 = fmaf(v, W[2*d+1], l1);
    }
    out[2*i+0] = l0;
    out[2*i+1] = l1;
}

// ---------------- host orchestration ----------------
extern "C" void kernel_launch(void* const* d_in, const int* in_sizes, int n_in,
                              void* d_out, int out_size)
{
    const float* feat   = (const float*)d_in[0];
    const float* xyz_in = (const float*)d_in[1];
    const int*   src    = (const int*)  d_in[2];
    const int*   dst    = (const int*)  d_in[3];
    const void*  dmask  = d_in[4];
    const void*  bmask  = d_in[5];
    const float* fcW  = (const float*)d_in[6];
    const float* fcb  = (const float*)d_in[7];
    const float* gatW = (const float*)d_in[8];
    const float* al   = (const float*)d_in[9];
    const float* ar   = (const float*)d_in[10];
    const float* gcW  = (const float*)d_in[11];
    const float* cgW  = (const float*)d_in[12];
    const float* cgb  = (const float*)d_in[13];
    const float* qW   = (const float*)d_in[14];
    const float* qb_  = (const float*)d_in[15];
    const float* kW   = (const float*)d_in[16];
    const float* kb_  = (const float*)d_in[17];
    const float* vW   = (const float*)d_in[18];
    const float* vb_  = (const float*)d_in[19];
    const float* oW   = (const float*)d_in[20];
    const float* ob   = (const float*)d_in[21];
    const float* clsW = (const float*)d_in[22];
    const float* clsb = (const float*)d_in[23];

    float *px, *ph0, *phl, *pxg, *psup, *pq, *pk, *pv, *pvt, *phms, *pS, *pSb, *pSs;
    float *pqb, *pqs, *pkb, *pks, *pvtb, *pvts;
    float *pxyz0, *pxyz1, *pxs, *pys, *pzs, *ppart;
    cudaGetSymbolAddress((void**)&px,    g_x);
    cudaGetSymbolAddress((void**)&ph0,   g_h0);
    cudaGetSymbolAddress((void**)&phl,   g_hl);
    cudaGetSymbolAddress((void**)&pxg,   g_xg);
    cudaGetSymbolAddress((void**)&psup,  g_sup);
    cudaGetSymbolAddress((void**)&pq,    g_q);
    cudaGetSymbolAddress((void**)&pk,    g_k);
    cudaGetSymbolAddress((void**)&pv,    g_v);
    cudaGetSymbolAddress((void**)&pvt,   g_vt);
    cudaGetSymbolAddress((void**)&phms,  g_hms);
    cudaGetSymbolAddress((void**)&pS,    g_S);
    cudaGetSymbolAddress((void**)&pSb,   g_Sb);
    cudaGetSymbolAddress((void**)&pSs,   g_Ss);
    cudaGetSymbolAddress((void**)&pqb,   g_qb);
    cudaGetSymbolAddress((void**)&pqs,   g_qs);
    cudaGetSymbolAddress((void**)&pkb,   g_kb);
    cudaGetSymbolAddress((void**)&pks,   g_ks);
    cudaGetSymbolAddress((void**)&pvtb,  g_vtb);
    cudaGetSymbolAddress((void**)&pvts,  g_vts);
    cudaGetSymbolAddress((void**)&pxyz0, g_xyz0);
    cudaGetSymbolAddress((void**)&pxyz1, g_xyz1);
    cudaGetSymbolAddress((void**)&pxs,   g_xs);
    cudaGetSymbolAddress((void**)&pys,   g_ys);
    cudaGetSymbolAddress((void**)&pzs,   g_zs);
    cudaGetSymbolAddress((void**)&ppart, g_part);

    detect_mask_mode<<<1, 1>>>((const unsigned int*)dmask);

    sgemm64<<<dim3(HID_/64, N_/64), 256>>>(feat, fcW, px, nullptr, N_, HID_, FEAT_,
                                           fcb, 1, 1.0f, nullptr,0.f, nullptr,0.f, nullptr,0.f, ph0);

    zero_cnt<<<N_/256, 256>>>();
    count_edges<<<E_/256, 256>>>(dst);
    scan4096<<<1, 1024>>>();
    scatter_edges<<<E_/256, 256>>>(src, dst);

    const float ALPHA = 0.1f, LAMDA = 0.5f;
    for (int l = 0; l < 4; l++) {
        sgemm64<<<dim3(HID_/64, N_/64), 256>>>(px, gatW + (size_t)l*HID_*HID_, phl, nullptr,
                                               N_, HID_, HID_, nullptr, 0, 1.0f,
                                               nullptr,0.f, nullptr,0.f, nullptr,0.f, nullptr);
        compute_elr<<<(N_*4)/256, 256>>>(phl, al + l*4*64, ar + l*4*64);
        gat_aggregate<<<N_/8, 256>>>(phl, pxg);
        pack_support<<<(N_*512)/256, 256>>>(pxg, ph0, psup);
        float theta = fminf(1.0f, logf(LAMDA / (float)(l + 1) + 1.0f));
        sgemm64<<<dim3(HID_/64, N_/64), 256>>>(psup, gcW + (size_t)l*512*HID_, px, nullptr,
                                               N_, HID_, 512, nullptr, 0, theta,
                                               pxg, (1.0f-theta)*(1.0f-ALPHA),
                                               ph0, (1.0f-theta)*ALPHA,
                                               px,  1.0f, nullptr);
    }

    yhat_k<<<N_/256, 256>>>(px, cgW, cgb);

    const float* xyz_cur = xyz_in;
    float* xyz_buf[2] = { pxyz0, pxyz1 };
    const int splitg = (N_*HID_/4)/256;   // 1024 blocks
    for (int l = 0; l < 4; l++) {
        sgemm64<<<dim3(HID_/64, N_/64), 256>>>(px, qW + (size_t)l*HID_*HID_, pq, nullptr,
                                               N_, HID_, HID_, qb_ + l*HID_, 0, 1.0f,
                                               nullptr,0.f, nullptr,0.f, nullptr,0.f, nullptr);
        sgemm64<<<dim3(HID_/64, N_/64), 256>>>(px, kW + (size_t)l*HID_*HID_, pk, nullptr,
                                               N_, HID_, HID_, kb_ + l*HID_, 0, 1.0f,
                                               nullptr,0.f, nullptr,0.f, nullptr,0.f, nullptr);
        sgemm64<<<dim3(HID_/64, N_/64), 256>>>(px, vW + (size_t)l*HID_*HID_, pv, pvt,
                                               N_, HID_, HID_, vb_ + l*HID_, 0, 1.0f,
                                               nullptr,0.f, nullptr,0.f, nullptr,0.f, nullptr);
        split_tf32<<<splitg, 256>>>(pq, pqb, pqs);
        split_tf32<<<splitg, 256>>>(pk, pkb, pks);
        split_tf32<<<splitg, 256>>>(pvt, pvtb, pvts);
        scores_tc<<<dim3(N_/128, N_/128), 256>>>(pqb, pqs, pkb, pks, xyz_cur, dmask, bmask, pS);
        xyz2soa<<<N_/256, 256>>>(xyz_cur, pxs, pys, pzs);
        softmax_xyz<<<N_, 256>>>(pS, pSb, pSs, pxs, pys, pzs, xyz_buf[l & 1]);
        attnv_tc<<<dim3(HID_/128, N_/128, KCHUNKS_), 256>>>(pSb, pSs, pvtb, pvts, ppart);
        combine_parts<<<(N_*HID_/4)/256, 256>>>(ppart, phms);
        sgemm64<<<dim3(HID_/64, N_/64), 256>>>(phms, oW + (size_t)l*HID_*HID_, px, nullptr,
                                               N_, HID_, HID_, ob + l*HID_, 0, 1.0f,
                                               px, 1.0f, nullptr,0.f, nullptr,0.f, nullptr);
        xyz_cur = xyz_buf[l & 1];
    }

    cls_k<<<N_/256, 256>>>(px, clsW, clsb, (float*)d_out);
}

// round 8
// speedup vs baseline: 1.4253x; 1.4253x over previous
#include <cuda_runtime.h>
#include <cuda_bf16.h>
#include <math.h>
#include <stdint.h>

#define N_    4096
#define E_    131072
#define FEAT_ 64
#define HID_  256
#define NEG_  (-1e9f)
#define KZ_   4

// ---------------- scratch ----------------
__device__ float g_h0 [N_*HID_];
__device__ float g_x  [N_*HID_];
__device__ float g_hl [N_*HID_];
__device__ float g_xg [N_*HID_];
__device__ float g_sup[N_*2*HID_];
__device__ float g_q  [N_*HID_];
__device__ float g_k  [N_*HID_];
__device__ float g_v  [N_*HID_];
__device__ float g_vt [HID_*N_];
__device__ float g_hms[N_*HID_];
__device__ float g_part[(size_t)KZ_*N_*HID_];
__device__ float g_S  [(size_t)N_*N_];
__device__ __nv_bfloat16 g_qb2[N_*HID_], g_qs2[N_*HID_];
__device__ __nv_bfloat16 g_kb2[N_*HID_], g_ks2[N_*HID_];
__device__ __nv_bfloat16 g_vtb2[HID_*N_], g_vts2[HID_*N_];
__device__ __nv_bfloat16 g_sb2[(size_t)N_*N_], g_ss2[(size_t)N_*N_];
__device__ float g_el [N_*4];
__device__ float g_er [N_*4];
__device__ float g_y  [N_];
__device__ float g_xyz0[N_*3];
__device__ float g_xyz1[N_*3];
__device__ float g_xs[N_], g_ys[N_], g_zs[N_];
__device__ int   g_cnt[N_];
__device__ int   g_rowptr[N_+1];
__device__ int   g_cur[N_];
__device__ int   g_psrc[E_];
__device__ int   g_maskmode;

// ---------------- helpers ----------------
__device__ __forceinline__ uint32_t smem_u32(const void* p) {
    uint32_t a;
    asm("{ .reg .u64 t; cvta.to.shared.u64 t, %1; cvt.u32.u64 %0, t; }" : "=r"(a) : "l"(p));
    return a;
}
#define LDMX4(r, a) \
    asm volatile("ldmatrix.sync.aligned.m8n8.x4.shared.b16 {%0,%1,%2,%3}, [%4];" \
        : "=r"((r)[0]), "=r"((r)[1]), "=r"((r)[2]), "=r"((r)[3]) : "r"(a))
#define MMA16816(c, a, b0, b1) \
    asm volatile("mma.sync.aligned.m16n8k16.row.col.f32.bf16.bf16.f32 " \
        "{%0,%1,%2,%3}, {%4,%5,%6,%7}, {%8,%9}, {%0,%1,%2,%3};" \
        : "+f"((c)[0]), "+f"((c)[1]), "+f"((c)[2]), "+f"((c)[3]) \
        : "r"((a)[0]), "r"((a)[1]), "r"((a)[2]), "r"((a)[3]), "r"(b0), "r"(b1))

__global__ void detect_mask_mode(const unsigned int* __restrict__ m) {
    bool allbin = true, anyfloat = false;
    for (int i = 0; i < 1024; i++) {
        unsigned int w = m[i];
        if (w == 0x3f800000u) anyfloat = true;
        if (w > 1u) allbin = false;
    }
    g_maskmode = anyfloat ? 2 : (allbin ? 1 : 0);
}
__device__ __forceinline__ bool mask_at(const void* p, size_t i, int mode) {
    if (mode == 0) return ((const unsigned char*)p)[i] != 0;
    if (mode == 1) return ((const int*)p)[i] != 0;
    return ((const float*)p)[i] != 0.0f;
}

__global__ void split_bf16(const float* __restrict__ X,
                           __nv_bfloat16* __restrict__ Xb, __nv_bfloat16* __restrict__ Xs)
{
    int i = blockIdx.x * blockDim.x + threadIdx.x;
    float4 x = *(const float4*)&X[(size_t)i*4];
    float xv[4] = {x.x, x.y, x.z, x.w};
    __align__(8) __nv_bfloat16 b[4], s[4];
#pragma unroll
    for (int e = 0; e < 4; e++) {
        b[e] = __float2bfloat16(xv[e]);
        s[e] = __float2bfloat16(xv[e] - __bfloat162float(b[e]));
    }
    *(uint2*)&Xb[(size_t)i*4] = *(uint2*)b;
    *(uint2*)&Xs[(size_t)i*4] = *(uint2*)s;
}

// ---- shared mma-core macro: one k32 chunk on a buffer pair ----
#define COMPUTE32(abase, bbase)                                                     \
    _Pragma("unroll")                                                               \
    for (int kk = 0; kk < 2; kk++) {                                                \
        uint32_t af[4][4], bfr[2][4];                                               \
        _Pragma("unroll")                                                           \
        for (int mt = 0; mt < 4; mt++) {                                            \
            uint32_t ad = (abase) + (uint32_t)((wr64 + mt*16 + a_r)*80 + kk*32 + a_c); \
            LDMX4(af[mt], ad);                                                      \
        }                                                                           \
        _Pragma("unroll")                                                           \
        for (int np = 0; np < 2; np++) {                                            \
            uint32_t bd = (bbase) + (uint32_t)((wc32 + np*16 + b_r)*80 + kk*32 + b_c); \
            LDMX4(bfr[np], bd);                                                     \
        }                                                                           \
        _Pragma("unroll")                                                           \
        for (int mt = 0; mt < 4; mt++)                                              \
            _Pragma("unroll")                                                       \
            for (int nt = 0; nt < 4; nt++)                                          \
                MMA16816(acc[mt][nt], af[mt], bfr[nt>>1][(nt&1)*2], bfr[nt>>1][(nt&1)*2+1]); \
    }

// ================= scores via bf16 mma: S = mask ? (QK^T/16 - |dy|) : NEG =================
// grid (N/128, N/128), 256 threads (8 warps, 2x4), 3-pass big/small split.
__global__ __launch_bounds__(256) void scores_mma(
    const __nv_bfloat16* __restrict__ qb, const __nv_bfloat16* __restrict__ qs,
    const __nv_bfloat16* __restrict__ kb, const __nv_bfloat16* __restrict__ ks,
    const float* __restrict__ xyz,
    const void* __restrict__ dmask, const void* __restrict__ bmask,
    float* __restrict__ S)
{
    __shared__ __align__(16) char Ash[2][128*80];
    __shared__ __align__(16) char Bsh[2][128*80];
    __shared__ float gix[128*3], gisq[128], giy[128];
    __shared__ float gjx[128*3], gjsq[128], gjy[128];
    const int t = threadIdx.x, lane = t & 31, wid = t >> 5;
    const int wr64 = (wid >> 2) * 64, wc32 = (wid & 3) * 32;
    const int g = lane >> 2, tg = lane & 3;
    const int a_r = ((lane >> 3) & 1) * 8 + (lane & 7);
    const int a_c = (lane >> 4) * 16;
    const int b_r = ((lane >> 4) & 1) * 8 + (lane & 7);
    const int b_c = ((lane >> 3) & 1) * 16;
    const int i0 = blockIdx.y * 128, j0 = blockIdx.x * 128;
    const int lrow = t >> 2, lq = t & 3;

    if (t < 128) {
        float a = xyz[(i0+t)*3+0], b = xyz[(i0+t)*3+1], c = xyz[(i0+t)*3+2];
        gix[t*3+0]=a; gix[t*3+1]=b; gix[t*3+2]=c;
        gisq[t] = fmaf(c,c,fmaf(b,b,a*a));
        giy[t]  = g_y[i0+t];
    } else {
        int u = t - 128;
        float a = xyz[(j0+u)*3+0], b = xyz[(j0+u)*3+1], c = xyz[(j0+u)*3+2];
        gjx[u*3+0]=a; gjx[u*3+1]=b; gjx[u*3+2]=c;
        gjsq[u] = fmaf(c,c,fmaf(b,b,a*a));
        gjy[u]  = g_y[j0+u];
    }

    uint32_t aS[2] = { smem_u32(Ash[0]), smem_u32(Ash[1]) };
    uint32_t bS[2] = { smem_u32(Bsh[0]), smem_u32(Bsh[1]) };
    float acc[4][4][4] = {};

    const __nv_bfloat16* APs[3] = { qb, qb, qs };
    const __nv_bfloat16* BPs[3] = { kb, ks, kb };

    uint4 va[2], vb[2];
#pragma unroll
    for (int r = 0; r < 2; r++) {
        int row = lrow + r*64;
        va[r] = *(const uint4*)(APs[0] + (size_t)(i0+row)*HID_ + lq*8);
        vb[r] = *(const uint4*)(BPs[0] + (size_t)(j0+row)*HID_ + lq*8);
    }
#pragma unroll
    for (int r = 0; r < 2; r++) {
        int row = lrow + r*64;
        *(uint4*)(Ash[0] + row*80 + lq*16) = va[r];
        *(uint4*)(Bsh[0] + row*80 + lq*16) = vb[r];
    }
    __syncthreads();

    const int NC = 24;   // 3 passes x 8 chunks of k32
    for (int c = 0; c < NC; c++) {
        const int buf = c & 1;
        if (c + 1 < NC) {
            const int p = (c+1) >> 3, kc = (c+1) & 7;
            const __nv_bfloat16* A = APs[p];
            const __nv_bfloat16* B = BPs[p];
#pragma unroll
            for (int r = 0; r < 2; r++) {
                int row = lrow + r*64;
                va[r] = *(const uint4*)(A + (size_t)(i0+row)*HID_ + kc*32 + lq*8);
                vb[r] = *(const uint4*)(B + (size_t)(j0+row)*HID_ + kc*32 + lq*8);
            }
        }
        COMPUTE32(aS[buf], bS[buf]);
        if (c + 1 < NC) {
            const int nb = buf ^ 1;
#pragma unroll
            for (int r = 0; r < 2; r++) {
                int row = lrow + r*64;
                *(uint4*)(Ash[nb] + row*80 + lq*16) = va[r];
                *(uint4*)(Bsh[nb] + row*80 + lq*16) = vb[r];
            }
            __syncthreads();
        }
    }

    const int mode = g_maskmode;
#pragma unroll
    for (int mt = 0; mt < 4; mt++) {
#pragma unroll
        for (int h = 0; h < 2; h++) {
            const int li = wr64 + mt*16 + g + 8*h;
            const int gi = i0 + li;
            const float xa = gix[li*3], xbv = gix[li*3+1], xc = gix[li*3+2];
            const float sqa = gisq[li], ya = giy[li];
            const size_t rb = (size_t)gi * N_;
#pragma unroll
            for (int nt = 0; nt < 4; nt++) {
                const int lj0 = wc32 + nt*8 + 2*tg;
                float2 r;
#pragma unroll
                for (int e = 0; e < 2; e++) {
                    const int lj = lj0 + e;
                    const size_t gidx = rb + j0 + lj;
                    float dot = fmaf(xc, gjx[lj*3+2], fmaf(xbv, gjx[lj*3+1], xa * gjx[lj*3]));
                    float dist2 = (sqa + gjsq[lj]) - 2.0f * dot;
                    bool ok = mask_at(dmask, gidx, mode) && mask_at(bmask, gidx, mode) && (dist2 <= 100.0f);
                    float av = acc[mt][nt][h*2 + e];
                    ((float*)&r)[e] = ok ? (av * 0.0625f - fabsf(ya - gjy[lj])) : NEG_;
                }
                *(float2*)&S[rb + j0 + lj0] = r;
            }
        }
    }
}

// ================= attn@V via bf16 mma, split-K z =================
// grid (HID/128, N/128, KZ_), 256 threads.
__global__ __launch_bounds__(256) void attnv_mma(
    const __nv_bfloat16* __restrict__ Sb, const __nv_bfloat16* __restrict__ Ss,
    const __nv_bfloat16* __restrict__ Vtb, const __nv_bfloat16* __restrict__ Vts,
    float* __restrict__ Cpart)
{
    __shared__ __align__(16) char Ash[2][128*80];
    __shared__ __align__(16) char Bsh[2][128*80];
    const int t = threadIdx.x, lane = t & 31, wid = t >> 5;
    const int wr64 = (wid >> 2) * 64, wc32 = (wid & 3) * 32;
    const int g = lane >> 2, tg = lane & 3;
    const int a_r = ((lane >> 3) & 1) * 8 + (lane & 7);
    const int a_c = (lane >> 4) * 16;
    const int b_r = ((lane >> 4) & 1) * 8 + (lane & 7);
    const int b_c = ((lane >> 3) & 1) * 16;
    const int m0 = blockIdx.y * 128, n0 = blockIdx.x * 128;
    const int kbase = blockIdx.z * (N_ / KZ_);
    const int lrow = t >> 2, lq = t & 3;

    uint32_t aS[2] = { smem_u32(Ash[0]), smem_u32(Ash[1]) };
    uint32_t bS[2] = { smem_u32(Bsh[0]), smem_u32(Bsh[1]) };
    float acc[4][4][4] = {};

    const __nv_bfloat16* APs[3] = { Sb, Sb, Ss };
    const __nv_bfloat16* BPs[3] = { Vtb, Vts, Vtb };
    const int CPP = (N_ / KZ_) / 32;   // 32 chunks per pass
    const int NC = 3 * CPP;

    uint4 va[2], vb[2];
#pragma unroll
    for (int r = 0; r < 2; r++) {
        int row = lrow + r*64;
        va[r] = *(const uint4*)(APs[0] + (size_t)(m0+row)*N_ + kbase + lq*8);
        vb[r] = *(const uint4*)(BPs[0] + (size_t)(n0+row)*N_ + kbase + lq*8);
    }
#pragma unroll
    for (int r = 0; r < 2; r++) {
        int row = lrow + r*64;
        *(uint4*)(Ash[0] + row*80 + lq*16) = va[r];
        *(uint4*)(Bsh[0] + row*80 + lq*16) = vb[r];
    }
    __syncthreads();

    for (int c = 0; c < NC; c++) {
        const int buf = c & 1;
        if (c + 1 < NC) {
            const int p = (c+1) >> 5, kc = (c+1) & 31;
            const __nv_bfloat16* A = APs[p];
            const __nv_bfloat16* B = BPs[p];
#pragma unroll
            for (int r = 0; r < 2; r++) {
                int row = lrow + r*64;
                va[r] = *(const uint4*)(A + (size_t)(m0+row)*N_ + kbase + kc*32 + lq*8);
                vb[r] = *(const uint4*)(B + (size_t)(n0+row)*N_ + kbase + kc*32 + lq*8);
            }
        }
        COMPUTE32(aS[buf], bS[buf]);
        if (c + 1 < NC) {
            const int nb = buf ^ 1;
#pragma unroll
            for (int r = 0; r < 2; r++) {
                int row = lrow + r*64;
                *(uint4*)(Ash[nb] + row*80 + lq*16) = va[r];
                *(uint4*)(Bsh[nb] + row*80 + lq*16) = vb[r];
            }
            __syncthreads();
        }
    }

    float* Cz = Cpart + (size_t)blockIdx.z * N_ * HID_;
#pragma unroll
    for (int mt = 0; mt < 4; mt++) {
#pragma unroll
        for (int h = 0; h < 2; h++) {
            const int m = m0 + wr64 + mt*16 + g + 8*h;
            const size_t rb = (size_t)m * HID_;
#pragma unroll
            for (int nt = 0; nt < 4; nt++) {
                const int n = n0 + wc32 + nt*8 + 2*tg;
                float2 r = { acc[mt][nt][h*2], acc[mt][nt][h*2 + 1] };
                *(float2*)&Cz[rb + n] = r;
            }
        }
    }
}

__global__ void combine_parts(const float* __restrict__ P, float* __restrict__ C)
{
    int i = blockIdx.x * blockDim.x + threadIdx.x;
    const size_t n = (size_t)N_ * HID_;
    float4 a = *(const float4*)&P[(size_t)i*4];
    float4 b = *(const float4*)&P[n + (size_t)i*4];
    float4 c = *(const float4*)&P[2*n + (size_t)i*4];
    float4 d = *(const float4*)&P[3*n + (size_t)i*4];
    float4 r = { a.x+b.x+c.x+d.x, a.y+b.y+c.y+d.y, a.z+b.z+c.z+d.z, a.w+b.w+c.w+d.w };
    *(float4*)&C[(size_t)i*4] = r;
}

// ================= 64x64x16 SGEMM (small GEMMs; epilogue + opt transpose) =================
__global__ void sgemm64(const float* __restrict__ A, const float* __restrict__ B,
                        float* __restrict__ C, float* __restrict__ CT,
                        int M, int Nc, int K,
                        const float* __restrict__ bias, int relu, float cacc,
                        const float* __restrict__ X1, float c1,
                        const float* __restrict__ X2, float c2,
                        const float* __restrict__ X3, float c3,
                        float* __restrict__ C2)
{
    __shared__ __align__(16) float As[16][68];
    __shared__ __align__(16) float Bs[16][68];
    const int t  = threadIdx.x;
    const int tx = t & 15, ty = t >> 4;
    const int m0 = blockIdx.y * 64, n0 = blockIdx.x * 64;
    const int ra = t >> 2, kq = t & 3;
    const int kr = t >> 4, nq = t & 15;

    float acc[4][4] = {};
    for (int k0 = 0; k0 < K; k0 += 16) {
        float4 a = *(const float4*)&A[(size_t)(m0 + ra) * K + k0 + kq * 4];
        As[kq*4+0][ra] = a.x; As[kq*4+1][ra] = a.y; As[kq*4+2][ra] = a.z; As[kq*4+3][ra] = a.w;
        float4 b = *(const float4*)&B[(size_t)(k0 + kr) * Nc + n0 + nq * 4];
        *(float4*)&Bs[kr][nq*4] = b;
        __syncthreads();
#pragma unroll
        for (int kk = 0; kk < 16; kk++) {
            float4 av = *(float4*)&As[kk][ty*4];
            float4 bv = *(float4*)&Bs[kk][tx*4];
            acc[0][0]=fmaf(av.x,bv.x,acc[0][0]); acc[0][1]=fmaf(av.x,bv.y,acc[0][1]);
            acc[0][2]=fmaf(av.x,bv.z,acc[0][2]); acc[0][3]=fmaf(av.x,bv.w,acc[0][3]);
            acc[1][0]=fmaf(av.y,bv.x,acc[1][0]); acc[1][1]=fmaf(av.y,bv.y,acc[1][1]);
            acc[1][2]=fmaf(av.y,bv.z,acc[1][2]); acc[1][3]=fmaf(av.y,bv.w,acc[1][3]);
            acc[2][0]=fmaf(av.z,bv.x,acc[2][0]); acc[2][1]=fmaf(av.z,bv.y,acc[2][1]);
            acc[2][2]=fmaf(av.z,bv.z,acc[2][2]); acc[2][3]=fmaf(av.z,bv.w,acc[2][3]);
            acc[3][0]=fmaf(av.w,bv.x,acc[3][0]); acc[3][1]=fmaf(av.w,bv.y,acc[3][1]);
            acc[3][2]=fmaf(av.w,bv.z,acc[3][2]); acc[3][3]=fmaf(av.w,bv.w,acc[3][3]);
        }
        __syncthreads();
    }
#pragma unroll
    for (int i = 0; i < 4; i++) {
        int m = m0 + ty*4 + i;
#pragma unroll
        for (int j = 0; j < 4; j++) {
            int n = n0 + tx*4 + j;
            size_t idx = (size_t)m * Nc + n;
            float v = cacc * acc[i][j];
            if (bias) v += bias[n];
            if (X1) v += c1 * X1[idx];
            if (X2) v += c2 * X2[idx];
            if (X3) v += c3 * X3[idx];
            if (relu) v = fmaxf(v, 0.0f);
            C[idx] = v;
            if (C2) C2[idx] = v;
            if (CT) CT[(size_t)n * M + m] = v;
        }
    }
}

// ---------------- softmax + attn@xyz + bf16 split of attn ----------------
__global__ void softmax_xyz(const float* __restrict__ S,
                            __nv_bfloat16* __restrict__ Sb, __nv_bfloat16* __restrict__ Ss,
                            const float* __restrict__ xs, const float* __restrict__ ys,
                            const float* __restrict__ zs, float* __restrict__ out)
{
    __shared__ float r0[256], r1[256], r2[256];
    const int row = blockIdx.x, t = threadIdx.x;
    const float* p = S + (size_t)row * N_;
    float4 v[4];
    float mx = -1e30f;
#pragma unroll
    for (int c = 0; c < 4; c++) {
        v[c] = *(const float4*)&p[c*1024 + t*4];
        mx = fmaxf(mx, fmaxf(fmaxf(v[c].x, v[c].y), fmaxf(v[c].z, v[c].w)));
    }
    r0[t] = mx; __syncthreads();
    for (int s = 128; s > 0; s >>= 1) { if (t < s) r0[t] = fmaxf(r0[t], r0[t+s]); __syncthreads(); }
    mx = r0[0]; __syncthreads();
    float sum = 0.0f;
#pragma unroll
    for (int c = 0; c < 4; c++) {
        v[c].x = expf(v[c].x - mx); v[c].y = expf(v[c].y - mx);
        v[c].z = expf(v[c].z - mx); v[c].w = expf(v[c].w - mx);
        sum += v[c].x + v[c].y + v[c].z + v[c].w;
    }
    r0[t] = sum; __syncthreads();
    for (int s = 128; s > 0; s >>= 1) { if (t < s) r0[t] += r0[t+s]; __syncthreads(); }
    const float inv = 1.0f / r0[0];
    __syncthreads();
    float a0 = 0.f, a1 = 0.f, a2 = 0.f;
#pragma unroll
    for (int c = 0; c < 4; c++) {
        v[c].x *= inv; v[c].y *= inv; v[c].z *= inv; v[c].w *= inv;
        float vv[4] = { v[c].x, v[c].y, v[c].z, v[c].w };
        __align__(8) __nv_bfloat16 vb[4], vsm[4];
#pragma unroll
        for (int e = 0; e < 4; e++) {
            vb[e]  = __float2bfloat16(vv[e]);
            vsm[e] = __float2bfloat16(vv[e] - __bfloat162float(vb[e]));
        }
        const size_t off = (size_t)row * N_ + c*1024 + t*4;
        *(uint2*)&Sb[off] = *(uint2*)vb;
        *(uint2*)&Ss[off] = *(uint2*)vsm;
        const int j = c*1024 + t*4;
        a0 = fmaf(v[c].x, xs[j], fmaf(v[c].y, xs[j+1], fmaf(v[c].z, xs[j+2], fmaf(v[c].w, xs[j+3], a0))));
        a1 = fmaf(v[c].x, ys[j], fmaf(v[c].y, ys[j+1], fmaf(v[c].z, ys[j+2], fmaf(v[c].w, ys[j+3], a1))));
        a2 = fmaf(v[c].x, zs[j], fmaf(v[c].y, zs[j+1], fmaf(v[c].z, zs[j+2], fmaf(v[c].w, zs[j+3], a2))));
    }
    r0[t]=a0; r1[t]=a1; r2[t]=a2; __syncthreads();
    for (int s = 128; s > 0; s >>= 1) {
        if (t < s) { r0[t]+=r0[t+s]; r1[t]+=r1[t+s]; r2[t]+=r2[t+s]; }
        __syncthreads();
    }
    if (t == 0) { out[row*3+0]=r0[0]; out[row*3+1]=r1[0]; out[row*3+2]=r2[0]; }
}

__global__ void xyz2soa(const float* __restrict__ xyz, float* __restrict__ xs,
                        float* __restrict__ ys, float* __restrict__ zs)
{
    int i = blockIdx.x * blockDim.x + threadIdx.x;
    if (i < N_) { xs[i] = xyz[3*i]; ys[i] = xyz[3*i+1]; zs[i] = xyz[3*i+2]; }
}

// ---------------- GAT pieces ----------------
__global__ void compute_elr(const float* __restrict__ hl, const float* __restrict__ al,
                            const float* __restrict__ ar)
{
    int idx = blockIdx.x * blockDim.x + threadIdx.x;
    if (idx >= N_*4) return;
    int node = idx >> 2, h = idx & 3;
    const float* row = hl + (size_t)node * HID_ + h * 64;
    float sl = 0.f, sr = 0.f;
#pragma unroll 8
    for (int d = 0; d < 64; d++) {
        float v = row[d];
        sl = fmaf(v, al[h*64+d], sl);
        sr = fmaf(v, ar[h*64+d], sr);
    }
    g_el[idx] = sl; g_er[idx] = sr;
}

__global__ void zero_cnt() { int i = blockIdx.x*blockDim.x + threadIdx.x; if (i < N_) g_cnt[i] = 0; }
__global__ void count_edges(const int* __restrict__ dst) {
    int e = blockIdx.x*blockDim.x + threadIdx.x; if (e < E_) atomicAdd(&g_cnt[dst[e]], 1);
}
__global__ void scan4096() {
    __shared__ int part[1024];
    int t = threadIdx.x, base = t * 4;
    int a0 = g_cnt[base], a1 = g_cnt[base+1], a2 = g_cnt[base+2], a3 = g_cnt[base+3];
    int s = a0 + a1 + a2 + a3;
    part[t] = s; __syncthreads();
    for (int off = 1; off < 1024; off <<= 1) {
        int v = (t >= off) ? part[t-off] : 0;
        __syncthreads();
        part[t] += v;
        __syncthreads();
    }
    int excl = part[t] - s;
    g_rowptr[base+0] = excl;           g_cur[base+0] = excl;
    g_rowptr[base+1] = excl+a0;        g_cur[base+1] = excl+a0;
    g_rowptr[base+2] = excl+a0+a1;     g_cur[base+2] = excl+a0+a1;
    g_rowptr[base+3] = excl+a0+a1+a2;  g_cur[base+3] = excl+a0+a1+a2;
    if (t == 1023) g_rowptr[4096] = part[1023];
}
__global__ void scatter_edges(const int* __restrict__ src, const int* __restrict__ dst) {
    int e = blockIdx.x*blockDim.x + threadIdx.x;
    if (e < E_) { int p = atomicAdd(&g_cur[dst[e]], 1); g_psrc[p] = src[e]; }
}

__global__ void gat_aggregate(const float* __restrict__ hl, float* __restrict__ xg)
{
    const int node = (blockIdx.x * blockDim.x + threadIdx.x) >> 5;
    const int lane = threadIdx.x & 31;
    if (node >= N_) return;
    const int beg = g_rowptr[node], end = g_rowptr[node+1];
    const float er_i = (lane < 4) ? g_er[node*4 + lane] : 0.f;
    float m = -1e30f;
    for (int p = beg; p < end; p++) {
        int s = g_psrc[p];
        if (lane < 4) {
            float v = g_el[s*4 + lane] + er_i;
            float e = (v > 0.f) ? v : 0.2f * v;
            m = fmaxf(m, e);
        }
    }
    float m0 = __shfl_sync(0xffffffffu, m, 0), m1 = __shfl_sync(0xffffffffu, m, 1);
    float m2 = __shfl_sync(0xffffffffu, m, 2), m3 = __shfl_sync(0xffffffffu, m, 3);
    const int myh = lane >> 3;
    float4 acc0 = {0,0,0,0}, acc1 = {0,0,0,0};
    float z = 0.f;
    for (int p = beg; p < end; p++) {
        int s = g_psrc[p];
        float w = 0.f;
        if (lane < 4) {
            float v = g_el[s*4 + lane] + er_i;
            float e = (v > 0.f) ? v : 0.2f * v;
            float mm = (lane==0)?m0:(lane==1)?m1:(lane==2)?m2:m3;
            w = expf(e - mm);
            z += w;
        }
        float w0 = __shfl_sync(0xffffffffu, w, 0), w1 = __shfl_sync(0xffffffffu, w, 1);
        float w2 = __shfl_sync(0xffffffffu, w, 2), w3 = __shfl_sync(0xffffffffu, w, 3);
        float wm = (myh==0)?w0:(myh==1)?w1:(myh==2)?w2:w3;
        const float4* hp = (const float4*)(hl + (size_t)s * HID_ + lane * 8);
        float4 hv0 = hp[0], hv1 = hp[1];
        acc0.x=fmaf(wm,hv0.x,acc0.x); acc0.y=fmaf(wm,hv0.y,acc0.y);
        acc0.z=fmaf(wm,hv0.z,acc0.z); acc0.w=fmaf(wm,hv0.w,acc0.w);
        acc1.x=fmaf(wm,hv1.x,acc1.x); acc1.y=fmaf(wm,hv1.y,acc1.y);
        acc1.z=fmaf(wm,hv1.z,acc1.z); acc1.w=fmaf(wm,hv1.w,acc1.w);
    }
    float z0 = __shfl_sync(0xffffffffu, z, 0), z1 = __shfl_sync(0xffffffffu, z, 1);
    float z2 = __shfl_sync(0xffffffffu, z, 2), z3 = __shfl_sync(0xffffffffu, z, 3);
    float zm = (myh==0)?z0:(myh==1)?z1:(myh==2)?z2:z3;
    float inv = 1.0f / (zm + 1e-9f);
    acc0.x*=inv; acc0.y*=inv; acc0.z*=inv; acc0.w*=inv;
    acc1.x*=inv; acc1.y*=inv; acc1.z*=inv; acc1.w*=inv;
    float4* op = (float4*)(xg + (size_t)node * HID_ + lane * 8);
    op[0] = acc0; op[1] = acc1;
}

__global__ void pack_support(const float* __restrict__ xg, const float* __restrict__ h0,
                             float* __restrict__ sup)
{
    int i = blockIdx.x * blockDim.x + threadIdx.x;
    if (i >= N_ * 512) return;
    int r = i >> 9, c = i & 511;
    sup[i] = (c < 256) ? xg[(size_t)r*256 + c] : h0[(size_t)r*256 + (c-256)];
}

__global__ void yhat_k(const float* __restrict__ x, const float* __restrict__ W,
                       const float* __restrict__ b)
{
    int i = blockIdx.x * blockDim.x + threadIdx.x;
    if (i >= N_) return;
    const float* r = x + (size_t)i * HID_;
    float l0 = b[0], l1 = b[1];
#pragma unroll 8
    for (int d = 0; d < HID_; d++) {
        float v = r[d];
        l0 = fmaf(v, W[2*d+0], l0);
        l1 = fmaf(v, W[2*d+1], l1);
    }
    g_y[i] = 1.0f / (1.0f + expf(l0 - l1));
}

__global__ void cls_k(const float* __restrict__ x, const float* __restrict__ W,
                      const float* __restrict__ b, float* __restrict__ out)
{
    int i = blockIdx.x * blockDim.x + threadIdx.x;
    if (i >= N_) return;
    const float* r = x + (size_t)i * HID_;
    float l0 = b[0], l1 = b[1];
#pragma unroll 8
    for (int d = 0; d < HID_; d++) {
        float v = r[d];
        l0 = fmaf(v, W[2*d+0], l0);
        l1 = fmaf(v, W[2*d+1], l1);
    }
    out[2*i+0] = l0;
    out[2*i+1] = l1;
}

// ---------------- host orchestration ----------------
extern "C" void kernel_launch(void* const* d_in, const int* in_sizes, int n_in,
                              void* d_out, int out_size)
{
    const float* feat   = (const float*)d_in[0];
    const float* xyz_in = (const float*)d_in[1];
    const int*   src    = (const int*)  d_in[2];
    const int*   dst    = (const int*)  d_in[3];
    const void*  dmask  = d_in[4];
    const void*  bmask  = d_in[5];
    const float* fcW  = (const float*)d_in[6];
    const float* fcb  = (const float*)d_in[7];
    const float* gatW = (const float*)d_in[8];
    const float* al   = (const float*)d_in[9];
    const float* ar   = (const float*)d_in[10];
    const float* gcW  = (const float*)d_in[11];
    const float* cgW  = (const float*)d_in[12];
    const float* cgb  = (const float*)d_in[13];
    const float* qW   = (const float*)d_in[14];
    const float* qb_  = (const float*)d_in[15];
    const float* kW   = (const float*)d_in[16];
    const float* kb_  = (const float*)d_in[17];
    const float* vW   = (const float*)d_in[18];
    const float* vb_  = (const float*)d_in[19];
    const float* oW   = (const float*)d_in[20];
    const float* ob   = (const float*)d_in[21];
    const float* clsW = (const float*)d_in[22];
    const float* clsb = (const float*)d_in[23];

    float *px, *ph0, *phl, *pxg, *psup, *pq, *pk, *pv, *pvt, *phms, *pS;
    float *pxyz0, *pxyz1, *pxs, *pys, *pzs, *ppart;
    __nv_bfloat16 *pqb2, *pqs2, *pkb2, *pks2, *pvtb2, *pvts2, *psb2, *pss2;
    cudaGetSymbolAddress((void**)&px,    g_x);
    cudaGetSymbolAddress((void**)&ph0,   g_h0);
    cudaGetSymbolAddress((void**)&phl,   g_hl);
    cudaGetSymbolAddress((void**)&pxg,   g_xg);
    cudaGetSymbolAddress((void**)&psup,  g_sup);
    cudaGetSymbolAddress((void**)&pq,    g_q);
    cudaGetSymbolAddress((void**)&pk,    g_k);
    cudaGetSymbolAddress((void**)&pv,    g_v);
    cudaGetSymbolAddress((void**)&pvt,   g_vt);
    cudaGetSymbolAddress((void**)&phms,  g_hms);
    cudaGetSymbolAddress((void**)&pS,    g_S);
    cudaGetSymbolAddress((void**)&pxyz0, g_xyz0);
    cudaGetSymbolAddress((void**)&pxyz1, g_xyz1);
    cudaGetSymbolAddress((void**)&pxs,   g_xs);
    cudaGetSymbolAddress((void**)&pys,   g_ys);
    cudaGetSymbolAddress((void**)&pzs,   g_zs);
    cudaGetSymbolAddress((void**)&ppart, g_part);
    cudaGetSymbolAddress((void**)&pqb2,  g_qb2);
    cudaGetSymbolAddress((void**)&pqs2,  g_qs2);
    cudaGetSymbolAddress((void**)&pkb2,  g_kb2);
    cudaGetSymbolAddress((void**)&pks2,  g_ks2);
    cudaGetSymbolAddress((void**)&pvtb2, g_vtb2);
    cudaGetSymbolAddress((void**)&pvts2, g_vts2);
    cudaGetSymbolAddress((void**)&psb2,  g_sb2);
    cudaGetSymbolAddress((void**)&pss2,  g_ss2);

    detect_mask_mode<<<1, 1>>>((const unsigned int*)dmask);

    sgemm64<<<dim3(HID_/64, N_/64), 256>>>(feat, fcW, px, nullptr, N_, HID_, FEAT_,
                                           fcb, 1, 1.0f, nullptr,0.f, nullptr,0.f, nullptr,0.f, ph0);

    zero_cnt<<<N_/256, 256>>>();
    count_edges<<<E_/256, 256>>>(dst);
    scan4096<<<1, 1024>>>();
    scatter_edges<<<E_/256, 256>>>(src, dst);

    const float ALPHA = 0.1f, LAMDA = 0.5f;
    for (int l = 0; l < 4; l++) {
        sgemm64<<<dim3(HID_/64, N_/64), 256>>>(px, gatW + (size_t)l*HID_*HID_, phl, nullptr,
                                               N_, HID_, HID_, nullptr, 0, 1.0f,
                                               nullptr,0.f, nullptr,0.f, nullptr,0.f, nullptr);
        compute_elr<<<(N_*4)/256, 256>>>(phl, al + l*4*64, ar + l*4*64);
        gat_aggregate<<<N_/8, 256>>>(phl, pxg);
        pack_support<<<(N_*512)/256, 256>>>(pxg, ph0, psup);
        float theta = fminf(1.0f, logf(LAMDA / (float)(l + 1) + 1.0f));
        sgemm64<<<dim3(HID_/64, N_/64), 256>>>(psup, gcW + (size_t)l*512*HID_, px, nullptr,
                                               N_, HID_, 512, nullptr, 0, theta,
                                               pxg, (1.0f-theta)*(1.0f-ALPHA),
                                               ph0, (1.0f-theta)*ALPHA,
                                               px,  1.0f, nullptr);
    }

    yhat_k<<<N_/256, 256>>>(px, cgW, cgb);

    const float* xyz_cur = xyz_in;
    float* xyz_buf[2] = { pxyz0, pxyz1 };
    const int splitg = (N_*HID_/4)/256;   // 1024 blocks of float4s
    for (int l = 0; l < 4; l++) {
        sgemm64<<<dim3(HID_/64, N_/64), 256>>>(px, qW + (size_t)l*HID_*HID_, pq, nullptr,
                                               N_, HID_, HID_, qb_ + l*HID_, 0, 1.0f,
                                               nullptr,0.f, nullptr,0.f, nullptr,0.f, nullptr);
        sgemm64<<<dim3(HID_/64, N_/64), 256>>>(px, kW + (size_t)l*HID_*HID_, pk, nullptr,
                                               N_, HID_, HID_, kb_ + l*HID_, 0, 1.0f,
                                               nullptr,0.f, nullptr,0.f, nullptr,0.f, nullptr);
        sgemm64<<<dim3(HID_/64, N_/64), 256>>>(px, vW + (size_t)l*HID_*HID_, pv, pvt,
                                               N_, HID_, HID_, vb_ + l*HID_, 0, 1.0f,
                                               nullptr,0.f, nullptr,0.f, nullptr,0.f, nullptr);
        split_bf16<<<splitg, 256>>>(pq,  pqb2,  pqs2);
        split_bf16<<<splitg, 256>>>(pk,  pkb2,  pks2);
        split_bf16<<<splitg, 256>>>(pvt, pvtb2, pvts2);
        scores_mma<<<dim3(N_/128, N_/128), 256>>>(pqb2, pqs2, pkb2, pks2,
                                                  xyz_cur, dmask, bmask, pS);
        xyz2soa<<<N_/256, 256>>>(xyz_cur, pxs, pys, pzs);
        softmax_xyz<<<N_, 256>>>(pS, psb2, pss2, pxs, pys, pzs, xyz_buf[l & 1]);
        attnv_mma<<<dim3(HID_/128, N_/128, KZ_), 256>>>(psb2, pss2, pvtb2, pvts2, ppart);
        combine_parts<<<(N_*HID_/4)/256, 256>>>(ppart, phms);
        sgemm64<<<dim3(HID_/64, N_/64), 256>>>(phms, oW + (size_t)l*HID_*HID_, px, nullptr,
                                               N_, HID_, HID_, ob + l*HID_, 0, 1.0f,
                                               px, 1.0f, nullptr,0.f, nullptr,0.f, nullptr);
        xyz_cur = xyz_buf[l & 1];
    }

    cls_k<<<N_/256, 256>>>(px, clsW, clsb, (float*)d_out);
}

// round 9
// speedup vs baseline: 1.4953x; 1.0491x over previous
#include <cuda_runtime.h>
#include <cuda_bf16.h>
#include <math.h>
#include <stdint.h>

#define N_    4096
#define E_    131072
#define FEAT_ 64
#define HID_  256
#define NEG_  (-1e9f)
#define KZ_   4

typedef __nv_bfloat16 bf16;

// ---------------- scratch ----------------
__device__ float g_h0 [N_*HID_];
__device__ float g_x  [N_*HID_];
__device__ float g_hl [N_*HID_];
__device__ float g_xg [N_*HID_];
__device__ float g_part[(size_t)KZ_*N_*HID_];
__device__ float g_S  [(size_t)N_*N_];
__device__ bf16 g_xb[N_*HID_], g_xs[N_*HID_];
__device__ bf16 g_featb[N_*FEAT_], g_feats[N_*FEAT_];
__device__ bf16 g_supb[N_*2*HID_], g_sups[N_*2*HID_];
__device__ bf16 g_hmsb[N_*HID_], g_hmss[N_*HID_];
__device__ bf16 g_qb2[N_*HID_], g_qs2[N_*HID_];
__device__ bf16 g_kb2[N_*HID_], g_ks2[N_*HID_];
__device__ bf16 g_vtb2[HID_*N_], g_vts2[HID_*N_];
__device__ bf16 g_sb2[(size_t)N_*N_], g_ss2[(size_t)N_*N_];
// transposed-split weights [N,K] bf16
__device__ bf16 g_fcWtb[HID_*FEAT_], g_fcWts[HID_*FEAT_];
__device__ bf16 g_gatWtb[4*HID_*HID_], g_gatWts[4*HID_*HID_];
__device__ bf16 g_gcWtb[4*HID_*2*HID_], g_gcWts[4*HID_*2*HID_];
__device__ bf16 g_qWtb[4*HID_*HID_], g_qWts[4*HID_*HID_];
__device__ bf16 g_kWtb[4*HID_*HID_], g_kWts[4*HID_*HID_];
__device__ bf16 g_vWtb[4*HID_*HID_], g_vWts[4*HID_*HID_];
__device__ bf16 g_oWtb[4*HID_*HID_], g_oWts[4*HID_*HID_];
__device__ float g_el [N_*4];
__device__ float g_er [N_*4];
__device__ float g_y  [N_];
__device__ float g_xyz0[N_*3];
__device__ float g_xyz1[N_*3];
__device__ float g_xs_[N_], g_ys_[N_], g_zs_[N_];
__device__ int   g_cnt[N_];
__device__ int   g_rowptr[N_+1];
__device__ int   g_cur[N_];
__device__ int   g_psrc[E_];
__device__ int   g_maskmode;

// ---------------- helpers ----------------
__device__ __forceinline__ uint32_t smem_u32(const void* p) {
    uint32_t a;
    asm("{ .reg .u64 t; cvta.to.shared.u64 t, %1; cvt.u32.u64 %0, t; }" : "=r"(a) : "l"(p));
    return a;
}
#define LDMX4(r, a) \
    asm volatile("ldmatrix.sync.aligned.m8n8.x4.shared.b16 {%0,%1,%2,%3}, [%4];" \
        : "=r"((r)[0]), "=r"((r)[1]), "=r"((r)[2]), "=r"((r)[3]) : "r"(a))
#define MMA16816(c, a, b0, b1) \
    asm volatile("mma.sync.aligned.m16n8k16.row.col.f32.bf16.bf16.f32 " \
        "{%0,%1,%2,%3}, {%4,%5,%6,%7}, {%8,%9}, {%0,%1,%2,%3};" \
        : "+f"((c)[0]), "+f"((c)[1]), "+f"((c)[2]), "+f"((c)[3]) \
        : "r"((a)[0]), "r"((a)[1]), "r"((a)[2]), "r"((a)[3]), "r"(b0), "r"(b1))

__device__ __forceinline__ void split1(float v, bf16& b, bf16& s) {
    b = __float2bfloat16(v);
    s = __float2bfloat16(v - __bfloat162float(b));
}

__global__ void detect_mask_mode(const unsigned int* __restrict__ m) {
    bool allbin = true, anyfloat = false;
    for (int i = 0; i < 1024; i++) {
        unsigned int w = m[i];
        if (w == 0x3f800000u) anyfloat = true;
        if (w > 1u) allbin = false;
    }
    g_maskmode = anyfloat ? 2 : (allbin ? 1 : 0);
}
__device__ __forceinline__ bool mask_at(const void* p, size_t i, int mode) {
    if (mode == 0) return ((const unsigned char*)p)[i] != 0;
    if (mode == 1) return ((const int*)p)[i] != 0;
    return ((const float*)p)[i] != 0.0f;
}

__global__ void split_bf16(const float* __restrict__ X, bf16* __restrict__ Xb, bf16* __restrict__ Xs)
{
    int i = blockIdx.x * blockDim.x + threadIdx.x;
    float4 x = *(const float4*)&X[(size_t)i*4];
    float xv[4] = {x.x, x.y, x.z, x.w};
    __align__(8) bf16 b[4], s[4];
#pragma unroll
    for (int e = 0; e < 4; e++) split1(xv[e], b[e], s[e]);
    *(uint2*)&Xb[(size_t)i*4] = *(uint2*)b;
    *(uint2*)&Xs[(size_t)i*4] = *(uint2*)s;
}

// weight transpose-split: W [nmat][K,N] fp32 -> Wt [nmat][N,K] bf16 big/small
__global__ void wsplit(const float* __restrict__ W, bf16* __restrict__ Wtb,
                       bf16* __restrict__ Wts, int K, int N, int KN)
{
    int idx = blockIdx.x * 256 + threadIdx.x;
    int mat = idx / KN;
    int rem = idx - mat * KN;
    int k = rem / N;
    int n = rem - k * N;
    float v = W[idx];
    bf16 b, s; split1(v, b, s);
    int o = mat * KN + n * K + k;
    Wtb[o] = b; Wts[o] = s;
}

// ================= generic bf16-mma GEMM: tile 128x64, 3-pass split =================
// A (split) [M=4096, K], B (split) [N, K]; epilogue: cacc*acc + bias + c*X + relu;
// outputs: C/C2 fp32, Cb/Cs bf16 split, CTb/CTs transposed split (stride N_).
__global__ __launch_bounds__(256) void gemm_tc(
    const bf16* __restrict__ Ab, const bf16* __restrict__ Asm,
    const bf16* __restrict__ Bb, const bf16* __restrict__ Bsm,
    int K, int Nc,
    const float* __restrict__ bias, int relu, float cacc,
    const float* __restrict__ X1, float c1,
    const float* __restrict__ X2, float c2,
    const float* __restrict__ X3, float c3,
    float* __restrict__ C, float* __restrict__ C2,
    bf16* __restrict__ Cb, bf16* __restrict__ Cs,
    bf16* __restrict__ CTb, bf16* __restrict__ CTs)
{
    __shared__ __align__(16) char Ash[2][128*80];
    __shared__ __align__(16) char Bsh[2][64*80];
    const int t = threadIdx.x, lane = t & 31, wid = t >> 5;
    const int wr32 = (wid >> 1) * 32, wc32 = (wid & 1) * 32;
    const int g = lane >> 2, tg = lane & 3;
    const int a_r = ((lane >> 3) & 1) * 8 + (lane & 7);
    const int a_c = (lane >> 4) * 16;
    const int b_r = ((lane >> 4) & 1) * 8 + (lane & 7);
    const int b_c = ((lane >> 3) & 1) * 16;
    const int m0 = blockIdx.y * 128, n0 = blockIdx.x * 64;

    uint32_t aS[2] = { smem_u32(Ash[0]), smem_u32(Ash[1]) };
    uint32_t bS[2] = { smem_u32(Bsh[0]), smem_u32(Bsh[1]) };
    float acc[2][4][4] = {};

    const bf16* APs[3] = { Ab, Ab, Asm };
    const bf16* BPs[3] = { Bb, Bsm, Bb };
    const int chunks = K >> 5;
    const int NC = 3 * chunks;

    const int ar0 = t >> 1;                  // not used; loaders below
    (void)ar0;
    uint4 va[2], vb;
    // preload chunk 0 pass 0
#pragma unroll
    for (int i = 0; i < 2; i++) {
        int idx = t + i*256, row = idx >> 2, q = idx & 3;
        va[i] = *(const uint4*)(APs[0] + (size_t)(m0+row)*K + q*8);
    }
    { int row = t >> 2, q = t & 3;
      vb = *(const uint4*)(BPs[0] + (size_t)(n0+row)*K + q*8); }
#pragma unroll
    for (int i = 0; i < 2; i++) {
        int idx = t + i*256, row = idx >> 2, q = idx & 3;
        *(uint4*)(Ash[0] + row*80 + q*16) = va[i];
    }
    { int row = t >> 2, q = t & 3;
      *(uint4*)(Bsh[0] + row*80 + q*16) = vb; }
    __syncthreads();

    int pn = 0, kn = 0;
    for (int c = 0; c < NC; c++) {
        const int buf = c & 1;
        const bool more = (c + 1 < NC);
        if (more) {
            kn++; if (kn == chunks) { kn = 0; pn++; }
            const bf16* A = APs[pn];
            const bf16* B = BPs[pn];
#pragma unroll
            for (int i = 0; i < 2; i++) {
                int idx = t + i*256, row = idx >> 2, q = idx & 3;
                va[i] = *(const uint4*)(A + (size_t)(m0+row)*K + kn*32 + q*8);
            }
            { int row = t >> 2, q = t & 3;
              vb = *(const uint4*)(B + (size_t)(n0+row)*K + kn*32 + q*8); }
        }
        // compute on buf
#pragma unroll
        for (int kk = 0; kk < 2; kk++) {
            uint32_t af[2][4], bfr[2][4];
#pragma unroll
            for (int mt = 0; mt < 2; mt++) {
                uint32_t ad = aS[buf] + (uint32_t)((wr32 + mt*16 + a_r)*80 + kk*32 + a_c);
                LDMX4(af[mt], ad);
            }
#pragma unroll
            for (int np = 0; np < 2; np++) {
                uint32_t bd = bS[buf] + (uint32_t)((wc32 + np*16 + b_r)*80 + kk*32 + b_c);
                LDMX4(bfr[np], bd);
            }
#pragma unroll
            for (int mt = 0; mt < 2; mt++)
#pragma unroll
                for (int nt = 0; nt < 4; nt++)
                    MMA16816(acc[mt][nt], af[mt], bfr[nt>>1][(nt&1)*2], bfr[nt>>1][(nt&1)*2+1]);
        }
        if (more) {
            const int nb = buf ^ 1;
#pragma unroll
            for (int i = 0; i < 2; i++) {
                int idx = t + i*256, row = idx >> 2, q = idx & 3;
                *(uint4*)(Ash[nb] + row*80 + q*16) = va[i];
            }
            { int row = t >> 2, q = t & 3;
              *(uint4*)(Bsh[nb] + row*80 + q*16) = vb; }
            __syncthreads();
        }
    }

#pragma unroll
    for (int mt = 0; mt < 2; mt++) {
#pragma unroll
        for (int h = 0; h < 2; h++) {
            const int m = m0 + wr32 + mt*16 + g + 8*h;
            const size_t rb = (size_t)m * Nc;
#pragma unroll
            for (int nt = 0; nt < 4; nt++) {
                const int n = n0 + wc32 + nt*8 + 2*tg;
                float2 r = { acc[mt][nt][h*2], acc[mt][nt][h*2+1] };
                r.x *= cacc; r.y *= cacc;
                if (bias) { r.x += bias[n]; r.y += bias[n+1]; }
                if (X1) { float2 q = *(const float2*)&X1[rb+n];
                          r.x = fmaf(c1,q.x,r.x); r.y = fmaf(c1,q.y,r.y); }
                if (X2) { float2 q = *(const float2*)&X2[rb+n];
                          r.x = fmaf(c2,q.x,r.x); r.y = fmaf(c2,q.y,r.y); }
                if (X3) { float2 q = *(const float2*)&X3[rb+n];
                          r.x = fmaf(c3,q.x,r.x); r.y = fmaf(c3,q.y,r.y); }
                if (relu) { r.x = fmaxf(r.x, 0.f); r.y = fmaxf(r.y, 0.f); }
                if (C)  *(float2*)&C[rb+n]  = r;
                if (C2) *(float2*)&C2[rb+n] = r;
                if (Cb) {
                    __align__(4) bf16 b2[2], s2[2];
                    split1(r.x, b2[0], s2[0]); split1(r.y, b2[1], s2[1]);
                    *(uint32_t*)&Cb[rb+n] = *(uint32_t*)b2;
                    *(uint32_t*)&Cs[rb+n] = *(uint32_t*)s2;
                }
                if (CTb) {
                    bf16 b0, s0, b1, s1;
                    split1(r.x, b0, s0); split1(r.y, b1, s1);
                    CTb[(size_t)n * N_ + m] = b0;     CTs[(size_t)n * N_ + m] = s0;
                    CTb[(size_t)(n+1) * N_ + m] = b1; CTs[(size_t)(n+1) * N_ + m] = s1;
                }
            }
        }
    }
}

// ---- shared mma-core macro (128x128 kernels) ----
#define COMPUTE32(abase, bbase)                                                     \
    _Pragma("unroll")                                                               \
    for (int kk = 0; kk < 2; kk++) {                                                \
        uint32_t af[4][4], bfr[2][4];                                               \
        _Pragma("unroll")                                                           \
        for (int mt = 0; mt < 4; mt++) {                                            \
            uint32_t ad = (abase) + (uint32_t)((wr64 + mt*16 + a_r)*80 + kk*32 + a_c); \
            LDMX4(af[mt], ad);                                                      \
        }                                                                           \
        _Pragma("unroll")                                                           \
        for (int np = 0; np < 2; np++) {                                            \
            uint32_t bd = (bbase) + (uint32_t)((wc32 + np*16 + b_r)*80 + kk*32 + b_c); \
            LDMX4(bfr[np], bd);                                                     \
        }                                                                           \
        _Pragma("unroll")                                                           \
        for (int mt = 0; mt < 4; mt++)                                              \
            _Pragma("unroll")                                                       \
            for (int nt = 0; nt < 4; nt++)                                          \
                MMA16816(acc[mt][nt], af[mt], bfr[nt>>1][(nt&1)*2], bfr[nt>>1][(nt&1)*2+1]); \
    }

// ================= scores via bf16 mma =================
__global__ __launch_bounds__(256) void scores_mma(
    const bf16* __restrict__ qb, const bf16* __restrict__ qs,
    const bf16* __restrict__ kb, const bf16* __restrict__ ks,
    const float* __restrict__ xyz,
    const void* __restrict__ dmask, const void* __restrict__ bmask,
    float* __restrict__ S)
{
    __shared__ __align__(16) char Ash[2][128*80];
    __shared__ __align__(16) char Bsh[2][128*80];
    __shared__ float gix[128*3], gisq[128], giy[128];
    __shared__ float gjx[128*3], gjsq[128], gjy[128];
    const int t = threadIdx.x, lane = t & 31, wid = t >> 5;
    const int wr64 = (wid >> 2) * 64, wc32 = (wid & 3) * 32;
    const int g = lane >> 2, tg = lane & 3;
    const int a_r = ((lane >> 3) & 1) * 8 + (lane & 7);
    const int a_c = (lane >> 4) * 16;
    const int b_r = ((lane >> 4) & 1) * 8 + (lane & 7);
    const int b_c = ((lane >> 3) & 1) * 16;
    const int i0 = blockIdx.y * 128, j0 = blockIdx.x * 128;
    const int lrow = t >> 2, lq = t & 3;

    if (t < 128) {
        float a = xyz[(i0+t)*3+0], b = xyz[(i0+t)*3+1], c = xyz[(i0+t)*3+2];
        gix[t*3+0]=a; gix[t*3+1]=b; gix[t*3+2]=c;
        gisq[t] = fmaf(c,c,fmaf(b,b,a*a));
        giy[t]  = g_y[i0+t];
    } else {
        int u = t - 128;
        float a = xyz[(j0+u)*3+0], b = xyz[(j0+u)*3+1], c = xyz[(j0+u)*3+2];
        gjx[u*3+0]=a; gjx[u*3+1]=b; gjx[u*3+2]=c;
        gjsq[u] = fmaf(c,c,fmaf(b,b,a*a));
        gjy[u]  = g_y[j0+u];
    }

    uint32_t aS[2] = { smem_u32(Ash[0]), smem_u32(Ash[1]) };
    uint32_t bS[2] = { smem_u32(Bsh[0]), smem_u32(Bsh[1]) };
    float acc[4][4][4] = {};

    const bf16* APs[3] = { qb, qb, qs };
    const bf16* BPs[3] = { kb, ks, kb };

    uint4 va[2], vb[2];
#pragma unroll
    for (int r = 0; r < 2; r++) {
        int row = lrow + r*64;
        va[r] = *(const uint4*)(APs[0] + (size_t)(i0+row)*HID_ + lq*8);
        vb[r] = *(const uint4*)(BPs[0] + (size_t)(j0+row)*HID_ + lq*8);
    }
#pragma unroll
    for (int r = 0; r < 2; r++) {
        int row = lrow + r*64;
        *(uint4*)(Ash[0] + row*80 + lq*16) = va[r];
        *(uint4*)(Bsh[0] + row*80 + lq*16) = vb[r];
    }
    __syncthreads();

    const int NC = 24;
    for (int c = 0; c < NC; c++) {
        const int buf = c & 1;
        if (c + 1 < NC) {
            const int p = (c+1) >> 3, kc = (c+1) & 7;
            const bf16* A = APs[p];
            const bf16* B = BPs[p];
#pragma unroll
            for (int r = 0; r < 2; r++) {
                int row = lrow + r*64;
                va[r] = *(const uint4*)(A + (size_t)(i0+row)*HID_ + kc*32 + lq*8);
                vb[r] = *(const uint4*)(B + (size_t)(j0+row)*HID_ + kc*32 + lq*8);
            }
        }
        COMPUTE32(aS[buf], bS[buf]);
        if (c + 1 < NC) {
            const int nb = buf ^ 1;
#pragma unroll
            for (int r = 0; r < 2; r++) {
                int row = lrow + r*64;
                *(uint4*)(Ash[nb] + row*80 + lq*16) = va[r];
                *(uint4*)(Bsh[nb] + row*80 + lq*16) = vb[r];
            }
            __syncthreads();
        }
    }

    const int mode = g_maskmode;
#pragma unroll
    for (int mt = 0; mt < 4; mt++) {
#pragma unroll
        for (int h = 0; h < 2; h++) {
            const int li = wr64 + mt*16 + g + 8*h;
            const int gi = i0 + li;
            const float xa = gix[li*3], xbv = gix[li*3+1], xc = gix[li*3+2];
            const float sqa = gisq[li], ya = giy[li];
            const size_t rb = (size_t)gi * N_;
#pragma unroll
            for (int nt = 0; nt < 4; nt++) {
                const int lj0 = wc32 + nt*8 + 2*tg;
                float2 r;
#pragma unroll
                for (int e = 0; e < 2; e++) {
                    const int lj = lj0 + e;
                    const size_t gidx = rb + j0 + lj;
                    float dot = fmaf(xc, gjx[lj*3+2], fmaf(xbv, gjx[lj*3+1], xa * gjx[lj*3]));
                    float dist2 = (sqa + gjsq[lj]) - 2.0f * dot;
                    bool ok = mask_at(dmask, gidx, mode) && mask_at(bmask, gidx, mode) && (dist2 <= 100.0f);
                    float av = acc[mt][nt][h*2 + e];
                    ((float*)&r)[e] = ok ? (av * 0.0625f - fabsf(ya - gjy[lj])) : NEG_;
                }
                *(float2*)&S[rb + j0 + lj0] = r;
            }
        }
    }
}

// ================= attn@V via bf16 mma, split-K z =================
__global__ __launch_bounds__(256) void attnv_mma(
    const bf16* __restrict__ Sb, const bf16* __restrict__ Ss,
    const bf16* __restrict__ Vtb, const bf16* __restrict__ Vts,
    float* __restrict__ Cpart)
{
    __shared__ __align__(16) char Ash[2][128*80];
    __shared__ __align__(16) char Bsh[2][128*80];
    const int t = threadIdx.x, lane = t & 31, wid = t >> 5;
    const int wr64 = (wid >> 2) * 64, wc32 = (wid & 3) * 32;
    const int g = lane >> 2, tg = lane & 3;
    const int a_r = ((lane >> 3) & 1) * 8 + (lane & 7);
    const int a_c = (lane >> 4) * 16;
    const int b_r = ((lane >> 4) & 1) * 8 + (lane & 7);
    const int b_c = ((lane >> 3) & 1) * 16;
    const int m0 = blockIdx.y * 128, n0 = blockIdx.x * 128;
    const int kbase = blockIdx.z * (N_ / KZ_);
    const int lrow = t >> 2, lq = t & 3;

    uint32_t aS[2] = { smem_u32(Ash[0]), smem_u32(Ash[1]) };
    uint32_t bS[2] = { smem_u32(Bsh[0]), smem_u32(Bsh[1]) };
    float acc[4][4][4] = {};

    const bf16* APs[3] = { Sb, Sb, Ss };
    const bf16* BPs[3] = { Vtb, Vts, Vtb };
    const int CPP = (N_ / KZ_) / 32;
    const int NC = 3 * CPP;

    uint4 va[2], vb[2];
#pragma unroll
    for (int r = 0; r < 2; r++) {
        int row = lrow + r*64;
        va[r] = *(const uint4*)(APs[0] + (size_t)(m0+row)*N_ + kbase + lq*8);
        vb[r] = *(const uint4*)(BPs[0] + (size_t)(n0+row)*N_ + kbase + lq*8);
    }
#pragma unroll
    for (int r = 0; r < 2; r++) {
        int row = lrow + r*64;
        *(uint4*)(Ash[0] + row*80 + lq*16) = va[r];
        *(uint4*)(Bsh[0] + row*80 + lq*16) = vb[r];
    }
    __syncthreads();

    for (int c = 0; c < NC; c++) {
        const int buf = c & 1;
        if (c + 1 < NC) {
            const int p = (c+1) >> 5, kc = (c+1) & 31;
            const bf16* A = APs[p];
            const bf16* B = BPs[p];
#pragma unroll
            for (int r = 0; r < 2; r++) {
                int row = lrow + r*64;
                va[r] = *(const uint4*)(A + (size_t)(m0+row)*N_ + kbase + kc*32 + lq*8);
                vb[r] = *(const uint4*)(B + (size_t)(n0+row)*N_ + kbase + kc*32 + lq*8);
            }
        }
        COMPUTE32(aS[buf], bS[buf]);
        if (c + 1 < NC) {
            const int nb = buf ^ 1;
#pragma unroll
            for (int r = 0; r < 2; r++) {
                int row = lrow + r*64;
                *(uint4*)(Ash[nb] + row*80 + lq*16) = va[r];
                *(uint4*)(Bsh[nb] + row*80 + lq*16) = vb[r];
            }
            __syncthreads();
        }
    }

    float* Cz = Cpart + (size_t)blockIdx.z * N_ * HID_;
#pragma unroll
    for (int mt = 0; mt < 4; mt++) {
#pragma unroll
        for (int h = 0; h < 2; h++) {
            const int m = m0 + wr64 + mt*16 + g + 8*h;
            const size_t rb = (size_t)m * HID_;
#pragma unroll
            for (int nt = 0; nt < 4; nt++) {
                const int n = n0 + wc32 + nt*8 + 2*tg;
                float2 r = { acc[mt][nt][h*2], acc[mt][nt][h*2 + 1] };
                *(float2*)&Cz[rb + n] = r;
            }
        }
    }
}

// combine split-K partials -> bf16 split of hms
__global__ void combine_parts(const float* __restrict__ P,
                              bf16* __restrict__ Hb, bf16* __restrict__ Hs)
{
    int i = blockIdx.x * blockDim.x + threadIdx.x;
    const size_t n = (size_t)N_ * HID_;
    float4 a = *(const float4*)&P[(size_t)i*4];
    float4 b = *(const float4*)&P[n + (size_t)i*4];
    float4 c = *(const float4*)&P[2*n + (size_t)i*4];
    float4 d = *(const float4*)&P[3*n + (size_t)i*4];
    float rv[4] = { a.x+b.x+c.x+d.x, a.y+b.y+c.y+d.y, a.z+b.z+c.z+d.z, a.w+b.w+c.w+d.w };
    __align__(8) bf16 hb[4], hs[4];
#pragma unroll
    for (int e = 0; e < 4; e++) split1(rv[e], hb[e], hs[e]);
    *(uint2*)&Hb[(size_t)i*4] = *(uint2*)hb;
    *(uint2*)&Hs[(size_t)i*4] = *(uint2*)hs;
}

// ---------------- softmax + attn@xyz + bf16 split of attn ----------------
__global__ void softmax_xyz(const float* __restrict__ S,
                            bf16* __restrict__ Sb, bf16* __restrict__ Ss,
                            const float* __restrict__ xs, const float* __restrict__ ys,
                            const float* __restrict__ zs, float* __restrict__ out)
{
    __shared__ float r0[256], r1[256], r2[256];
    const int row = blockIdx.x, t = threadIdx.x;
    const float* p = S + (size_t)row * N_;
    float4 v[4];
    float mx = -1e30f;
#pragma unroll
    for (int c = 0; c < 4; c++) {
        v[c] = *(const float4*)&p[c*1024 + t*4];
        mx = fmaxf(mx, fmaxf(fmaxf(v[c].x, v[c].y), fmaxf(v[c].z, v[c].w)));
    }
    r0[t] = mx; __syncthreads();
    for (int s = 128; s > 0; s >>= 1) { if (t < s) r0[t] = fmaxf(r0[t], r0[t+s]); __syncthreads(); }
    mx = r0[0]; __syncthreads();
    float sum = 0.0f;
#pragma unroll
    for (int c = 0; c < 4; c++) {
        v[c].x = expf(v[c].x - mx); v[c].y = expf(v[c].y - mx);
        v[c].z = expf(v[c].z - mx); v[c].w = expf(v[c].w - mx);
        sum += v[c].x + v[c].y + v[c].z + v[c].w;
    }
    r0[t] = sum; __syncthreads();
    for (int s = 128; s > 0; s >>= 1) { if (t < s) r0[t] += r0[t+s]; __syncthreads(); }
    const float inv = 1.0f / r0[0];
    __syncthreads();
    float a0 = 0.f, a1 = 0.f, a2 = 0.f;
#pragma unroll
    for (int c = 0; c < 4; c++) {
        v[c].x *= inv; v[c].y *= inv; v[c].z *= inv; v[c].w *= inv;
        float vv[4] = { v[c].x, v[c].y, v[c].z, v[c].w };
        __align__(8) bf16 vb[4], vsm[4];
#pragma unroll
        for (int e = 0; e < 4; e++) split1(vv[e], vb[e], vsm[e]);
        const size_t off = (size_t)row * N_ + c*1024 + t*4;
        *(uint2*)&Sb[off] = *(uint2*)vb;
        *(uint2*)&Ss[off] = *(uint2*)vsm;
        const int j = c*1024 + t*4;
        a0 = fmaf(v[c].x, xs[j], fmaf(v[c].y, xs[j+1], fmaf(v[c].z, xs[j+2], fmaf(v[c].w, xs[j+3], a0))));
        a1 = fmaf(v[c].x, ys[j], fmaf(v[c].y, ys[j+1], fmaf(v[c].z, ys[j+2], fmaf(v[c].w, ys[j+3], a1))));
        a2 = fmaf(v[c].x, zs[j], fmaf(v[c].y, zs[j+1], fmaf(v[c].z, zs[j+2], fmaf(v[c].w, zs[j+3], a2))));
    }
    r0[t]=a0; r1[t]=a1; r2[t]=a2; __syncthreads();
    for (int s = 128; s > 0; s >>= 1) {
        if (t < s) { r0[t]+=r0[t+s]; r1[t]+=r1[t+s]; r2[t]+=r2[t+s]; }
        __syncthreads();
    }
    if (t == 0) { out[row*3+0]=r0[0]; out[row*3+1]=r1[0]; out[row*3+2]=r2[0]; }
}

__global__ void xyz2soa(const float* __restrict__ xyz, float* __restrict__ xs,
                        float* __restrict__ ys, float* __restrict__ zs)
{
    int i = blockIdx.x * blockDim.x + threadIdx.x;
    if (i < N_) { xs[i] = xyz[3*i]; ys[i] = xyz[3*i+1]; zs[i] = xyz[3*i+2]; }
}

// ---------------- GAT pieces ----------------
__global__ void compute_elr(const float* __restrict__ hl, const float* __restrict__ al,
                            const float* __restrict__ ar)
{
    int idx = blockIdx.x * blockDim.x + threadIdx.x;
    if (idx >= N_*4) return;
    int node = idx >> 2, h = idx & 3;
    const float* row = hl + (size_t)node * HID_ + h * 64;
    float sl = 0.f, sr = 0.f;
#pragma unroll 8
    for (int d = 0; d < 64; d++) {
        float v = row[d];
        sl = fmaf(v, al[h*64+d], sl);
        sr = fmaf(v, ar[h*64+d], sr);
    }
    g_el[idx] = sl; g_er[idx] = sr;
}

__global__ void zero_cnt() { int i = blockIdx.x*blockDim.x + threadIdx.x; if (i < N_) g_cnt[i] = 0; }
__global__ void count_edges(const int* __restrict__ dst) {
    int e = blockIdx.x*blockDim.x + threadIdx.x; if (e < E_) atomicAdd(&g_cnt[dst[e]], 1);
}
__global__ void scan4096() {
    __shared__ int part[1024];
    int t = threadIdx.x, base = t * 4;
    int a0 = g_cnt[base], a1 = g_cnt[base+1], a2 = g_cnt[base+2], a3 = g_cnt[base+3];
    int s = a0 + a1 + a2 + a3;
    part[t] = s; __syncthreads();
    for (int off = 1; off < 1024; off <<= 1) {
        int v = (t >= off) ? part[t-off] : 0;
        __syncthreads();
        part[t] += v;
        __syncthreads();
    }
    int excl = part[t] - s;
    g_rowptr[base+0] = excl;           g_cur[base+0] = excl;
    g_rowptr[base+1] = excl+a0;        g_cur[base+1] = excl+a0;
    g_rowptr[base+2] = excl+a0+a1;     g_cur[base+2] = excl+a0+a1;
    g_rowptr[base+3] = excl+a0+a1+a2;  g_cur[base+3] = excl+a0+a1+a2;
    if (t == 1023) g_rowptr[4096] = part[1023];
}
__global__ void scatter_edges(const int* __restrict__ src, const int* __restrict__ dst) {
    int e = blockIdx.x*blockDim.x + threadIdx.x;
    if (e < E_) { int p = atomicAdd(&g_cur[dst[e]], 1); g_psrc[p] = src[e]; }
}

__global__ void gat_aggregate(const float* __restrict__ hl, float* __restrict__ xg)
{
    const int node = (blockIdx.x * blockDim.x + threadIdx.x) >> 5;
    const int lane = threadIdx.x & 31;
    if (node >= N_) return;
    const int beg = g_rowptr[node], end = g_rowptr[node+1];
    const float er_i = (lane < 4) ? g_er[node*4 + lane] : 0.f;
    float m = -1e30f;
    for (int p = beg; p < end; p++) {
        int s = g_psrc[p];
        if (lane < 4) {
            float v = g_el[s*4 + lane] + er_i;
            float e = (v > 0.f) ? v : 0.2f * v;
            m = fmaxf(m, e);
        }
    }
    float m0 = __shfl_sync(0xffffffffu, m, 0), m1 = __shfl_sync(0xffffffffu, m, 1);
    float m2 = __shfl_sync(0xffffffffu, m, 2), m3 = __shfl_sync(0xffffffffu, m, 3);
    const int myh = lane >> 3;
    float4 acc0 = {0,0,0,0}, acc1 = {0,0,0,0};
    float z = 0.f;
    for (int p = beg; p < end; p++) {
        int s = g_psrc[p];
        float w = 0.f;
        if (lane < 4) {
            float v = g_el[s*4 + lane] + er_i;
            float e = (v > 0.f) ? v : 0.2f * v;
            float mm = (lane==0)?m0:(lane==1)?m1:(lane==2)?m2:m3;
            w = expf(e - mm);
            z += w;
        }
        float w0 = __shfl_sync(0xffffffffu, w, 0), w1 = __shfl_sync(0xffffffffu, w, 1);
        float w2 = __shfl_sync(0xffffffffu, w, 2), w3 = __shfl_sync(0xffffffffu, w, 3);
        float wm = (myh==0)?w0:(myh==1)?w1:(myh==2)?w2:w3;
        const float4* hp = (const float4*)(hl + (size_t)s * HID_ + lane * 8);
        float4 hv0 = hp[0], hv1 = hp[1];
        acc0.x=fmaf(wm,hv0.x,acc0.x); acc0.y=fmaf(wm,hv0.y,acc0.y);
        acc0.z=fmaf(wm,hv0.z,acc0.z); acc0.w=fmaf(wm,hv0.w,acc0.w);
        acc1.x=fmaf(wm,hv1.x,acc1.x); acc1.y=fmaf(wm,hv1.y,acc1.y);
        acc1.z=fmaf(wm,hv1.z,acc1.z); acc1.w=fmaf(wm,hv1.w,acc1.w);
    }
    float z0 = __shfl_sync(0xffffffffu, z, 0), z1 = __shfl_sync(0xffffffffu, z, 1);
    float z2 = __shfl_sync(0xffffffffu, z, 2), z3 = __shfl_sync(0xffffffffu, z, 3);
    float zm = (myh==0)?z0:(myh==1)?z1:(myh==2)?z2:z3;
    float inv = 1.0f / (zm + 1e-9f);
    acc0.x*=inv; acc0.y*=inv; acc0.z*=inv; acc0.w*=inv;
    acc1.x*=inv; acc1.y*=inv; acc1.z*=inv; acc1.w*=inv;
    float4* op = (float4*)(xg + (size_t)node * HID_ + lane * 8);
    op[0] = acc0; op[1] = acc1;
}

// pack support [xg, h0] -> bf16 split only
__global__ void pack_support(const float* __restrict__ xg, const float* __restrict__ h0,
                             bf16* __restrict__ supb, bf16* __restrict__ sups)
{
    int i = blockIdx.x * blockDim.x + threadIdx.x;
    if (i >= N_ * 512) return;
    int r = i >> 9, c = i & 511;
    float v = (c < 256) ? xg[(size_t)r*256 + c] : h0[(size_t)r*256 + (c-256)];
    bf16 b, s; split1(v, b, s);
    supb[i] = b; sups[i] = s;
}

__global__ void yhat_k(const float* __restrict__ x, const float* __restrict__ W,
                       const float* __restrict__ b)
{
    int i = blockIdx.x * blockDim.x + threadIdx.x;
    if (i >= N_) return;
    const float* r = x + (size_t)i * HID_;
    float l0 = b[0], l1 = b[1];
#pragma unroll 8
    for (int d = 0; d < HID_; d++) {
        float v = r[d];
        l0 = fmaf(v, W[2*d+0], l0);
        l1 = fmaf(v, W[2*d+1], l1);
    }
    g_y[i] = 1.0f / (1.0f + expf(l0 - l1));
}

__global__ void cls_k(const float* __restrict__ x, const float* __restrict__ W,
                      const float* __restrict__ b, float* __restrict__ out)
{
    int i = blockIdx.x * blockDim.x + threadIdx.x;
    if (i >= N_) return;
    const float* r = x + (size_t)i * HID_;
    float l0 = b[0], l1 = b[1];
#pragma unroll 8
    for (int d = 0; d < HID_; d++) {
        float v = r[d];
        l0 = fmaf(v, W[2*d+0], l0);
        l1 = fmaf(v, W[2*d+1], l1);
    }
    out[2*i+0] = l0;
    out[2*i+1] = l1;
}

// ---------------- host orchestration ----------------
extern "C" void kernel_launch(void* const* d_in, const int* in_sizes, int n_in,
                              void* d_out, int out_size)
{
    const float* feat   = (const float*)d_in[0];
    const float* xyz_in = (const float*)d_in[1];
    const int*   src    = (const int*)  d_in[2];
    const int*   dst    = (const int*)  d_in[3];
    const void*  dmask  = d_in[4];
    const void*  bmask  = d_in[5];
    const float* fcW  = (const float*)d_in[6];
    const float* fcb  = (const float*)d_in[7];
    const float* gatW = (const float*)d_in[8];
    const float* al   = (const float*)d_in[9];
    const float* ar   = (const float*)d_in[10];
    const float* gcW  = (const float*)d_in[11];
    const float* cgW  = (const float*)d_in[12];
    const float* cgb  = (const float*)d_in[13];
    const float* qW   = (const float*)d_in[14];
    const float* qb_  = (const float*)d_in[15];
    const float* kW   = (const float*)d_in[16];
    const float* kb_  = (const float*)d_in[17];
    const float* vW   = (const float*)d_in[18];
    const float* vb_  = (const float*)d_in[19];
    const float* oW   = (const float*)d_in[20];
    const float* ob   = (const float*)d_in[21];
    const float* clsW = (const float*)d_in[22];
    const float* clsb = (const float*)d_in[23];

    float *px, *ph0, *phl, *pxg, *pS, *pxyz0, *pxyz1, *pxs, *pys, *pzs, *ppart;
    bf16 *pxb, *pxs2, *pfeatb, *pfeats, *psupb, *psups, *phmsb, *phmss;
    bf16 *pqb2, *pqs2, *pkb2, *pks2, *pvtb2, *pvts2, *psb2, *pss2;
    bf16 *pfcWtb, *pfcWts, *pgatWtb, *pgatWts, *pgcWtb, *pgcWts;
    bf16 *pqWtb, *pqWts, *pkWtb, *pkWts, *pvWtb, *pvWts, *poWtb, *poWts;
    cudaGetSymbolAddress((void**)&px,    g_x);
    cudaGetSymbolAddress((void**)&ph0,   g_h0);
    cudaGetSymbolAddress((void**)&phl,   g_hl);
    cudaGetSymbolAddress((void**)&pxg,   g_xg);
    cudaGetSymbolAddress((void**)&pS,    g_S);
    cudaGetSymbolAddress((void**)&pxyz0, g_xyz0);
    cudaGetSymbolAddress((void**)&pxyz1, g_xyz1);
    cudaGetSymbolAddress((void**)&pxs,   g_xs_);
    cudaGetSymbolAddress((void**)&pys,   g_ys_);
    cudaGetSymbolAddress((void**)&pzs,   g_zs_);
    cudaGetSymbolAddress((void**)&ppart, g_part);
    cudaGetSymbolAddress((void**)&pxb,   g_xb);
    cudaGetSymbolAddress((void**)&pxs2,  g_xs);
    cudaGetSymbolAddress((void**)&pfeatb,g_featb);
    cudaGetSymbolAddress((void**)&pfeats,g_feats);
    cudaGetSymbolAddress((void**)&psupb, g_supb);
    cudaGetSymbolAddress((void**)&psups, g_sups);
    cudaGetSymbolAddress((void**)&phmsb, g_hmsb);
    cudaGetSymbolAddress((void**)&phmss, g_hmss);
    cudaGetSymbolAddress((void**)&pqb2,  g_qb2);
    cudaGetSymbolAddress((void**)&pqs2,  g_qs2);
    cudaGetSymbolAddress((void**)&pkb2,  g_kb2);
    cudaGetSymbolAddress((void**)&pks2,  g_ks2);
    cudaGetSymbolAddress((void**)&pvtb2, g_vtb2);
    cudaGetSymbolAddress((void**)&pvts2, g_vts2);
    cudaGetSymbolAddress((void**)&psb2,  g_sb2);
    cudaGetSymbolAddress((void**)&pss2,  g_ss2);
    cudaGetSymbolAddress((void**)&pfcWtb, g_fcWtb);
    cudaGetSymbolAddress((void**)&pfcWts, g_fcWts);
    cudaGetSymbolAddress((void**)&pgatWtb, g_gatWtb);
    cudaGetSymbolAddress((void**)&pgatWts, g_gatWts);
    cudaGetSymbolAddress((void**)&pgcWtb, g_gcWtb);
    cudaGetSymbolAddress((void**)&pgcWts, g_gcWts);
    cudaGetSymbolAddress((void**)&pqWtb, g_qWtb);
    cudaGetSymbolAddress((void**)&pqWts, g_qWts);
    cudaGetSymbolAddress((void**)&pkWtb, g_kWtb);
    cudaGetSymbolAddress((void**)&pkWts, g_kWts);
    cudaGetSymbolAddress((void**)&pvWtb, g_vWtb);
    cudaGetSymbolAddress((void**)&pvWts, g_vWts);
    cudaGetSymbolAddress((void**)&poWtb, g_oWtb);
    cudaGetSymbolAddress((void**)&poWts, g_oWts);

    detect_mask_mode<<<1, 1>>>((const unsigned int*)dmask);

    // weight transpose-splits (once per launch)
    wsplit<<<(FEAT_*HID_)/256, 256>>>(fcW, pfcWtb, pfcWts, FEAT_, HID_, FEAT_*HID_);
    wsplit<<<(4*HID_*HID_)/256, 256>>>(gatW, pgatWtb, pgatWts, HID_, HID_, HID_*HID_);
    wsplit<<<(4*2*HID_*HID_)/256, 256>>>(gcW, pgcWtb, pgcWts, 2*HID_, HID_, 2*HID_*HID_);
    wsplit<<<(4*HID_*HID_)/256, 256>>>(qW, pqWtb, pqWts, HID_, HID_, HID_*HID_);
    wsplit<<<(4*HID_*HID_)/256, 256>>>(kW, pkWtb, pkWts, HID_, HID_, HID_*HID_);
    wsplit<<<(4*HID_*HID_)/256, 256>>>(vW, pvWtb, pvWts, HID_, HID_, HID_*HID_);
    wsplit<<<(4*HID_*HID_)/256, 256>>>(oW, poWtb, poWts, HID_, HID_, HID_*HID_);
    split_bf16<<<(N_*FEAT_/4)/256, 256>>>(feat, pfeatb, pfeats);

    // fc: x = relu(feat@fcW + b); h0 = x; emit xb/xs
    gemm_tc<<<dim3(HID_/64, N_/128), 256>>>(pfeatb, pfeats, pfcWtb, pfcWts, FEAT_, HID_,
                                            fcb, 1, 1.0f, nullptr,0.f, nullptr,0.f, nullptr,0.f,
                                            px, ph0, pxb, pxs2, nullptr, nullptr);

    zero_cnt<<<N_/256, 256>>>();
    count_edges<<<E_/256, 256>>>(dst);
    scan4096<<<1, 1024>>>();
    scatter_edges<<<E_/256, 256>>>(src, dst);

    const float ALPHA = 0.1f, LAMDA = 0.5f;
    for (int l = 0; l < 4; l++) {
        gemm_tc<<<dim3(HID_/64, N_/128), 256>>>(pxb, pxs2, pgatWtb + (size_t)l*HID_*HID_,
                                                pgatWts + (size_t)l*HID_*HID_, HID_, HID_,
                                                nullptr, 0, 1.0f, nullptr,0.f, nullptr,0.f, nullptr,0.f,
                                                phl, nullptr, nullptr, nullptr, nullptr, nullptr);
        compute_elr<<<(N_*4)/256, 256>>>(phl, al + l*4*64, ar + l*4*64);
        gat_aggregate<<<N_/8, 256>>>(phl, pxg);
        pack_support<<<(N_*512)/256, 256>>>(pxg, ph0, psupb, psups);
        float theta = fminf(1.0f, logf(LAMDA / (float)(l + 1) + 1.0f));
        gemm_tc<<<dim3(HID_/64, N_/128), 256>>>(psupb, psups, pgcWtb + (size_t)l*2*HID_*HID_,
                                                pgcWts + (size_t)l*2*HID_*HID_, 2*HID_, HID_,
                                                nullptr, 0, theta,
                                                pxg, (1.0f-theta)*(1.0f-ALPHA),
                                                ph0, (1.0f-theta)*ALPHA,
                                                px,  1.0f,
                                                px, nullptr, pxb, pxs2, nullptr, nullptr);
    }

    yhat_k<<<N_/256, 256>>>(px, cgW, cgb);

    const float* xyz_cur = xyz_in;
    float* xyz_buf[2] = { pxyz0, pxyz1 };
    for (int l = 0; l < 4; l++) {
        gemm_tc<<<dim3(HID_/64, N_/128), 256>>>(pxb, pxs2, pqWtb + (size_t)l*HID_*HID_,
                                                pqWts + (size_t)l*HID_*HID_, HID_, HID_,
                                                qb_ + l*HID_, 0, 1.0f, nullptr,0.f, nullptr,0.f, nullptr,0.f,
                                                nullptr, nullptr, pqb2, pqs2, nullptr, nullptr);
        gemm_tc<<<dim3(HID_/64, N_/128), 256>>>(pxb, pxs2, pkWtb + (size_t)l*HID_*HID_,
                                                pkWts + (size_t)l*HID_*HID_, HID_, HID_,
                                                kb_ + l*HID_, 0, 1.0f, nullptr,0.f, nullptr,0.f, nullptr,0.f,
                                                nullptr, nullptr, pkb2, pks2, nullptr, nullptr);
        gemm_tc<<<dim3(HID_/64, N_/128), 256>>>(pxb, pxs2, pvWtb + (size_t)l*HID_*HID_,
                                                pvWts + (size_t)l*HID_*HID_, HID_, HID_,
                                                vb_ + l*HID_, 0, 1.0f, nullptr,0.f, nullptr,0.f, nullptr,0.f,
                                                nullptr, nullptr, nullptr, nullptr, pvtb2, pvts2);
        scores_mma<<<dim3(N_/128, N_/128), 256>>>(pqb2, pqs2, pkb2, pks2,
                                                  xyz_cur, dmask, bmask, pS);
        xyz2soa<<<N_/256, 256>>>(xyz_cur, pxs, pys, pzs);
        softmax_xyz<<<N_, 256>>>(pS, psb2, pss2, pxs, pys, pzs, xyz_buf[l & 1]);
        attnv_mma<<<dim3(HID_/128, N_/128, KZ_), 256>>>(psb2, pss2, pvtb2, pvts2, ppart);
        combine_parts<<<(N_*HID_/4)/256, 256>>>(ppart, phmsb, phmss);
        gemm_tc<<<dim3(HID_/64, N_/128), 256>>>(phmsb, phmss, poWtb + (size_t)l*HID_*HID_,
                                                poWts + (size_t)l*HID_*HID_, HID_, HID_,
                                                ob + l*HID_, 0, 1.0f,
                                                px, 1.0f, nullptr,0.f, nullptr,0.f,
                                                px, nullptr, pxb, pxs2, nullptr, nullptr);
        xyz_cur = xyz_buf[l & 1];
    }

    cls_k<<<N_/256, 256>>>(px, clsW, clsb, (float*)d_out);
}

// round 10
// speedup vs baseline: 1.5399x; 1.0298x over previous
#include <cuda_runtime.h>
#include <cuda_bf16.h>
#include <math.h>
#include <stdint.h>

#define N_    4096
#define E_    131072
#define FEAT_ 64
#define HID_  256
#define NEG_  (-1e9f)
#define KZ_   4

typedef __nv_bfloat16 bf16;

// ---------------- scratch ----------------
__device__ float g_h0 [N_*HID_];
__device__ float g_x  [N_*HID_];
__device__ float g_hl [N_*HID_];
__device__ float g_xg [N_*HID_];
__device__ float g_part[(size_t)KZ_*N_*HID_];
__device__ float g_S  [(size_t)N_*N_];
__device__ bf16 g_xb[N_*HID_], g_xs[N_*HID_];
__device__ bf16 g_featb[N_*FEAT_], g_feats[N_*FEAT_];
__device__ bf16 g_supb[N_*2*HID_], g_sups[N_*2*HID_];
__device__ bf16 g_hmsb[N_*HID_], g_hmss[N_*HID_];
__device__ bf16 g_qb2[N_*HID_], g_qs2[N_*HID_];
__device__ bf16 g_kb2[N_*HID_], g_ks2[N_*HID_];
__device__ bf16 g_vtb2[HID_*N_], g_vts2[HID_*N_];
__device__ bf16 g_sb2[(size_t)N_*N_], g_ss2[(size_t)N_*N_];
// transposed-split weights
__device__ bf16 g_fcWtb[HID_*FEAT_], g_fcWts[HID_*FEAT_];
__device__ bf16 g_gatWtb[4*HID_*HID_], g_gatWts[4*HID_*HID_];
__device__ bf16 g_gcWtb[4*HID_*2*HID_], g_gcWts[4*HID_*2*HID_];
__device__ bf16 g_qkvWtb[4*768*HID_], g_qkvWts[4*768*HID_];
__device__ float g_qkvb[4*768];
__device__ bf16 g_oWtb[4*HID_*HID_], g_oWts[4*HID_*HID_];
__device__ float g_el [N_*4];
__device__ float g_er [N_*4];
__device__ float g_y  [N_];
__device__ float g_xyz0[N_*3];
__device__ float g_xyz1[N_*3];
__device__ float g_xs_[N_], g_ys_[N_], g_zs_[N_];
__device__ int   g_cnt[N_];
__device__ int   g_rowptr[N_+1];
__device__ int   g_cur[N_];
__device__ int   g_psrc[E_];
__device__ int   g_maskmode;

// ---------------- helpers ----------------
__device__ __forceinline__ uint32_t smem_u32(const void* p) {
    uint32_t a;
    asm("{ .reg .u64 t; cvta.to.shared.u64 t, %1; cvt.u32.u64 %0, t; }" : "=r"(a) : "l"(p));
    return a;
}
#define LDMX4(r, a) \
    asm volatile("ldmatrix.sync.aligned.m8n8.x4.shared.b16 {%0,%1,%2,%3}, [%4];" \
        : "=r"((r)[0]), "=r"((r)[1]), "=r"((r)[2]), "=r"((r)[3]) : "r"(a))
#define MMA16816(c, a, b0, b1) \
    asm volatile("mma.sync.aligned.m16n8k16.row.col.f32.bf16.bf16.f32 " \
        "{%0,%1,%2,%3}, {%4,%5,%6,%7}, {%8,%9}, {%0,%1,%2,%3};" \
        : "+f"((c)[0]), "+f"((c)[1]), "+f"((c)[2]), "+f"((c)[3]) \
        : "r"((a)[0]), "r"((a)[1]), "r"((a)[2]), "r"((a)[3]), "r"(b0), "r"(b1))

__device__ __forceinline__ void split1(float v, bf16& b, bf16& s) {
    b = __float2bfloat16(v);
    s = __float2bfloat16(v - __bfloat162float(b));
}

__global__ void detect_mask_mode(const unsigned int* __restrict__ m) {
    bool allbin = true, anyfloat = false;
    for (int i = 0; i < 1024; i++) {
        unsigned int w = m[i];
        if (w == 0x3f800000u) anyfloat = true;
        if (w > 1u) allbin = false;
    }
    g_maskmode = anyfloat ? 2 : (allbin ? 1 : 0);
}
__device__ __forceinline__ bool mask_at(const void* p, size_t i, int mode) {
    if (mode == 0) return ((const unsigned char*)p)[i] != 0;
    if (mode == 1) return ((const int*)p)[i] != 0;
    return ((const float*)p)[i] != 0.0f;
}

__global__ void split_bf16(const float* __restrict__ X, bf16* __restrict__ Xb, bf16* __restrict__ Xs)
{
    int i = blockIdx.x * blockDim.x + threadIdx.x;
    float4 x = *(const float4*)&X[(size_t)i*4];
    float xv[4] = {x.x, x.y, x.z, x.w};
    __align__(8) bf16 b[4], s[4];
#pragma unroll
    for (int e = 0; e < 4; e++) split1(xv[e], b[e], s[e]);
    *(uint2*)&Xb[(size_t)i*4] = *(uint2*)b;
    *(uint2*)&Xs[(size_t)i*4] = *(uint2*)s;
}

// W [nmat][K,N] fp32 -> Wt [nmat][N,K] bf16 split
__global__ void wsplit(const float* __restrict__ W, bf16* __restrict__ Wtb,
                       bf16* __restrict__ Wts, int K, int N, int KN)
{
    int idx = blockIdx.x * 256 + threadIdx.x;
    int mat = idx / KN;
    int rem = idx - mat * KN;
    int k = rem / N;
    int n = rem - k * N;
    float v = W[idx];
    bf16 b, s; split1(v, b, s);
    int o = mat * KN + n * K + k;
    Wtb[o] = b; Wts[o] = s;
}

// q/k/v weights [4][256,256] -> combined [4][768,256] at row offset ro
__global__ void wsplit_ro(const float* __restrict__ W, bf16* __restrict__ Wtb,
                          bf16* __restrict__ Wts, int ro)
{
    int idx = blockIdx.x * 256 + threadIdx.x;     // over 4*256*256
    int l = idx >> 16;
    int rem = idx & 65535;
    int k = rem >> 8, n = rem & 255;
    float v = W[idx];
    bf16 b, s; split1(v, b, s);
    size_t o = (size_t)l * 768 * HID_ + (size_t)(ro + n) * HID_ + k;
    Wtb[o] = b; Wts[o] = s;
}

__global__ void qkvbias(const float* __restrict__ qb, const float* __restrict__ kb,
                        const float* __restrict__ vb, float* __restrict__ out)
{
    int idx = blockIdx.x * 256 + threadIdx.x;
    if (idx >= 4*768) return;
    int l = idx / 768, c = idx % 768;
    int sect = c >> 8, cc = c & 255;
    out[idx] = (sect == 0) ? qb[l*256+cc] : (sect == 1) ? kb[l*256+cc] : vb[l*256+cc];
}

// ================= gemm_tc64: 64x64 tile bf16-mma, 3-pass split =================
__global__ __launch_bounds__(256) void gemm_tc64(
    const bf16* __restrict__ Ab, const bf16* __restrict__ Asm,
    const bf16* __restrict__ Bb, const bf16* __restrict__ Bsm,
    int K, int Nc,
    const float* __restrict__ bias, int relu, float cacc,
    const float* __restrict__ X1, float c1,
    const float* __restrict__ X2, float c2,
    const float* __restrict__ X3, float c3,
    float* __restrict__ C, float* __restrict__ C2,
    bf16* __restrict__ Cb, bf16* __restrict__ Cs)
{
    __shared__ __align__(16) char Ash[2][64*80];
    __shared__ __align__(16) char Bsh[2][64*80];
    const int t = threadIdx.x, lane = t & 31, wid = t >> 5;
    const int wr32 = (wid >> 2) * 32, wc16 = (wid & 3) * 16;
    const int g = lane >> 2, tg = lane & 3;
    const int a_r = ((lane >> 3) & 1) * 8 + (lane & 7);
    const int a_c = (lane >> 4) * 16;
    const int b_r = ((lane >> 4) & 1) * 8 + (lane & 7);
    const int b_c = ((lane >> 3) & 1) * 16;
    const int m0 = blockIdx.y * 64, n0 = blockIdx.x * 64;
    const int lrow = t >> 2, lq = t & 3;

    uint32_t aS[2] = { smem_u32(Ash[0]), smem_u32(Ash[1]) };
    uint32_t bS[2] = { smem_u32(Bsh[0]), smem_u32(Bsh[1]) };
    float acc[2][2][4] = {};

    const bf16* APs[3] = { Ab, Ab, Asm };
    const bf16* BPs[3] = { Bb, Bsm, Bb };
    const int chunks = K >> 5;
    const int NC = 3 * chunks;

    uint4 va = *(const uint4*)(APs[0] + (size_t)(m0+lrow)*K + lq*8);
    uint4 vb = *(const uint4*)(BPs[0] + (size_t)(n0+lrow)*K + lq*8);
    *(uint4*)(Ash[0] + lrow*80 + lq*16) = va;
    *(uint4*)(Bsh[0] + lrow*80 + lq*16) = vb;
    __syncthreads();

    int pn = 0, kn = 0;
    for (int c = 0; c < NC; c++) {
        const int buf = c & 1;
        const bool more = (c + 1 < NC);
        if (more) {
            kn++; if (kn == chunks) { kn = 0; pn++; }
            va = *(const uint4*)(APs[pn] + (size_t)(m0+lrow)*K + kn*32 + lq*8);
            vb = *(const uint4*)(BPs[pn] + (size_t)(n0+lrow)*K + kn*32 + lq*8);
        }
#pragma unroll
        for (int kk = 0; kk < 2; kk++) {
            uint32_t af[2][4], bfr[4];
#pragma unroll
            for (int mt = 0; mt < 2; mt++) {
                uint32_t ad = aS[buf] + (uint32_t)((wr32 + mt*16 + a_r)*80 + kk*32 + a_c);
                LDMX4(af[mt], ad);
            }
            {
                uint32_t bd = bS[buf] + (uint32_t)((wc16 + b_r)*80 + kk*32 + b_c);
                LDMX4(bfr, bd);
            }
#pragma unroll
            for (int mt = 0; mt < 2; mt++)
#pragma unroll
                for (int nt = 0; nt < 2; nt++)
                    MMA16816(acc[mt][nt], af[mt], bfr[nt*2], bfr[nt*2+1]);
        }
        if (more) {
            const int nb = buf ^ 1;
            *(uint4*)(Ash[nb] + lrow*80 + lq*16) = va;
            *(uint4*)(Bsh[nb] + lrow*80 + lq*16) = vb;
            __syncthreads();
        }
    }

#pragma unroll
    for (int mt = 0; mt < 2; mt++) {
#pragma unroll
        for (int h = 0; h < 2; h++) {
            const int m = m0 + wr32 + mt*16 + g + 8*h;
            const size_t rb = (size_t)m * Nc;
#pragma unroll
            for (int nt = 0; nt < 2; nt++) {
                const int n = n0 + wc16 + nt*8 + 2*tg;
                float2 r = { acc[mt][nt][h*2], acc[mt][nt][h*2+1] };
                r.x *= cacc; r.y *= cacc;
                if (bias) { r.x += bias[n]; r.y += bias[n+1]; }
                if (X1) { float2 q = *(const float2*)&X1[rb+n];
                          r.x = fmaf(c1,q.x,r.x); r.y = fmaf(c1,q.y,r.y); }
                if (X2) { float2 q = *(const float2*)&X2[rb+n];
                          r.x = fmaf(c2,q.x,r.x); r.y = fmaf(c2,q.y,r.y); }
                if (X3) { float2 q = *(const float2*)&X3[rb+n];
                          r.x = fmaf(c3,q.x,r.x); r.y = fmaf(c3,q.y,r.y); }
                if (relu) { r.x = fmaxf(r.x, 0.f); r.y = fmaxf(r.y, 0.f); }
                if (C)  *(float2*)&C[rb+n]  = r;
                if (C2) *(float2*)&C2[rb+n] = r;
                if (Cb) {
                    __align__(4) bf16 b2[2], s2[2];
                    split1(r.x, b2[0], s2[0]); split1(r.y, b2[1], s2[1]);
                    *(uint32_t*)&Cb[rb+n] = *(uint32_t*)b2;
                    *(uint32_t*)&Cs[rb+n] = *(uint32_t*)s2;
                }
            }
        }
    }
}

// ================= qkv_tc: fused QKV GEMM, tile 128x64, Nc=768 routed =================
__global__ __launch_bounds__(256) void qkv_tc(
    const bf16* __restrict__ Ab, const bf16* __restrict__ Asm,
    const bf16* __restrict__ Bb, const bf16* __restrict__ Bsm,
    const float* __restrict__ bias,
    bf16* __restrict__ Qb, bf16* __restrict__ Qs,
    bf16* __restrict__ Kb, bf16* __restrict__ Ks,
    bf16* __restrict__ Vtb, bf16* __restrict__ Vts)
{
    __shared__ __align__(16) char Ash[2][128*80];
    __shared__ __align__(16) char Bsh[2][64*80];
    const int t = threadIdx.x, lane = t & 31, wid = t >> 5;
    const int wr32 = (wid >> 1) * 32, wc32 = (wid & 1) * 32;
    const int g = lane >> 2, tg = lane & 3;
    const int a_r = ((lane >> 3) & 1) * 8 + (lane & 7);
    const int a_c = (lane >> 4) * 16;
    const int b_r = ((lane >> 4) & 1) * 8 + (lane & 7);
    const int b_c = ((lane >> 3) & 1) * 16;
    const int m0 = blockIdx.y * 128, n0 = blockIdx.x * 64;
    const int K = HID_;

    uint32_t aS[2] = { smem_u32(Ash[0]), smem_u32(Ash[1]) };
    uint32_t bS[2] = { smem_u32(Bsh[0]), smem_u32(Bsh[1]) };
    float acc[2][4][4] = {};

    const bf16* APs[3] = { Ab, Ab, Asm };
    const bf16* BPs[3] = { Bb, Bsm, Bb };
    const int chunks = K >> 5;     // 8
    const int NC = 3 * chunks;     // 24

    uint4 va[2], vb;
#pragma unroll
    for (int i = 0; i < 2; i++) {
        int idx = t + i*256, row = idx >> 2, q = idx & 3;
        va[i] = *(const uint4*)(APs[0] + (size_t)(m0+row)*K + q*8);
    }
    { int row = t >> 2, q = t & 3;
      vb = *(const uint4*)(BPs[0] + (size_t)(n0+row)*K + q*8); }
#pragma unroll
    for (int i = 0; i < 2; i++) {
        int idx = t + i*256, row = idx >> 2, q = idx & 3;
        *(uint4*)(Ash[0] + row*80 + q*16) = va[i];
    }
    { int row = t >> 2, q = t & 3;
      *(uint4*)(Bsh[0] + row*80 + q*16) = vb; }
    __syncthreads();

    int pn = 0, kn = 0;
    for (int c = 0; c < NC; c++) {
        const int buf = c & 1;
        const bool more = (c + 1 < NC);
        if (more) {
            kn++; if (kn == chunks) { kn = 0; pn++; }
#pragma unroll
            for (int i = 0; i < 2; i++) {
                int idx = t + i*256, row = idx >> 2, q = idx & 3;
                va[i] = *(const uint4*)(APs[pn] + (size_t)(m0+row)*K + kn*32 + q*8);
            }
            { int row = t >> 2, q = t & 3;
              vb = *(const uint4*)(BPs[pn] + (size_t)(n0+row)*K + kn*32 + q*8); }
        }
#pragma unroll
        for (int kk = 0; kk < 2; kk++) {
            uint32_t af[2][4], bfr[2][4];
#pragma unroll
            for (int mt = 0; mt < 2; mt++) {
                uint32_t ad = aS[buf] + (uint32_t)((wr32 + mt*16 + a_r)*80 + kk*32 + a_c);
                LDMX4(af[mt], ad);
            }
#pragma unroll
            for (int np = 0; np < 2; np++) {
                uint32_t bd = bS[buf] + (uint32_t)((wc32 + np*16 + b_r)*80 + kk*32 + b_c);
                LDMX4(bfr[np], bd);
            }
#pragma unroll
            for (int mt = 0; mt < 2; mt++)
#pragma unroll
                for (int nt = 0; nt < 4; nt++)
                    MMA16816(acc[mt][nt], af[mt], bfr[nt>>1][(nt&1)*2], bfr[nt>>1][(nt&1)*2+1]);
        }
        if (more) {
            const int nb = buf ^ 1;
#pragma unroll
            for (int i = 0; i < 2; i++) {
                int idx = t + i*256, row = idx >> 2, q = idx & 3;
                *(uint4*)(Ash[nb] + row*80 + q*16) = va[i];
            }
            { int row = t >> 2, q = t & 3;
              *(uint4*)(Bsh[nb] + row*80 + q*16) = vb; }
            __syncthreads();
        }
    }

#pragma unroll
    for (int mt = 0; mt < 2; mt++) {
#pragma unroll
        for (int h = 0; h < 2; h++) {
            const int m = m0 + wr32 + mt*16 + g + 8*h;
#pragma unroll
            for (int nt = 0; nt < 4; nt++) {
                const int n = n0 + wc32 + nt*8 + 2*tg;   // 0..767, even
                float2 r = { acc[mt][nt][h*2], acc[mt][nt][h*2+1] };
                r.x += bias[n]; r.y += bias[n+1];
                bf16 b0, s0, b1, s1;
                split1(r.x, b0, s0); split1(r.y, b1, s1);
                const int sect = n >> 8, cc = n & 255;
                if (sect == 0) {
                    __align__(4) bf16 bb[2] = {b0, b1}, ss[2] = {s0, s1};
                    *(uint32_t*)&Qb[(size_t)m*HID_ + cc] = *(uint32_t*)bb;
                    *(uint32_t*)&Qs[(size_t)m*HID_ + cc] = *(uint32_t*)ss;
                } else if (sect == 1) {
                    __align__(4) bf16 bb[2] = {b0, b1}, ss[2] = {s0, s1};
                    *(uint32_t*)&Kb[(size_t)m*HID_ + cc] = *(uint32_t*)bb;
                    *(uint32_t*)&Ks[(size_t)m*HID_ + cc] = *(uint32_t*)ss;
                } else {
                    Vtb[(size_t)cc * N_ + m] = b0;     Vts[(size_t)cc * N_ + m] = s0;
                    Vtb[(size_t)(cc+1) * N_ + m] = b1; Vts[(size_t)(cc+1) * N_ + m] = s1;
                }
            }
        }
    }
}

// ---- shared mma-core macro (128x128 kernels) ----
#define COMPUTE32(abase, bbase)                                                     \
    _Pragma("unroll")                                                               \
    for (int kk = 0; kk < 2; kk++) {                                                \
        uint32_t af[4][4], bfr[2][4];                                               \
        _Pragma("unroll")                                                           \
        for (int mt = 0; mt < 4; mt++) {                                            \
            uint32_t ad = (abase) + (uint32_t)((wr64 + mt*16 + a_r)*80 + kk*32 + a_c); \
            LDMX4(af[mt], ad);                                                      \
        }                                                                           \
        _Pragma("unroll")                                                           \
        for (int np = 0; np < 2; np++) {                                            \
            uint32_t bd = (bbase) + (uint32_t)((wc32 + np*16 + b_r)*80 + kk*32 + b_c); \
            LDMX4(bfr[np], bd);                                                     \
        }                                                                           \
        _Pragma("unroll")                                                           \
        for (int mt = 0; mt < 4; mt++)                                              \
            _Pragma("unroll")                                                       \
            for (int nt = 0; nt < 4; nt++)                                          \
                MMA16816(acc[mt][nt], af[mt], bfr[nt>>1][(nt&1)*2], bfr[nt>>1][(nt&1)*2+1]); \
    }

// ================= scores via bf16 mma =================
__global__ __launch_bounds__(256) void scores_mma(
    const bf16* __restrict__ qb, const bf16* __restrict__ qs,
    const bf16* __restrict__ kb, const bf16* __restrict__ ks,
    const float* __restrict__ xyz,
    const void* __restrict__ dmask, const void* __restrict__ bmask,
    float* __restrict__ S)
{
    __shared__ __align__(16) char Ash[2][128*80];
    __shared__ __align__(16) char Bsh[2][128*80];
    __shared__ float gix[128*3], gisq[128], giy[128];
    __shared__ float gjx[128*3], gjsq[128], gjy[128];
    const int t = threadIdx.x, lane = t & 31, wid = t >> 5;
    const int wr64 = (wid >> 2) * 64, wc32 = (wid & 3) * 32;
    const int g = lane >> 2, tg = lane & 3;
    const int a_r = ((lane >> 3) & 1) * 8 + (lane & 7);
    const int a_c = (lane >> 4) * 16;
    const int b_r = ((lane >> 4) & 1) * 8 + (lane & 7);
    const int b_c = ((lane >> 3) & 1) * 16;
    const int i0 = blockIdx.y * 128, j0 = blockIdx.x * 128;
    const int lrow = t >> 2, lq = t & 3;

    if (t < 128) {
        float a = xyz[(i0+t)*3+0], b = xyz[(i0+t)*3+1], c = xyz[(i0+t)*3+2];
        gix[t*3+0]=a; gix[t*3+1]=b; gix[t*3+2]=c;
        gisq[t] = fmaf(c,c,fmaf(b,b,a*a));
        giy[t]  = g_y[i0+t];
    } else {
        int u = t - 128;
        float a = xyz[(j0+u)*3+0], b = xyz[(j0+u)*3+1], c = xyz[(j0+u)*3+2];
        gjx[u*3+0]=a; gjx[u*3+1]=b; gjx[u*3+2]=c;
        gjsq[u] = fmaf(c,c,fmaf(b,b,a*a));
        gjy[u]  = g_y[j0+u];
    }

    uint32_t aS[2] = { smem_u32(Ash[0]), smem_u32(Ash[1]) };
    uint32_t bS[2] = { smem_u32(Bsh[0]), smem_u32(Bsh[1]) };
    float acc[4][4][4] = {};

    const bf16* APs[3] = { qb, qb, qs };
    const bf16* BPs[3] = { kb, ks, kb };

    uint4 va[2], vb[2];
#pragma unroll
    for (int r = 0; r < 2; r++) {
        int row = lrow + r*64;
        va[r] = *(const uint4*)(APs[0] + (size_t)(i0+row)*HID_ + lq*8);
        vb[r] = *(const uint4*)(BPs[0] + (size_t)(j0+row)*HID_ + lq*8);
    }
#pragma unroll
    for (int r = 0; r < 2; r++) {
        int row = lrow + r*64;
        *(uint4*)(Ash[0] + row*80 + lq*16) = va[r];
        *(uint4*)(Bsh[0] + row*80 + lq*16) = vb[r];
    }
    __syncthreads();

    const int NC = 24;
    for (int c = 0; c < NC; c++) {
        const int buf = c & 1;
        if (c + 1 < NC) {
            const int p = (c+1) >> 3, kc = (c+1) & 7;
            const bf16* A = APs[p];
            const bf16* B = BPs[p];
#pragma unroll
            for (int r = 0; r < 2; r++) {
                int row = lrow + r*64;
                va[r] = *(const uint4*)(A + (size_t)(i0+row)*HID_ + kc*32 + lq*8);
                vb[r] = *(const uint4*)(B + (size_t)(j0+row)*HID_ + kc*32 + lq*8);
            }
        }
        COMPUTE32(aS[buf], bS[buf]);
        if (c + 1 < NC) {
            const int nb = buf ^ 1;
#pragma unroll
            for (int r = 0; r < 2; r++) {
                int row = lrow + r*64;
                *(uint4*)(Ash[nb] + row*80 + lq*16) = va[r];
                *(uint4*)(Bsh[nb] + row*80 + lq*16) = vb[r];
            }
            __syncthreads();
        }
    }

    const int mode = g_maskmode;
#pragma unroll
    for (int mt = 0; mt < 4; mt++) {
#pragma unroll
        for (int h = 0; h < 2; h++) {
            const int li = wr64 + mt*16 + g + 8*h;
            const int gi = i0 + li;
            const float xa = gix[li*3], xbv = gix[li*3+1], xc = gix[li*3+2];
            const float sqa = gisq[li], ya = giy[li];
            const size_t rb = (size_t)gi * N_;
#pragma unroll
            for (int nt = 0; nt < 4; nt++) {
                const int lj0 = wc32 + nt*8 + 2*tg;
                float2 r;
#pragma unroll
                for (int e = 0; e < 2; e++) {
                    const int lj = lj0 + e;
                    const size_t gidx = rb + j0 + lj;
                    float dot = fmaf(xc, gjx[lj*3+2], fmaf(xbv, gjx[lj*3+1], xa * gjx[lj*3]));
                    float dist2 = (sqa + gjsq[lj]) - 2.0f * dot;
                    bool ok = mask_at(dmask, gidx, mode) && mask_at(bmask, gidx, mode) && (dist2 <= 100.0f);
                    float av = acc[mt][nt][h*2 + e];
                    ((float*)&r)[e] = ok ? (av * 0.0625f - fabsf(ya - gjy[lj])) : NEG_;
                }
                *(float2*)&S[rb + j0 + lj0] = r;
            }
        }
    }
}

// ================= attn@V via bf16 mma, split-K z =================
__global__ __launch_bounds__(256) void attnv_mma(
    const bf16* __restrict__ Sb, const bf16* __restrict__ Ss,
    const bf16* __restrict__ Vtb, const bf16* __restrict__ Vts,
    float* __restrict__ Cpart)
{
    __shared__ __align__(16) char Ash[2][128*80];
    __shared__ __align__(16) char Bsh[2][128*80];
    const int t = threadIdx.x, lane = t & 31, wid = t >> 5;
    const int wr64 = (wid >> 2) * 64, wc32 = (wid & 3) * 32;
    const int g = lane >> 2, tg = lane & 3;
    const int a_r = ((lane >> 3) & 1) * 8 + (lane & 7);
    const int a_c = (lane >> 4) * 16;
    const int b_r = ((lane >> 4) & 1) * 8 + (lane & 7);
    const int b_c = ((lane >> 3) & 1) * 16;
    const int m0 = blockIdx.y * 128, n0 = blockIdx.x * 128;
    const int kbase = blockIdx.z * (N_ / KZ_);
    const int lrow = t >> 2, lq = t & 3;

    uint32_t aS[2] = { smem_u32(Ash[0]), smem_u32(Ash[1]) };
    uint32_t bS[2] = { smem_u32(Bsh[0]), smem_u32(Bsh[1]) };
    float acc[4][4][4] = {};

    const bf16* APs[3] = { Sb, Sb, Ss };
    const bf16* BPs[3] = { Vtb, Vts, Vtb };
    const int CPP = (N_ / KZ_) / 32;
    const int NC = 3 * CPP;

    uint4 va[2], vb[2];
#pragma unroll
    for (int r = 0; r < 2; r++) {
        int row = lrow + r*64;
        va[r] = *(const uint4*)(APs[0] + (size_t)(m0+row)*N_ + kbase + lq*8);
        vb[r] = *(const uint4*)(BPs[0] + (size_t)(n0+row)*N_ + kbase + lq*8);
    }
#pragma unroll
    for (int r = 0; r < 2; r++) {
        int row = lrow + r*64;
        *(uint4*)(Ash[0] + row*80 + lq*16) = va[r];
        *(uint4*)(Bsh[0] + row*80 + lq*16) = vb[r];
    }
    __syncthreads();

    for (int c = 0; c < NC; c++) {
        const int buf = c & 1;
        if (c + 1 < NC) {
            const int p = (c+1) / CPP, kc = (c+1) % CPP;
            const bf16* A = APs[p];
            const bf16* B = BPs[p];
#pragma unroll
            for (int r = 0; r < 2; r++) {
                int row = lrow + r*64;
                va[r] = *(const uint4*)(A + (size_t)(m0+row)*N_ + kbase + kc*32 + lq*8);
                vb[r] = *(const uint4*)(B + (size_t)(n0+row)*N_ + kbase + kc*32 + lq*8);
            }
        }
        COMPUTE32(aS[buf], bS[buf]);
        if (c + 1 < NC) {
            const int nb = buf ^ 1;
#pragma unroll
            for (int r = 0; r < 2; r++) {
                int row = lrow + r*64;
                *(uint4*)(Ash[nb] + row*80 + lq*16) = va[r];
                *(uint4*)(Bsh[nb] + row*80 + lq*16) = vb[r];
            }
            __syncthreads();
        }
    }

    float* Cz = Cpart + (size_t)blockIdx.z * N_ * HID_;
#pragma unroll
    for (int mt = 0; mt < 4; mt++) {
#pragma unroll
        for (int h = 0; h < 2; h++) {
            const int m = m0 + wr64 + mt*16 + g + 8*h;
            const size_t rb = (size_t)m * HID_;
#pragma unroll
            for (int nt = 0; nt < 4; nt++) {
                const int n = n0 + wc32 + nt*8 + 2*tg;
                float2 r = { acc[mt][nt][h*2], acc[mt][nt][h*2 + 1] };
                *(float2*)&Cz[rb + n] = r;
            }
        }
    }
}

__global__ void combine_parts(const float* __restrict__ P,
                              bf16* __restrict__ Hb, bf16* __restrict__ Hs)
{
    int i = blockIdx.x * blockDim.x + threadIdx.x;
    const size_t n = (size_t)N_ * HID_;
    float4 a = *(const float4*)&P[(size_t)i*4];
    float4 b = *(const float4*)&P[n + (size_t)i*4];
    float4 c = *(const float4*)&P[2*n + (size_t)i*4];
    float4 d = *(const float4*)&P[3*n + (size_t)i*4];
    float rv[4] = { a.x+b.x+c.x+d.x, a.y+b.y+c.y+d.y, a.z+b.z+c.z+d.z, a.w+b.w+c.w+d.w };
    __align__(8) bf16 hb[4], hs[4];
#pragma unroll
    for (int e = 0; e < 4; e++) split1(rv[e], hb[e], hs[e]);
    *(uint2*)&Hb[(size_t)i*4] = *(uint2*)hb;
    *(uint2*)&Hs[(size_t)i*4] = *(uint2*)hs;
}

// ---------------- softmax + attn@xyz + bf16 split ----------------
__global__ void softmax_xyz(const float* __restrict__ S,
                            bf16* __restrict__ Sb, bf16* __restrict__ Ss,
                            const float* __restrict__ xs, const float* __restrict__ ys,
                            const float* __restrict__ zs, float* __restrict__ out)
{
    __shared__ float r0[256], r1[256], r2[256];
    const int row = blockIdx.x, t = threadIdx.x;
    const float* p = S + (size_t)row * N_;
    float4 v[4];
    float mx = -1e30f;
#pragma unroll
    for (int c = 0; c < 4; c++) {
        v[c] = *(const float4*)&p[c*1024 + t*4];
        mx = fmaxf(mx, fmaxf(fmaxf(v[c].x, v[c].y), fmaxf(v[c].z, v[c].w)));
    }
    r0[t] = mx; __syncthreads();
    for (int s = 128; s > 0; s >>= 1) { if (t < s) r0[t] = fmaxf(r0[t], r0[t+s]); __syncthreads(); }
    mx = r0[0]; __syncthreads();
    float sum = 0.0f;
#pragma unroll
    for (int c = 0; c < 4; c++) {
        v[c].x = expf(v[c].x - mx); v[c].y = expf(v[c].y - mx);
        v[c].z = expf(v[c].z - mx); v[c].w = expf(v[c].w - mx);
        sum += v[c].x + v[c].y + v[c].z + v[c].w;
    }
    r0[t] = sum; __syncthreads();
    for (int s = 128; s > 0; s >>= 1) { if (t < s) r0[t] += r0[t+s]; __syncthreads(); }
    const float inv = 1.0f / r0[0];
    __syncthreads();
    float a0 = 0.f, a1 = 0.f, a2 = 0.f;
#pragma unroll
    for (int c = 0; c < 4; c++) {
        v[c].x *= inv; v[c].y *= inv; v[c].z *= inv; v[c].w *= inv;
        float vv[4] = { v[c].x, v[c].y, v[c].z, v[c].w };
        __align__(8) bf16 vb[4], vsm[4];
#pragma unroll
        for (int e = 0; e < 4; e++) split1(vv[e], vb[e], vsm[e]);
        const size_t off = (size_t)row * N_ + c*1024 + t*4;
        *(uint2*)&Sb[off] = *(uint2*)vb;
        *(uint2*)&Ss[off] = *(uint2*)vsm;
        const int j = c*1024 + t*4;
        a0 = fmaf(v[c].x, xs[j], fmaf(v[c].y, xs[j+1], fmaf(v[c].z, xs[j+2], fmaf(v[c].w, xs[j+3], a0))));
        a1 = fmaf(v[c].x, ys[j], fmaf(v[c].y, ys[j+1], fmaf(v[c].z, ys[j+2], fmaf(v[c].w, ys[j+3], a1))));
        a2 = fmaf(v[c].x, zs[j], fmaf(v[c].y, zs[j+1], fmaf(v[c].z, zs[j+2], fmaf(v[c].w, zs[j+3], a2))));
    }
    r0[t]=a0; r1[t]=a1; r2[t]=a2; __syncthreads();
    for (int s = 128; s > 0; s >>= 1) {
        if (t < s) { r0[t]+=r0[t+s]; r1[t]+=r1[t+s]; r2[t]+=r2[t+s]; }
        __syncthreads();
    }
    if (t == 0) { out[row*3+0]=r0[0]; out[row*3+1]=r1[0]; out[row*3+2]=r2[0]; }
}

__global__ void xyz2soa(const float* __restrict__ xyz, float* __restrict__ xs,
                        float* __restrict__ ys, float* __restrict__ zs)
{
    int i = blockIdx.x * blockDim.x + threadIdx.x;
    if (i < N_) { xs[i] = xyz[3*i]; ys[i] = xyz[3*i+1]; zs[i] = xyz[3*i+2]; }
}

// ---------------- GAT pieces ----------------
__global__ void compute_elr(const float* __restrict__ hl, const float* __restrict__ al,
                            const float* __restrict__ ar)
{
    int idx = blockIdx.x * blockDim.x + threadIdx.x;
    if (idx >= N_*4) return;
    int node = idx >> 2, h = idx & 3;
    const float* row = hl + (size_t)node * HID_ + h * 64;
    float sl = 0.f, sr = 0.f;
#pragma unroll 8
    for (int d = 0; d < 64; d++) {
        float v = row[d];
        sl = fmaf(v, al[h*64+d], sl);
        sr = fmaf(v, ar[h*64+d], sr);
    }
    g_el[idx] = sl; g_er[idx] = sr;
}

__global__ void zero_cnt() { int i = blockIdx.x*blockDim.x + threadIdx.x; if (i < N_) g_cnt[i] = 0; }
__global__ void count_edges(const int* __restrict__ dst) {
    int e = blockIdx.x*blockDim.x + threadIdx.x; if (e < E_) atomicAdd(&g_cnt[dst[e]], 1);
}
__global__ void scan4096() {
    __shared__ int part[1024];
    int t = threadIdx.x, base = t * 4;
    int a0 = g_cnt[base], a1 = g_cnt[base+1], a2 = g_cnt[base+2], a3 = g_cnt[base+3];
    int s = a0 + a1 + a2 + a3;
    part[t] = s; __syncthreads();
    for (int off = 1; off < 1024; off <<= 1) {
        int v = (t >= off) ? part[t-off] : 0;
        __syncthreads();
        part[t] += v;
        __syncthreads();
    }
    int excl = part[t] - s;
    g_rowptr[base+0] = excl;           g_cur[base+0] = excl;
    g_rowptr[base+1] = excl+a0;        g_cur[base+1] = excl+a0;
    g_rowptr[base+2] = excl+a0+a1;     g_cur[base+2] = excl+a0+a1;
    g_rowptr[base+3] = excl+a0+a1+a2;  g_cur[base+3] = excl+a0+a1+a2;
    if (t == 1023) g_rowptr[4096] = part[1023];
}
__global__ void scatter_edges(const int* __restrict__ src, const int* __restrict__ dst) {
    int e = blockIdx.x*blockDim.x + threadIdx.x;
    if (e < E_) { int p = atomicAdd(&g_cur[dst[e]], 1); g_psrc[p] = src[e]; }
}

__global__ void gat_aggregate(const float* __restrict__ hl, float* __restrict__ xg)
{
    const int node = (blockIdx.x * blockDim.x + threadIdx.x) >> 5;
    const int lane = threadIdx.x & 31;
    if (node >= N_) return;
    const int beg = g_rowptr[node], end = g_rowptr[node+1];
    const float er_i = (lane < 4) ? g_er[node*4 + lane] : 0.f;
    float m = -1e30f;
    for (int p = beg; p < end; p++) {
        int s = g_psrc[p];
        if (lane < 4) {
            float v = g_el[s*4 + lane] + er_i;
            float e = (v > 0.f) ? v : 0.2f * v;
            m = fmaxf(m, e);
        }
    }
    float m0 = __shfl_sync(0xffffffffu, m, 0), m1 = __shfl_sync(0xffffffffu, m, 1);
    float m2 = __shfl_sync(0xffffffffu, m, 2), m3 = __shfl_sync(0xffffffffu, m, 3);
    const int myh = lane >> 3;
    float4 acc0 = {0,0,0,0}, acc1 = {0,0,0,0};
    float z = 0.f;
    for (int p = beg; p < end; p++) {
        int s = g_psrc[p];
        float w = 0.f;
        if (lane < 4) {
            float v = g_el[s*4 + lane] + er_i;
            float e = (v > 0.f) ? v : 0.2f * v;
            float mm = (lane==0)?m0:(lane==1)?m1:(lane==2)?m2:m3;
            w = expf(e - mm);
            z += w;
        }
        float w0 = __shfl_sync(0xffffffffu, w, 0), w1 = __shfl_sync(0xffffffffu, w, 1);
        float w2 = __shfl_sync(0xffffffffu, w, 2), w3 = __shfl_sync(0xffffffffu, w, 3);
        float wm = (myh==0)?w0:(myh==1)?w1:(myh==2)?w2:w3;
        const float4* hp = (const float4*)(hl + (size_t)s * HID_ + lane * 8);
        float4 hv0 = hp[0], hv1 = hp[1];
        acc0.x=fmaf(wm,hv0.x,acc0.x); acc0.y=fmaf(wm,hv0.y,acc0.y);
        acc0.z=fmaf(wm,hv0.z,acc0.z); acc0.w=fmaf(wm,hv0.w,acc0.w);
        acc1.x=fmaf(wm,hv1.x,acc1.x); acc1.y=fmaf(wm,hv1.y,acc1.y);
        acc1.z=fmaf(wm,hv1.z,acc1.z); acc1.w=fmaf(wm,hv1.w,acc1.w);
    }
    float z0 = __shfl_sync(0xffffffffu, z, 0), z1 = __shfl_sync(0xffffffffu, z, 1);
    float z2 = __shfl_sync(0xffffffffu, z, 2), z3 = __shfl_sync(0xffffffffu, z, 3);
    float zm = (myh==0)?z0:(myh==1)?z1:(myh==2)?z2:z3;
    float inv = 1.0f / (zm + 1e-9f);
    acc0.x*=inv; acc0.y*=inv; acc0.z*=inv; acc0.w*=inv;
    acc1.x*=inv; acc1.y*=inv; acc1.z*=inv; acc1.w*=inv;
    float4* op = (float4*)(xg + (size_t)node * HID_ + lane * 8);
    op[0] = acc0; op[1] = acc1;
}

__global__ void pack_support(const float* __restrict__ xg, const float* __restrict__ h0,
                             bf16* __restrict__ supb, bf16* __restrict__ sups)
{
    int i = blockIdx.x * blockDim.x + threadIdx.x;
    if (i >= N_ * 512) return;
    int r = i >> 9, c = i & 511;
    float v = (c < 256) ? xg[(size_t)r*256 + c] : h0[(size_t)r*256 + (c-256)];
    bf16 b, s; split1(v, b, s);
    supb[i] = b; sups[i] = s;
}

__global__ void yhat_k(const float* __restrict__ x, const float* __restrict__ W,
                       const float* __restrict__ b)
{
    int i = blockIdx.x * blockDim.x + threadIdx.x;
    if (i >= N_) return;
    const float* r = x + (size_t)i * HID_;
    float l0 = b[0], l1 = b[1];
#pragma unroll 8
    for (int d = 0; d < HID_; d++) {
        float v = r[d];
        l0 = fmaf(v, W[2*d+0], l0);
        l1 = fmaf(v, W[2*d+1], l1);
    }
    g_y[i] = 1.0f / (1.0f + expf(l0 - l1));
}

__global__ void cls_k(const float* __restrict__ x, const float* __restrict__ W,
                      const float* __restrict__ b, float* __restrict__ out)
{
    int i = blockIdx.x * blockDim.x + threadIdx.x;
    if (i >= N_) return;
    const float* r = x + (size_t)i * HID_;
    float l0 = b[0], l1 = b[1];
#pragma unroll 8
    for (int d = 0; d < HID_; d++) {
        float v = r[d];
        l0 = fmaf(v, W[2*d+0], l0);
        l1 = fmaf(v, W[2*d+1], l1);
    }
    out[2*i+0] = l0;
    out[2*i+1] = l1;
}

// ---------------- host orchestration ----------------
extern "C" void kernel_launch(void* const* d_in, const int* in_sizes, int n_in,
                              void* d_out, int out_size)
{
    const float* feat   = (const float*)d_in[0];
    const float* xyz_in = (const float*)d_in[1];
    const int*   src    = (const int*)  d_in[2];
    const int*   dst    = (const int*)  d_in[3];
    const void*  dmask  = d_in[4];
    const void*  bmask  = d_in[5];
    const float* fcW  = (const float*)d_in[6];
    const float* fcb  = (const float*)d_in[7];
    const float* gatW = (const float*)d_in[8];
    const float* al   = (const float*)d_in[9];
    const float* ar   = (const float*)d_in[10];
    const float* gcW  = (const float*)d_in[11];
    const float* cgW  = (const float*)d_in[12];
    const float* cgb  = (const float*)d_in[13];
    const float* qW   = (const float*)d_in[14];
    const float* qb_  = (const float*)d_in[15];
    const float* kW   = (const float*)d_in[16];
    const float* kb_  = (const float*)d_in[17];
    const float* vW   = (const float*)d_in[18];
    const float* vb_  = (const float*)d_in[19];
    const float* oW   = (const float*)d_in[20];
    const float* ob   = (const float*)d_in[21];
    const float* clsW = (const float*)d_in[22];
    const float* clsb = (const float*)d_in[23];

    float *px, *ph0, *phl, *pxg, *pS, *pxyz0, *pxyz1, *pxs, *pys, *pzs, *ppart, *pqkvb;
    bf16 *pxb, *pxs2, *pfeatb, *pfeats, *psupb, *psups, *phmsb, *phmss;
    bf16 *pqb2, *pqs2, *pkb2, *pks2, *pvtb2, *pvts2, *psb2, *pss2;
    bf16 *pfcWtb, *pfcWts, *pgatWtb, *pgatWts, *pgcWtb, *pgcWts;
    bf16 *pqkvWtb, *pqkvWts, *poWtb, *poWts;
    cudaGetSymbolAddress((void**)&px,    g_x);
    cudaGetSymbolAddress((void**)&ph0,   g_h0);
    cudaGetSymbolAddress((void**)&phl,   g_hl);
    cudaGetSymbolAddress((void**)&pxg,   g_xg);
    cudaGetSymbolAddress((void**)&pS,    g_S);
    cudaGetSymbolAddress((void**)&pxyz0, g_xyz0);
    cudaGetSymbolAddress((void**)&pxyz1, g_xyz1);
    cudaGetSymbolAddress((void**)&pxs,   g_xs_);
    cudaGetSymbolAddress((void**)&pys,   g_ys_);
    cudaGetSymbolAddress((void**)&pzs,   g_zs_);
    cudaGetSymbolAddress((void**)&ppart, g_part);
    cudaGetSymbolAddress((void**)&pqkvb, g_qkvb);
    cudaGetSymbolAddress((void**)&pxb,   g_xb);
    cudaGetSymbolAddress((void**)&pxs2,  g_xs);
    cudaGetSymbolAddress((void**)&pfeatb,g_featb);
    cudaGetSymbolAddress((void**)&pfeats,g_feats);
    cudaGetSymbolAddress((void**)&psupb, g_supb);
    cudaGetSymbolAddress((void**)&psups, g_sups);
    cudaGetSymbolAddress((void**)&phmsb, g_hmsb);
    cudaGetSymbolAddress((void**)&phmss, g_hmss);
    cudaGetSymbolAddress((void**)&pqb2,  g_qb2);
    cudaGetSymbolAddress((void**)&pqs2,  g_qs2);
    cudaGetSymbolAddress((void**)&pkb2,  g_kb2);
    cudaGetSymbolAddress((void**)&pks2,  g_ks2);
    cudaGetSymbolAddress((void**)&pvtb2, g_vtb2);
    cudaGetSymbolAddress((void**)&pvts2, g_vts2);
    cudaGetSymbolAddress((void**)&psb2,  g_sb2);
    cudaGetSymbolAddress((void**)&pss2,  g_ss2);
    cudaGetSymbolAddress((void**)&pfcWtb, g_fcWtb);
    cudaGetSymbolAddress((void**)&pfcWts, g_fcWts);
    cudaGetSymbolAddress((void**)&pgatWtb, g_gatWtb);
    cudaGetSymbolAddress((void**)&pgatWts, g_gatWts);
    cudaGetSymbolAddress((void**)&pgcWtb, g_gcWtb);
    cudaGetSymbolAddress((void**)&pgcWts, g_gcWts);
    cudaGetSymbolAddress((void**)&pqkvWtb, g_qkvWtb);
    cudaGetSymbolAddress((void**)&pqkvWts, g_qkvWts);
    cudaGetSymbolAddress((void**)&poWtb, g_oWtb);
    cudaGetSymbolAddress((void**)&poWts, g_oWts);

    detect_mask_mode<<<1, 1>>>((const unsigned int*)dmask);

    // weight prep (once per launch)
    wsplit<<<(FEAT_*HID_)/256, 256>>>(fcW, pfcWtb, pfcWts, FEAT_, HID_, FEAT_*HID_);
    wsplit<<<(4*HID_*HID_)/256, 256>>>(gatW, pgatWtb, pgatWts, HID_, HID_, HID_*HID_);
    wsplit<<<(4*2*HID_*HID_)/256, 256>>>(gcW, pgcWtb, pgcWts, 2*HID_, HID_, 2*HID_*HID_);
    wsplit<<<(4*HID_*HID_)/256, 256>>>(oW, poWtb, poWts, HID_, HID_, HID_*HID_);
    wsplit_ro<<<(4*HID_*HID_)/256, 256>>>(qW, pqkvWtb, pqkvWts, 0);
    wsplit_ro<<<(4*HID_*HID_)/256, 256>>>(kW, pqkvWtb, pqkvWts, 256);
    wsplit_ro<<<(4*HID_*HID_)/256, 256>>>(vW, pqkvWtb, pqkvWts, 512);
    qkvbias<<<12, 256>>>(qb_, kb_, vb_, pqkvb);
    split_bf16<<<(N_*FEAT_/4)/256, 256>>>(feat, pfeatb, pfeats);

    // fc
    gemm_tc64<<<dim3(HID_/64, N_/64), 256>>>(pfeatb, pfeats, pfcWtb, pfcWts, FEAT_, HID_,
                                             fcb, 1, 1.0f, nullptr,0.f, nullptr,0.f, nullptr,0.f,
                                             px, ph0, pxb, pxs2);

    zero_cnt<<<N_/256, 256>>>();
    count_edges<<<E_/256, 256>>>(dst);
    scan4096<<<1, 1024>>>();
    scatter_edges<<<E_/256, 256>>>(src, dst);

    const float ALPHA = 0.1f, LAMDA = 0.5f;
    for (int l = 0; l < 4; l++) {
        gemm_tc64<<<dim3(HID_/64, N_/64), 256>>>(pxb, pxs2, pgatWtb + (size_t)l*HID_*HID_,
                                                 pgatWts + (size_t)l*HID_*HID_, HID_, HID_,
                                                 nullptr, 0, 1.0f, nullptr,0.f, nullptr,0.f, nullptr,0.f,
                                                 phl, nullptr, nullptr, nullptr);
        compute_elr<<<(N_*4)/256, 256>>>(phl, al + l*4*64, ar + l*4*64);
        gat_aggregate<<<N_/8, 256>>>(phl, pxg);
        pack_support<<<(N_*512)/256, 256>>>(pxg, ph0, psupb, psups);
        float theta = fminf(1.0f, logf(LAMDA / (float)(l + 1) + 1.0f));
        gemm_tc64<<<dim3(HID_/64, N_/64), 256>>>(psupb, psups, pgcWtb + (size_t)l*2*HID_*HID_,
                                                 pgcWts + (size_t)l*2*HID_*HID_, 2*HID_, HID_,
                                                 nullptr, 0, theta,
                                                 pxg, (1.0f-theta)*(1.0f-ALPHA),
                                                 ph0, (1.0f-theta)*ALPHA,
                                                 px,  1.0f,
                                                 px, nullptr, pxb, pxs2);
    }

    yhat_k<<<N_/256, 256>>>(px, cgW, cgb);

    const float* xyz_cur = xyz_in;
    float* xyz_buf[2] = { pxyz0, pxyz1 };
    for (int l = 0; l < 4; l++) {
        qkv_tc<<<dim3(768/64, N_/128), 256>>>(pxb, pxs2,
                                              pqkvWtb + (size_t)l*768*HID_,
                                              pqkvWts + (size_t)l*768*HID_,
                                              pqkvb + l*768,
                                              pqb2, pqs2, pkb2, pks2, pvtb2, pvts2);
        scores_mma<<<dim3(N_/128, N_/128), 256>>>(pqb2, pqs2, pkb2, pks2,
                                                  xyz_cur, dmask, bmask, pS);
        xyz2soa<<<N_/256, 256>>>(xyz_cur, pxs, pys, pzs);
        softmax_xyz<<<N_, 256>>>(pS, psb2, pss2, pxs, pys, pzs, xyz_buf[l & 1]);
        attnv_mma<<<dim3(HID_/128, N_/128, KZ_), 256>>>(psb2, pss2, pvtb2, pvts2, ppart);
        combine_parts<<<(N_*HID_/4)/256, 256>>>(ppart, phmsb, phmss);
        gemm_tc64<<<dim3(HID_/64, N_/64), 256>>>(phmsb, phmss, poWtb + (size_t)l*HID_*HID_,
                                                 poWts + (size_t)l*HID_*HID_, HID_, HID_,
                                                 ob + l*HID_, 0, 1.0f,
                                                 px, 1.0f, nullptr,0.f, nullptr,0.f,
                                                 px, nullptr, pxb, pxs2);
        xyz_cur = xyz_buf[l & 1];
    }

    cls_k<<<N_/256, 256>>>(px, clsW, clsb, (float*)d_out);
}

// round 11
// speedup vs baseline: 1.5401x; 1.0002x over previous
#include <cuda_runtime.h>
#include <cuda_bf16.h>
#include <math.h>
#include <stdint.h>

#define N_    4096
#define E_    131072
#define FEAT_ 64
#define HID_  256
#define NEG_  (-1e9f)
#define KZ_   4

typedef __nv_bfloat16 bf16;

// ---------------- scratch ----------------
__device__ float g_h0 [N_*HID_];
__device__ float g_x  [N_*HID_];
__device__ float g_hl [N_*HID_];
__device__ float g_xg [N_*HID_];
__device__ float g_part[(size_t)KZ_*N_*HID_];
__device__ float g_S  [(size_t)N_*N_];
__device__ bf16 g_xb[N_*HID_], g_xs[N_*HID_];
__device__ bf16 g_featb[N_*FEAT_], g_feats[N_*FEAT_];
__device__ bf16 g_supb[N_*2*HID_], g_sups[N_*2*HID_];
__device__ bf16 g_hmsb[N_*HID_], g_hmss[N_*HID_];
__device__ bf16 g_qb2[N_*HID_], g_qs2[N_*HID_];
__device__ bf16 g_kb2[N_*HID_], g_ks2[N_*HID_];
__device__ bf16 g_vtb2[HID_*N_], g_vts2[HID_*N_];
__device__ bf16 g_sb2[(size_t)N_*N_], g_ss2[(size_t)N_*N_];
__device__ bf16 g_fcWtb[HID_*FEAT_], g_fcWts[HID_*FEAT_];
__device__ bf16 g_gatWtb[4*HID_*HID_], g_gatWts[4*HID_*HID_];
__device__ bf16 g_gcWtb[4*HID_*2*HID_], g_gcWts[4*HID_*2*HID_];
__device__ bf16 g_qkvWtb[4*768*HID_], g_qkvWts[4*768*HID_];
__device__ float g_qkvb[4*768];
__device__ bf16 g_oWtb[4*HID_*HID_], g_oWts[4*HID_*HID_];
__device__ float g_el [N_*4];
__device__ float g_er [N_*4];
__device__ float g_y  [N_];
__device__ float g_xyz0[N_*3];
__device__ float g_xyz1[N_*3];
__device__ float g_xs_[N_], g_ys_[N_], g_zs_[N_];
__device__ int   g_cnt[N_];
__device__ int   g_rowptr[N_+1];
__device__ int   g_cur[N_];
__device__ int   g_psrc[E_];
__device__ int   g_maskmode;

// ---------------- helpers ----------------
__device__ __forceinline__ uint32_t smem_u32(const void* p) {
    uint32_t a;
    asm("{ .reg .u64 t; cvta.to.shared.u64 t, %1; cvt.u32.u64 %0, t; }" : "=r"(a) : "l"(p));
    return a;
}
#define LDMX4(r, a) \
    asm volatile("ldmatrix.sync.aligned.m8n8.x4.shared.b16 {%0,%1,%2,%3}, [%4];" \
        : "=r"((r)[0]), "=r"((r)[1]), "=r"((r)[2]), "=r"((r)[3]) : "r"(a))
#define MMA16816(c, a, b0, b1) \
    asm volatile("mma.sync.aligned.m16n8k16.row.col.f32.bf16.bf16.f32 " \
        "{%0,%1,%2,%3}, {%4,%5,%6,%7}, {%8,%9}, {%0,%1,%2,%3};" \
        : "+f"((c)[0]), "+f"((c)[1]), "+f"((c)[2]), "+f"((c)[3]) \
        : "r"((a)[0]), "r"((a)[1]), "r"((a)[2]), "r"((a)[3]), "r"(b0), "r"(b1))

__device__ __forceinline__ void split1(float v, bf16& b, bf16& s) {
    b = __float2bfloat16(v);
    s = __float2bfloat16(v - __bfloat162float(b));
}

// branch-free exp on the FMA/ALU pipes (no MUFU). Valid for x <= 0 (incl. -1e9).
// rel err ~1.2e-7 (degree-6 Taylor of 2^f on [-0.5, 0.5]).
__device__ __forceinline__ float fast_exp(float x) {
    float t = x * 1.4426950408889634f;
    t = fmaxf(t, -126.0f);
    float z = t + 12582912.0f;                 // round-to-nearest integer
    float n = z - 12582912.0f;
    float f = t - n;
    float p = 1.5404e-4f;
    p = fmaf(p, f, 1.33336e-3f);
    p = fmaf(p, f, 9.61813e-3f);
    p = fmaf(p, f, 5.550411e-2f);
    p = fmaf(p, f, 2.4022651e-1f);
    p = fmaf(p, f, 6.9314718e-1f);
    p = fmaf(p, f, 1.0f);
    int ni = __float_as_int(z) - 0x4B400000;   // integer n
    float sc = __int_as_float((ni + 127) << 23);
    return p * sc;
}

__global__ void detect_mask_mode(const unsigned int* __restrict__ m) {
    bool allbin = true, anyfloat = false;
    for (int i = 0; i < 1024; i++) {
        unsigned int w = m[i];
        if (w == 0x3f800000u) anyfloat = true;
        if (w > 1u) allbin = false;
    }
    g_maskmode = anyfloat ? 2 : (allbin ? 1 : 0);
}
__device__ __forceinline__ bool mask_at(const void* p, size_t i, int mode) {
    if (mode == 0) return ((const unsigned char*)p)[i] != 0;
    if (mode == 1) return ((const int*)p)[i] != 0;
    return ((const float*)p)[i] != 0.0f;
}

__global__ void split_bf16(const float* __restrict__ X, bf16* __restrict__ Xb, bf16* __restrict__ Xs)
{
    int i = blockIdx.x * blockDim.x + threadIdx.x;
    float4 x = *(const float4*)&X[(size_t)i*4];
    float xv[4] = {x.x, x.y, x.z, x.w};
    __align__(8) bf16 b[4], s[4];
#pragma unroll
    for (int e = 0; e < 4; e++) split1(xv[e], b[e], s[e]);
    *(uint2*)&Xb[(size_t)i*4] = *(uint2*)b;
    *(uint2*)&Xs[(size_t)i*4] = *(uint2*)s;
}

__global__ void wsplit(const float* __restrict__ W, bf16* __restrict__ Wtb,
                       bf16* __restrict__ Wts, int K, int N, int KN)
{
    int idx = blockIdx.x * 256 + threadIdx.x;
    int mat = idx / KN;
    int rem = idx - mat * KN;
    int k = rem / N;
    int n = rem - k * N;
    float v = W[idx];
    bf16 b, s; split1(v, b, s);
    int o = mat * KN + n * K + k;
    Wtb[o] = b; Wts[o] = s;
}

__global__ void wsplit_ro(const float* __restrict__ W, bf16* __restrict__ Wtb,
                          bf16* __restrict__ Wts, int ro)
{
    int idx = blockIdx.x * 256 + threadIdx.x;
    int l = idx >> 16;
    int rem = idx & 65535;
    int k = rem >> 8, n = rem & 255;
    float v = W[idx];
    bf16 b, s; split1(v, b, s);
    size_t o = (size_t)l * 768 * HID_ + (size_t)(ro + n) * HID_ + k;
    Wtb[o] = b; Wts[o] = s;
}

__global__ void qkvbias(const float* __restrict__ qb, const float* __restrict__ kb,
                        const float* __restrict__ vb, float* __restrict__ out)
{
    int idx = blockIdx.x * 256 + threadIdx.x;
    if (idx >= 4*768) return;
    int l = idx / 768, c = idx % 768;
    int sect = c >> 8, cc = c & 255;
    out[idx] = (sect == 0) ? qb[l*256+cc] : (sect == 1) ? kb[l*256+cc] : vb[l*256+cc];
}

// ================= gemm_tc64: 64x64 tile bf16-mma, 3-pass split =================
__global__ __launch_bounds__(256) void gemm_tc64(
    const bf16* __restrict__ Ab, const bf16* __restrict__ Asm,
    const bf16* __restrict__ Bb, const bf16* __restrict__ Bsm,
    int K, int Nc,
    const float* __restrict__ bias, int relu, float cacc,
    const float* __restrict__ X1, float c1,
    const float* __restrict__ X2, float c2,
    const float* __restrict__ X3, float c3,
    float* __restrict__ C, float* __restrict__ C2,
    bf16* __restrict__ Cb, bf16* __restrict__ Cs)
{
    __shared__ __align__(16) char Ash[2][64*80];
    __shared__ __align__(16) char Bsh[2][64*80];
    const int t = threadIdx.x, lane = t & 31, wid = t >> 5;
    const int wr32 = (wid >> 2) * 32, wc16 = (wid & 3) * 16;
    const int g = lane >> 2, tg = lane & 3;
    const int a_r = ((lane >> 3) & 1) * 8 + (lane & 7);
    const int a_c = (lane >> 4) * 16;
    const int b_r = ((lane >> 4) & 1) * 8 + (lane & 7);
    const int b_c = ((lane >> 3) & 1) * 16;
    const int m0 = blockIdx.y * 64, n0 = blockIdx.x * 64;
    const int lrow = t >> 2, lq = t & 3;

    uint32_t aS[2] = { smem_u32(Ash[0]), smem_u32(Ash[1]) };
    uint32_t bS[2] = { smem_u32(Bsh[0]), smem_u32(Bsh[1]) };
    float acc[2][2][4] = {};

    const bf16* APs[3] = { Ab, Ab, Asm };
    const bf16* BPs[3] = { Bb, Bsm, Bb };
    const int chunks = K >> 5;
    const int NC = 3 * chunks;

    uint4 va = *(const uint4*)(APs[0] + (size_t)(m0+lrow)*K + lq*8);
    uint4 vb = *(const uint4*)(BPs[0] + (size_t)(n0+lrow)*K + lq*8);
    *(uint4*)(Ash[0] + lrow*80 + lq*16) = va;
    *(uint4*)(Bsh[0] + lrow*80 + lq*16) = vb;
    __syncthreads();

    int pn = 0, kn = 0;
    for (int c = 0; c < NC; c++) {
        const int buf = c & 1;
        const bool more = (c + 1 < NC);
        if (more) {
            kn++; if (kn == chunks) { kn = 0; pn++; }
            va = *(const uint4*)(APs[pn] + (size_t)(m0+lrow)*K + kn*32 + lq*8);
            vb = *(const uint4*)(BPs[pn] + (size_t)(n0+lrow)*K + kn*32 + lq*8);
        }
#pragma unroll
        for (int kk = 0; kk < 2; kk++) {
            uint32_t af[2][4], bfr[4];
#pragma unroll
            for (int mt = 0; mt < 2; mt++) {
                uint32_t ad = aS[buf] + (uint32_t)((wr32 + mt*16 + a_r)*80 + kk*32 + a_c);
                LDMX4(af[mt], ad);
            }
            {
                uint32_t bd = bS[buf] + (uint32_t)((wc16 + b_r)*80 + kk*32 + b_c);
                LDMX4(bfr, bd);
            }
#pragma unroll
            for (int mt = 0; mt < 2; mt++)
#pragma unroll
                for (int nt = 0; nt < 2; nt++)
                    MMA16816(acc[mt][nt], af[mt], bfr[nt*2], bfr[nt*2+1]);
        }
        if (more) {
            const int nb = buf ^ 1;
            *(uint4*)(Ash[nb] + lrow*80 + lq*16) = va;
            *(uint4*)(Bsh[nb] + lrow*80 + lq*16) = vb;
            __syncthreads();
        }
    }

#pragma unroll
    for (int mt = 0; mt < 2; mt++) {
#pragma unroll
        for (int h = 0; h < 2; h++) {
            const int m = m0 + wr32 + mt*16 + g + 8*h;
            const size_t rb = (size_t)m * Nc;
#pragma unroll
            for (int nt = 0; nt < 2; nt++) {
                const int n = n0 + wc16 + nt*8 + 2*tg;
                float2 r = { acc[mt][nt][h*2], acc[mt][nt][h*2+1] };
                r.x *= cacc; r.y *= cacc;
                if (bias) { r.x += bias[n]; r.y += bias[n+1]; }
                if (X1) { float2 q = *(const float2*)&X1[rb+n];
                          r.x = fmaf(c1,q.x,r.x); r.y = fmaf(c1,q.y,r.y); }
                if (X2) { float2 q = *(const float2*)&X2[rb+n];
                          r.x = fmaf(c2,q.x,r.x); r.y = fmaf(c2,q.y,r.y); }
                if (X3) { float2 q = *(const float2*)&X3[rb+n];
                          r.x = fmaf(c3,q.x,r.x); r.y = fmaf(c3,q.y,r.y); }
                if (relu) { r.x = fmaxf(r.x, 0.f); r.y = fmaxf(r.y, 0.f); }
                if (C)  *(float2*)&C[rb+n]  = r;
                if (C2) *(float2*)&C2[rb+n] = r;
                if (Cb) {
                    __align__(4) bf16 b2[2], s2[2];
                    split1(r.x, b2[0], s2[0]); split1(r.y, b2[1], s2[1]);
                    *(uint32_t*)&Cb[rb+n] = *(uint32_t*)b2;
                    *(uint32_t*)&Cs[rb+n] = *(uint32_t*)s2;
                }
            }
        }
    }
}

// ================= qkv_tc: fused QKV GEMM, tile 128x64, Nc=768 routed =================
__global__ __launch_bounds__(256) void qkv_tc(
    const bf16* __restrict__ Ab, const bf16* __restrict__ Asm,
    const bf16* __restrict__ Bb, const bf16* __restrict__ Bsm,
    const float* __restrict__ bias,
    bf16* __restrict__ Qb, bf16* __restrict__ Qs,
    bf16* __restrict__ Kb, bf16* __restrict__ Ks,
    bf16* __restrict__ Vtb, bf16* __restrict__ Vts)
{
    __shared__ __align__(16) char Ash[2][128*80];
    __shared__ __align__(16) char Bsh[2][64*80];
    const int t = threadIdx.x, lane = t & 31, wid = t >> 5;
    const int wr32 = (wid >> 1) * 32, wc32 = (wid & 1) * 32;
    const int g = lane >> 2, tg = lane & 3;
    const int a_r = ((lane >> 3) & 1) * 8 + (lane & 7);
    const int a_c = (lane >> 4) * 16;
    const int b_r = ((lane >> 4) & 1) * 8 + (lane & 7);
    const int b_c = ((lane >> 3) & 1) * 16;
    const int m0 = blockIdx.y * 128, n0 = blockIdx.x * 64;
    const int K = HID_;

    uint32_t aS[2] = { smem_u32(Ash[0]), smem_u32(Ash[1]) };
    uint32_t bS[2] = { smem_u32(Bsh[0]), smem_u32(Bsh[1]) };
    float acc[2][4][4] = {};

    const bf16* APs[3] = { Ab, Ab, Asm };
    const bf16* BPs[3] = { Bb, Bsm, Bb };
    const int chunks = K >> 5;
    const int NC = 3 * chunks;

    uint4 va[2], vb;
#pragma unroll
    for (int i = 0; i < 2; i++) {
        int idx = t + i*256, row = idx >> 2, q = idx & 3;
        va[i] = *(const uint4*)(APs[0] + (size_t)(m0+row)*K + q*8);
    }
    { int row = t >> 2, q = t & 3;
      vb = *(const uint4*)(BPs[0] + (size_t)(n0+row)*K + q*8); }
#pragma unroll
    for (int i = 0; i < 2; i++) {
        int idx = t + i*256, row = idx >> 2, q = idx & 3;
        *(uint4*)(Ash[0] + row*80 + q*16) = va[i];
    }
    { int row = t >> 2, q = t & 3;
      *(uint4*)(Bsh[0] + row*80 + q*16) = vb; }
    __syncthreads();

    int pn = 0, kn = 0;
    for (int c = 0; c < NC; c++) {
        const int buf = c & 1;
        const bool more = (c + 1 < NC);
        if (more) {
            kn++; if (kn == chunks) { kn = 0; pn++; }
#pragma unroll
            for (int i = 0; i < 2; i++) {
                int idx = t + i*256, row = idx >> 2, q = idx & 3;
                va[i] = *(const uint4*)(APs[pn] + (size_t)(m0+row)*K + kn*32 + q*8);
            }
            { int row = t >> 2, q = t & 3;
              vb = *(const uint4*)(BPs[pn] + (size_t)(n0+row)*K + kn*32 + q*8); }
        }
#pragma unroll
        for (int kk = 0; kk < 2; kk++) {
            uint32_t af[2][4], bfr[2][4];
#pragma unroll
            for (int mt = 0; mt < 2; mt++) {
                uint32_t ad = aS[buf] + (uint32_t)((wr32 + mt*16 + a_r)*80 + kk*32 + a_c);
                LDMX4(af[mt], ad);
            }
#pragma unroll
            for (int np = 0; np < 2; np++) {
                uint32_t bd = bS[buf] + (uint32_t)((wc32 + np*16 + b_r)*80 + kk*32 + b_c);
                LDMX4(bfr[np], bd);
            }
#pragma unroll
            for (int mt = 0; mt < 2; mt++)
#pragma unroll
                for (int nt = 0; nt < 4; nt++)
                    MMA16816(acc[mt][nt], af[mt], bfr[nt>>1][(nt&1)*2], bfr[nt>>1][(nt&1)*2+1]);
        }
        if (more) {
            const int nb = buf ^ 1;
#pragma unroll
            for (int i = 0; i < 2; i++) {
                int idx = t + i*256, row = idx >> 2, q = idx & 3;
                *(uint4*)(Ash[nb] + row*80 + q*16) = va[i];
            }
            { int row = t >> 2, q = t & 3;
              *(uint4*)(Bsh[nb] + row*80 + q*16) = vb; }
            __syncthreads();
        }
    }

#pragma unroll
    for (int mt = 0; mt < 2; mt++) {
#pragma unroll
        for (int h = 0; h < 2; h++) {
            const int m = m0 + wr32 + mt*16 + g + 8*h;
#pragma unroll
            for (int nt = 0; nt < 4; nt++) {
                const int n = n0 + wc32 + nt*8 + 2*tg;
                float2 r = { acc[mt][nt][h*2], acc[mt][nt][h*2+1] };
                r.x += bias[n]; r.y += bias[n+1];
                bf16 b0, s0, b1, s1;
                split1(r.x, b0, s0); split1(r.y, b1, s1);
                const int sect = n >> 8, cc = n & 255;
                if (sect == 0) {
                    __align__(4) bf16 bb[2] = {b0, b1}, ss[2] = {s0, s1};
                    *(uint32_t*)&Qb[(size_t)m*HID_ + cc] = *(uint32_t*)bb;
                    *(uint32_t*)&Qs[(size_t)m*HID_ + cc] = *(uint32_t*)ss;
                } else if (sect == 1) {
                    __align__(4) bf16 bb[2] = {b0, b1}, ss[2] = {s0, s1};
                    *(uint32_t*)&Kb[(size_t)m*HID_ + cc] = *(uint32_t*)bb;
                    *(uint32_t*)&Ks[(size_t)m*HID_ + cc] = *(uint32_t*)ss;
                } else {
                    Vtb[(size_t)cc * N_ + m] = b0;     Vts[(size_t)cc * N_ + m] = s0;
                    Vtb[(size_t)(cc+1) * N_ + m] = b1; Vts[(size_t)(cc+1) * N_ + m] = s1;
                }
            }
        }
    }
}

// ---- shared mma-core macro (128x128 kernels) ----
#define COMPUTE32(abase, bbase)                                                     \
    _Pragma("unroll")                                                               \
    for (int kk = 0; kk < 2; kk++) {                                                \
        uint32_t af[4][4], bfr[2][4];                                               \
        _Pragma("unroll")                                                           \
        for (int mt = 0; mt < 4; mt++) {                                            \
            uint32_t ad = (abase) + (uint32_t)((wr64 + mt*16 + a_r)*80 + kk*32 + a_c); \
            LDMX4(af[mt], ad);                                                      \
        }                                                                           \
        _Pragma("unroll")                                                           \
        for (int np = 0; np < 2; np++) {                                            \
            uint32_t bd = (bbase) + (uint32_t)((wc32 + np*16 + b_r)*80 + kk*32 + b_c); \
            LDMX4(bfr[np], bd);                                                     \
        }                                                                           \
        _Pragma("unroll")                                                           \
        for (int mt = 0; mt < 4; mt++)                                              \
            _Pragma("unroll")                                                       \
            for (int nt = 0; nt < 4; nt++)                                          \
                MMA16816(acc[mt][nt], af[mt], bfr[nt>>1][(nt&1)*2], bfr[nt>>1][(nt&1)*2+1]); \
    }

// ================= scores via bf16 mma =================
__global__ __launch_bounds__(256) void scores_mma(
    const bf16* __restrict__ qb, const bf16* __restrict__ qs,
    const bf16* __restrict__ kb, const bf16* __restrict__ ks,
    const float* __restrict__ xyz,
    const void* __restrict__ dmask, const void* __restrict__ bmask,
    float* __restrict__ S)
{
    __shared__ __align__(16) char Ash[2][128*80];
    __shared__ __align__(16) char Bsh[2][128*80];
    __shared__ float gix[128*3], gisq[128], giy[128];
    __shared__ float gjx[128*3], gjsq[128], gjy[128];
    const int t = threadIdx.x, lane = t & 31, wid = t >> 5;
    const int wr64 = (wid >> 2) * 64, wc32 = (wid & 3) * 32;
    const int g = lane >> 2, tg = lane & 3;
    const int a_r = ((lane >> 3) & 1) * 8 + (lane & 7);
    const int a_c = (lane >> 4) * 16;
    const int b_r = ((lane >> 4) & 1) * 8 + (lane & 7);
    const int b_c = ((lane >> 3) & 1) * 16;
    const int i0 = blockIdx.y * 128, j0 = blockIdx.x * 128;
    const int lrow = t >> 2, lq = t & 3;

    if (t < 128) {
        float a = xyz[(i0+t)*3+0], b = xyz[(i0+t)*3+1], c = xyz[(i0+t)*3+2];
        gix[t*3+0]=a; gix[t*3+1]=b; gix[t*3+2]=c;
        gisq[t] = fmaf(c,c,fmaf(b,b,a*a));
        giy[t]  = g_y[i0+t];
    } else {
        int u = t - 128;
        float a = xyz[(j0+u)*3+0], b = xyz[(j0+u)*3+1], c = xyz[(j0+u)*3+2];
        gjx[u*3+0]=a; gjx[u*3+1]=b; gjx[u*3+2]=c;
        gjsq[u] = fmaf(c,c,fmaf(b,b,a*a));
        gjy[u]  = g_y[j0+u];
    }

    uint32_t aS[2] = { smem_u32(Ash[0]), smem_u32(Ash[1]) };
    uint32_t bS[2] = { smem_u32(Bsh[0]), smem_u32(Bsh[1]) };
    float acc[4][4][4] = {};

    const bf16* APs[3] = { qb, qb, qs };
    const bf16* BPs[3] = { kb, ks, kb };

    uint4 va[2], vb[2];
#pragma unroll
    for (int r = 0; r < 2; r++) {
        int row = lrow + r*64;
        va[r] = *(const uint4*)(APs[0] + (size_t)(i0+row)*HID_ + lq*8);
        vb[r] = *(const uint4*)(BPs[0] + (size_t)(j0+row)*HID_ + lq*8);
    }
#pragma unroll
    for (int r = 0; r < 2; r++) {
        int row = lrow + r*64;
        *(uint4*)(Ash[0] + row*80 + lq*16) = va[r];
        *(uint4*)(Bsh[0] + row*80 + lq*16) = vb[r];
    }
    __syncthreads();

    const int NC = 24;
    for (int c = 0; c < NC; c++) {
        const int buf = c & 1;
        if (c + 1 < NC) {
            const int p = (c+1) >> 3, kc = (c+1) & 7;
            const bf16* A = APs[p];
            const bf16* B = BPs[p];
#pragma unroll
            for (int r = 0; r < 2; r++) {
                int row = lrow + r*64;
                va[r] = *(const uint4*)(A + (size_t)(i0+row)*HID_ + kc*32 + lq*8);
                vb[r] = *(const uint4*)(B + (size_t)(j0+row)*HID_ + kc*32 + lq*8);
            }
        }
        COMPUTE32(aS[buf], bS[buf]);
        if (c + 1 < NC) {
            const int nb = buf ^ 1;
#pragma unroll
            for (int r = 0; r < 2; r++) {
                int row = lrow + r*64;
                *(uint4*)(Ash[nb] + row*80 + lq*16) = va[r];
                *(uint4*)(Bsh[nb] + row*80 + lq*16) = vb[r];
            }
            __syncthreads();
        }
    }

    const int mode = g_maskmode;
#pragma unroll
    for (int mt = 0; mt < 4; mt++) {
#pragma unroll
        for (int h = 0; h < 2; h++) {
            const int li = wr64 + mt*16 + g + 8*h;
            const int gi = i0 + li;
            const float xa = gix[li*3], xbv = gix[li*3+1], xc = gix[li*3+2];
            const float sqa = gisq[li], ya = giy[li];
            const size_t rb = (size_t)gi * N_;
#pragma unroll
            for (int nt = 0; nt < 4; nt++) {
                const int lj0 = wc32 + nt*8 + 2*tg;
                float2 r;
#pragma unroll
                for (int e = 0; e < 2; e++) {
                    const int lj = lj0 + e;
                    const size_t gidx = rb + j0 + lj;
                    float dot = fmaf(xc, gjx[lj*3+2], fmaf(xbv, gjx[lj*3+1], xa * gjx[lj*3]));
                    float dist2 = (sqa + gjsq[lj]) - 2.0f * dot;
                    bool ok = mask_at(dmask, gidx, mode) && mask_at(bmask, gidx, mode) && (dist2 <= 100.0f);
                    float av = acc[mt][nt][h*2 + e];
                    ((float*)&r)[e] = ok ? (av * 0.0625f - fabsf(ya - gjy[lj])) : NEG_;
                }
                *(float2*)&S[rb + j0 + lj0] = r;
            }
        }
    }
}

// ================= attn@V via bf16 mma, split-K z =================
__global__ __launch_bounds__(256) void attnv_mma(
    const bf16* __restrict__ Sb, const bf16* __restrict__ Ss,
    const bf16* __restrict__ Vtb, const bf16* __restrict__ Vts,
    float* __restrict__ Cpart)
{
    __shared__ __align__(16) char Ash[2][128*80];
    __shared__ __align__(16) char Bsh[2][128*80];
    const int t = threadIdx.x, lane = t & 31, wid = t >> 5;
    const int wr64 = (wid >> 2) * 64, wc32 = (wid & 3) * 32;
    const int g = lane >> 2, tg = lane & 3;
    const int a_r = ((lane >> 3) & 1) * 8 + (lane & 7);
    const int a_c = (lane >> 4) * 16;
    const int b_r = ((lane >> 4) & 1) * 8 + (lane & 7);
    const int b_c = ((lane >> 3) & 1) * 16;
    const int m0 = blockIdx.y * 128, n0 = blockIdx.x * 128;
    const int kbase = blockIdx.z * (N_ / KZ_);
    const int lrow = t >> 2, lq = t & 3;

    uint32_t aS[2] = { smem_u32(Ash[0]), smem_u32(Ash[1]) };
    uint32_t bS[2] = { smem_u32(Bsh[0]), smem_u32(Bsh[1]) };
    float acc[4][4][4] = {};

    const bf16* APs[3] = { Sb, Sb, Ss };
    const bf16* BPs[3] = { Vtb, Vts, Vtb };
    const int CPP = (N_ / KZ_) / 32;
    const int NC = 3 * CPP;

    uint4 va[2], vb[2];
#pragma unroll
    for (int r = 0; r < 2; r++) {
        int row = lrow + r*64;
        va[r] = *(const uint4*)(APs[0] + (size_t)(m0+row)*N_ + kbase + lq*8);
        vb[r] = *(const uint4*)(BPs[0] + (size_t)(n0+row)*N_ + kbase + lq*8);
    }
#pragma unroll
    for (int r = 0; r < 2; r++) {
        int row = lrow + r*64;
        *(uint4*)(Ash[0] + row*80 + lq*16) = va[r];
        *(uint4*)(Bsh[0] + row*80 + lq*16) = vb[r];
    }
    __syncthreads();

    for (int c = 0; c < NC; c++) {
        const int buf = c & 1;
        if (c + 1 < NC) {
            const int p = (c+1) / CPP, kc = (c+1) % CPP;
            const bf16* A = APs[p];
            const bf16* B = BPs[p];
#pragma unroll
            for (int r = 0; r < 2; r++) {
                int row = lrow + r*64;
                va[r] = *(const uint4*)(A + (size_t)(m0+row)*N_ + kbase + kc*32 + lq*8);
                vb[r] = *(const uint4*)(B + (size_t)(n0+row)*N_ + kbase + kc*32 + lq*8);
            }
        }
        COMPUTE32(aS[buf], bS[buf]);
        if (c + 1 < NC) {
            const int nb = buf ^ 1;
#pragma unroll
            for (int r = 0; r < 2; r++) {
                int row = lrow + r*64;
                *(uint4*)(Ash[nb] + row*80 + lq*16) = va[r];
                *(uint4*)(Bsh[nb] + row*80 + lq*16) = vb[r];
            }
            __syncthreads();
        }
    }

    float* Cz = Cpart + (size_t)blockIdx.z * N_ * HID_;
#pragma unroll
    for (int mt = 0; mt < 4; mt++) {
#pragma unroll
        for (int h = 0; h < 2; h++) {
            const int m = m0 + wr64 + mt*16 + g + 8*h;
            const size_t rb = (size_t)m * HID_;
#pragma unroll
            for (int nt = 0; nt < 4; nt++) {
                const int n = n0 + wc32 + nt*8 + 2*tg;
                float2 r = { acc[mt][nt][h*2], acc[mt][nt][h*2 + 1] };
                *(float2*)&Cz[rb + n] = r;
            }
        }
    }
}

__global__ void combine_parts(const float* __restrict__ P,
                              bf16* __restrict__ Hb, bf16* __restrict__ Hs)
{
    int i = blockIdx.x * blockDim.x + threadIdx.x;
    const size_t n = (size_t)N_ * HID_;
    float4 a = *(const float4*)&P[(size_t)i*4];
    float4 b = *(const float4*)&P[n + (size_t)i*4];
    float4 c = *(const float4*)&P[2*n + (size_t)i*4];
    float4 d = *(const float4*)&P[3*n + (size_t)i*4];
    float rv[4] = { a.x+b.x+c.x+d.x, a.y+b.y+c.y+d.y, a.z+b.z+c.z+d.z, a.w+b.w+c.w+d.w };
    __align__(8) bf16 hb[4], hs[4];
#pragma unroll
    for (int e = 0; e < 4; e++) split1(rv[e], hb[e], hs[e]);
    *(uint2*)&Hb[(size_t)i*4] = *(uint2*)hb;
    *(uint2*)&Hs[(size_t)i*4] = *(uint2*)hs;
}

// ---------------- softmax + attn@xyz + bf16 split (fast_exp) ----------------
__global__ void softmax_xyz(const float* __restrict__ S,
                            bf16* __restrict__ Sb, bf16* __restrict__ Ss,
                            const float* __restrict__ xs, const float* __restrict__ ys,
                            const float* __restrict__ zs, float* __restrict__ out)
{
    __shared__ float r0[256], r1[256], r2[256];
    const int row = blockIdx.x, t = threadIdx.x;
    const float* p = S + (size_t)row * N_;
    float4 v[4];
    float mx = -1e30f;
#pragma unroll
    for (int c = 0; c < 4; c++) {
        v[c] = *(const float4*)&p[c*1024 + t*4];
        mx = fmaxf(mx, fmaxf(fmaxf(v[c].x, v[c].y), fmaxf(v[c].z, v[c].w)));
    }
    r0[t] = mx; __syncthreads();
    for (int s = 128; s > 0; s >>= 1) { if (t < s) r0[t] = fmaxf(r0[t], r0[t+s]); __syncthreads(); }
    mx = r0[0]; __syncthreads();
    float sum = 0.0f;
#pragma unroll
    for (int c = 0; c < 4; c++) {
        v[c].x = fast_exp(v[c].x - mx); v[c].y = fast_exp(v[c].y - mx);
        v[c].z = fast_exp(v[c].z - mx); v[c].w = fast_exp(v[c].w - mx);
        sum += v[c].x + v[c].y + v[c].z + v[c].w;
    }
    r0[t] = sum; __syncthreads();
    for (int s = 128; s > 0; s >>= 1) { if (t < s) r0[t] += r0[t+s]; __syncthreads(); }
    const float inv = 1.0f / r0[0];
    __syncthreads();
    float a0 = 0.f, a1 = 0.f, a2 = 0.f;
#pragma unroll
    for (int c = 0; c < 4; c++) {
        v[c].x *= inv; v[c].y *= inv; v[c].z *= inv; v[c].w *= inv;
        float vv[4] = { v[c].x, v[c].y, v[c].z, v[c].w };
        __align__(8) bf16 vb[4], vsm[4];
#pragma unroll
        for (int e = 0; e < 4; e++) split1(vv[e], vb[e], vsm[e]);
        const size_t off = (size_t)row * N_ + c*1024 + t*4;
        *(uint2*)&Sb[off] = *(uint2*)vb;
        *(uint2*)&Ss[off] = *(uint2*)vsm;
        const int j = c*1024 + t*4;
        a0 = fmaf(v[c].x, xs[j], fmaf(v[c].y, xs[j+1], fmaf(v[c].z, xs[j+2], fmaf(v[c].w, xs[j+3], a0))));
        a1 = fmaf(v[c].x, ys[j], fmaf(v[c].y, ys[j+1], fmaf(v[c].z, ys[j+2], fmaf(v[c].w, ys[j+3], a1))));
        a2 = fmaf(v[c].x, zs[j], fmaf(v[c].y, zs[j+1], fmaf(v[c].z, zs[j+2], fmaf(v[c].w, zs[j+3], a2))));
    }
    r0[t]=a0; r1[t]=a1; r2[t]=a2; __syncthreads();
    for (int s = 128; s > 0; s >>= 1) {
        if (t < s) { r0[t]+=r0[t+s]; r1[t]+=r1[t+s]; r2[t]+=r2[t+s]; }
        __syncthreads();
    }
    if (t == 0) { out[row*3+0]=r0[0]; out[row*3+1]=r1[0]; out[row*3+2]=r2[0]; }
}

__global__ void xyz2soa(const float* __restrict__ xyz, float* __restrict__ xs,
                        float* __restrict__ ys, float* __restrict__ zs)
{
    int i = blockIdx.x * blockDim.x + threadIdx.x;
    if (i < N_) { xs[i] = xyz[3*i]; ys[i] = xyz[3*i+1]; zs[i] = xyz[3*i+2]; }
}

// ---------------- GAT pieces ----------------
__global__ void compute_elr(const float* __restrict__ hl, const float* __restrict__ al,
                            const float* __restrict__ ar)
{
    int idx = blockIdx.x * blockDim.x + threadIdx.x;
    if (idx >= N_*4) return;
    int node = idx >> 2, h = idx & 3;
    const float* row = hl + (size_t)node * HID_ + h * 64;
    float sl = 0.f, sr = 0.f;
#pragma unroll 8
    for (int d = 0; d < 64; d++) {
        float v = row[d];
        sl = fmaf(v, al[h*64+d], sl);
        sr = fmaf(v, ar[h*64+d], sr);
    }
    g_el[idx] = sl; g_er[idx] = sr;
}

__global__ void zero_cnt() { int i = blockIdx.x*blockDim.x + threadIdx.x; if (i < N_) g_cnt[i] = 0; }
__global__ void count_edges(const int* __restrict__ dst) {
    int e = blockIdx.x*blockDim.x + threadIdx.x; if (e < E_) atomicAdd(&g_cnt[dst[e]], 1);
}
__global__ void scan4096() {
    __shared__ int part[1024];
    int t = threadIdx.x, base = t * 4;
    int a0 = g_cnt[base], a1 = g_cnt[base+1], a2 = g_cnt[base+2], a3 = g_cnt[base+3];
    int s = a0 + a1 + a2 + a3;
    part[t] = s; __syncthreads();
    for (int off = 1; off < 1024; off <<= 1) {
        int v = (t >= off) ? part[t-off] : 0;
        __syncthreads();
        part[t] += v;
        __syncthreads();
    }
    int excl = part[t] - s;
    g_rowptr[base+0] = excl;           g_cur[base+0] = excl;
    g_rowptr[base+1] = excl+a0;        g_cur[base+1] = excl+a0;
    g_rowptr[base+2] = excl+a0+a1;     g_cur[base+2] = excl+a0+a1;
    g_rowptr[base+3] = excl+a0+a1+a2;  g_cur[base+3] = excl+a0+a1+a2;
    if (t == 1023) g_rowptr[4096] = part[1023];
}
__global__ void scatter_edges(const int* __restrict__ src, const int* __restrict__ dst) {
    int e = blockIdx.x*blockDim.x + threadIdx.x;
    if (e < E_) { int p = atomicAdd(&g_cur[dst[e]], 1); g_psrc[p] = src[e]; }
}

__global__ void gat_aggregate(const float* __restrict__ hl, float* __restrict__ xg)
{
    const int node = (blockIdx.x * blockDim.x + threadIdx.x) >> 5;
    const int lane = threadIdx.x & 31;
    if (node >= N_) return;
    const int beg = g_rowptr[node], end = g_rowptr[node+1];
    const float er_i = (lane < 4) ? g_er[node*4 + lane] : 0.f;
    float m = -1e30f;
    for (int p = beg; p < end; p++) {
        int s = g_psrc[p];
        if (lane < 4) {
            float v = g_el[s*4 + lane] + er_i;
            float e = (v > 0.f) ? v : 0.2f * v;
            m = fmaxf(m, e);
        }
    }
    float m0 = __shfl_sync(0xffffffffu, m, 0), m1 = __shfl_sync(0xffffffffu, m, 1);
    float m2 = __shfl_sync(0xffffffffu, m, 2), m3 = __shfl_sync(0xffffffffu, m, 3);
    const int myh = lane >> 3;
    float4 acc0 = {0,0,0,0}, acc1 = {0,0,0,0};
    float z = 0.f;
    for (int p = beg; p < end; p++) {
        int s = g_psrc[p];
        float w = 0.f;
        if (lane < 4) {
            float v = g_el[s*4 + lane] + er_i;
            float e = (v > 0.f) ? v : 0.2f * v;
            float mm = (lane==0)?m0:(lane==1)?m1:(lane==2)?m2:m3;
            w = fast_exp(e - mm);
            z += w;
        }
        float w0 = __shfl_sync(0xffffffffu, w, 0), w1 = __shfl_sync(0xffffffffu, w, 1);
        float w2 = __shfl_sync(0xffffffffu, w, 2), w3 = __shfl_sync(0xffffffffu, w, 3);
        float wm = (myh==0)?w0:(myh==1)?w1:(myh==2)?w2:w3;
        const float4* hp = (const float4*)(hl + (size_t)s * HID_ + lane * 8);
        float4 hv0 = hp[0], hv1 = hp[1];
        acc0.x=fmaf(wm,hv0.x,acc0.x); acc0.y=fmaf(wm,hv0.y,acc0.y);
        acc0.z=fmaf(wm,hv0.z,acc0.z); acc0.w=fmaf(wm,hv0.w,acc0.w);
        acc1.x=fmaf(wm,hv1.x,acc1.x); acc1.y=fmaf(wm,hv1.y,acc1.y);
        acc1.z=fmaf(wm,hv1.z,acc1.z); acc1.w=fmaf(wm,hv1.w,acc1.w);
    }
    float z0 = __shfl_sync(0xffffffffu, z, 0), z1 = __shfl_sync(0xffffffffu, z, 1);
    float z2 = __shfl_sync(0xffffffffu, z, 2), z3 = __shfl_sync(0xffffffffu, z, 3);
    float zm = (myh==0)?z0:(myh==1)?z1:(myh==2)?z2:z3;
    float inv = 1.0f / (zm + 1e-9f);
    acc0.x*=inv; acc0.y*=inv; acc0.z*=inv; acc0.w*=inv;
    acc1.x*=inv; acc1.y*=inv; acc1.z*=inv; acc1.w*=inv;
    float4* op = (float4*)(xg + (size_t)node * HID_ + lane * 8);
    op[0] = acc0; op[1] = acc1;
}

__global__ void pack_support(const float* __restrict__ xg, const float* __restrict__ h0,
                             bf16* __restrict__ supb, bf16* __restrict__ sups)
{
    int i = blockIdx.x * blockDim.x + threadIdx.x;
    if (i >= N_ * 512) return;
    int r = i >> 9, c = i & 511;
    float v = (c < 256) ? xg[(size_t)r*256 + c] : h0[(size_t)r*256 + (c-256)];
    bf16 b, s; split1(v, b, s);
    supb[i] = b; sups[i] = s;
}

__global__ void yhat_k(const float* __restrict__ x, const float* __restrict__ W,
                       const float* __restrict__ b)
{
    int i = blockIdx.x * blockDim.x + threadIdx.x;
    if (i >= N_) return;
    const float* r = x + (size_t)i * HID_;
    float l0 = b[0], l1 = b[1];
#pragma unroll 8
    for (int d = 0; d < HID_; d++) {
        float v = r[d];
        l0 = fmaf(v, W[2*d+0], l0);
        l1 = fmaf(v, W[2*d+1], l1);
    }
    g_y[i] = 1.0f / (1.0f + expf(l0 - l1));
}

__global__ void cls_k(const float* __restrict__ x, const float* __restrict__ W,
                      const float* __restrict__ b, float* __restrict__ out)
{
    int i = blockIdx.x * blockDim.x + threadIdx.x;
    if (i >= N_) return;
    const float* r = x + (size_t)i * HID_;
    float l0 = b[0], l1 = b[1];
#pragma unroll 8
    for (int d = 0; d < HID_; d++) {
        float v = r[d];
        l0 = fmaf(v, W[2*d+0], l0);
        l1 = fmaf(v, W[2*d+1], l1);
    }
    out[2*i+0] = l0;
    out[2*i+1] = l1;
}

// ---------------- host orchestration ----------------
extern "C" void kernel_launch(void* const* d_in, const int* in_sizes, int n_in,
                              void* d_out, int out_size)
{
    const float* feat   = (const float*)d_in[0];
    const float* xyz_in = (const float*)d_in[1];
    const int*   src    = (const int*)  d_in[2];
    const int*   dst    = (const int*)  d_in[3];
    const void*  dmask  = d_in[4];
    const void*  bmask  = d_in[5];
    const float* fcW  = (const float*)d_in[6];
    const float* fcb  = (const float*)d_in[7];
    const float* gatW = (const float*)d_in[8];
    const float* al   = (const float*)d_in[9];
    const float* ar   = (const float*)d_in[10];
    const float* gcW  = (const float*)d_in[11];
    const float* cgW  = (const float*)d_in[12];
    const float* cgb  = (const float*)d_in[13];
    const float* qW   = (const float*)d_in[14];
    const float* qb_  = (const float*)d_in[15];
    const float* kW   = (const float*)d_in[16];
    const float* kb_  = (const float*)d_in[17];
    const float* vW   = (const float*)d_in[18];
    const float* vb_  = (const float*)d_in[19];
    const float* oW   = (const float*)d_in[20];
    const float* ob   = (const float*)d_in[21];
    const float* clsW = (const float*)d_in[22];
    const float* clsb = (const float*)d_in[23];

    float *px, *ph0, *phl, *pxg, *pS, *pxyz0, *pxyz1, *pxs, *pys, *pzs, *ppart, *pqkvb;
    bf16 *pxb, *pxs2, *pfeatb, *pfeats, *psupb, *psups, *phmsb, *phmss;
    bf16 *pqb2, *pqs2, *pkb2, *pks2, *pvtb2, *pvts2, *psb2, *pss2;
    bf16 *pfcWtb, *pfcWts, *pgatWtb, *pgatWts, *pgcWtb, *pgcWts;
    bf16 *pqkvWtb, *pqkvWts, *poWtb, *poWts;
    cudaGetSymbolAddress((void**)&px,    g_x);
    cudaGetSymbolAddress((void**)&ph0,   g_h0);
    cudaGetSymbolAddress((void**)&phl,   g_hl);
    cudaGetSymbolAddress((void**)&pxg,   g_xg);
    cudaGetSymbolAddress((void**)&pS,    g_S);
    cudaGetSymbolAddress((void**)&pxyz0, g_xyz0);
    cudaGetSymbolAddress((void**)&pxyz1, g_xyz1);
    cudaGetSymbolAddress((void**)&pxs,   g_xs_);
    cudaGetSymbolAddress((void**)&pys,   g_ys_);
    cudaGetSymbolAddress((void**)&pzs,   g_zs_);
    cudaGetSymbolAddress((void**)&ppart, g_part);
    cudaGetSymbolAddress((void**)&pqkvb, g_qkvb);
    cudaGetSymbolAddress((void**)&pxb,   g_xb);
    cudaGetSymbolAddress((void**)&pxs2,  g_xs);
    cudaGetSymbolAddress((void**)&pfeatb,g_featb);
    cudaGetSymbolAddress((void**)&pfeats,g_feats);
    cudaGetSymbolAddress((void**)&psupb, g_supb);
    cudaGetSymbolAddress((void**)&psups, g_sups);
    cudaGetSymbolAddress((void**)&phmsb, g_hmsb);
    cudaGetSymbolAddress((void**)&phmss, g_hmss);
    cudaGetSymbolAddress((void**)&pqb2,  g_qb2);
    cudaGetSymbolAddress((void**)&pqs2,  g_qs2);
    cudaGetSymbolAddress((void**)&pkb2,  g_kb2);
    cudaGetSymbolAddress((void**)&pks2,  g_ks2);
    cudaGetSymbolAddress((void**)&pvtb2, g_vtb2);
    cudaGetSymbolAddress((void**)&pvts2, g_vts2);
    cudaGetSymbolAddress((void**)&psb2,  g_sb2);
    cudaGetSymbolAddress((void**)&pss2,  g_ss2);
    cudaGetSymbolAddress((void**)&pfcWtb, g_fcWtb);
    cudaGetSymbolAddress((void**)&pfcWts, g_fcWts);
    cudaGetSymbolAddress((void**)&pgatWtb, g_gatWtb);
    cudaGetSymbolAddress((void**)&pgatWts, g_gatWts);
    cudaGetSymbolAddress((void**)&pgcWtb, g_gcWtb);
    cudaGetSymbolAddress((void**)&pgcWts, g_gcWts);
    cudaGetSymbolAddress((void**)&pqkvWtb, g_qkvWtb);
    cudaGetSymbolAddress((void**)&pqkvWts, g_qkvWts);
    cudaGetSymbolAddress((void**)&poWtb, g_oWtb);
    cudaGetSymbolAddress((void**)&poWts, g_oWts);

    detect_mask_mode<<<1, 1>>>((const unsigned int*)dmask);

    wsplit<<<(FEAT_*HID_)/256, 256>>>(fcW, pfcWtb, pfcWts, FEAT_, HID_, FEAT_*HID_);
    wsplit<<<(4*HID_*HID_)/256, 256>>>(gatW, pgatWtb, pgatWts, HID_, HID_, HID_*HID_);
    wsplit<<<(4*2*HID_*HID_)/256, 256>>>(gcW, pgcWtb, pgcWts, 2*HID_, HID_, 2*HID_*HID_);
    wsplit<<<(4*HID_*HID_)/256, 256>>>(oW, poWtb, poWts, HID_, HID_, HID_*HID_);
    wsplit_ro<<<(4*HID_*HID_)/256, 256>>>(qW, pqkvWtb, pqkvWts, 0);
    wsplit_ro<<<(4*HID_*HID_)/256, 256>>>(kW, pqkvWtb, pqkvWts, 256);
    wsplit_ro<<<(4*HID_*HID_)/256, 256>>>(vW, pqkvWtb, pqkvWts, 512);
    qkvbias<<<12, 256>>>(qb_, kb_, vb_, pqkvb);
    split_bf16<<<(N_*FEAT_/4)/256, 256>>>(feat, pfeatb, pfeats);

    gemm_tc64<<<dim3(HID_/64, N_/64), 256>>>(pfeatb, pfeats, pfcWtb, pfcWts, FEAT_, HID_,
                                             fcb, 1, 1.0f, nullptr,0.f, nullptr,0.f, nullptr,0.f,
                                             px, ph0, pxb, pxs2);

    zero_cnt<<<N_/256, 256>>>();
    count_edges<<<E_/256, 256>>>(dst);
    scan4096<<<1, 1024>>>();
    scatter_edges<<<E_/256, 256>>>(src, dst);

    const float ALPHA = 0.1f, LAMDA = 0.5f;
    for (int l = 0; l < 4; l++) {
        gemm_tc64<<<dim3(HID_/64, N_/64), 256>>>(pxb, pxs2, pgatWtb + (size_t)l*HID_*HID_,
                                                 pgatWts + (size_t)l*HID_*HID_, HID_, HID_,
                                                 nullptr, 0, 1.0f, nullptr,0.f, nullptr,0.f, nullptr,0.f,
                                                 phl, nullptr, nullptr, nullptr);
        compute_elr<<<(N_*4)/256, 256>>>(phl, al + l*4*64, ar + l*4*64);
        gat_aggregate<<<N_/8, 256>>>(phl, pxg);
        pack_support<<<(N_*512)/256, 256>>>(pxg, ph0, psupb, psups);
        float theta = fminf(1.0f, logf(LAMDA / (float)(l + 1) + 1.0f));
        gemm_tc64<<<dim3(HID_/64, N_/64), 256>>>(psupb, psups, pgcWtb + (size_t)l*2*HID_*HID_,
                                                 pgcWts + (size_t)l*2*HID_*HID_, 2*HID_, HID_,
                                                 nullptr, 0, theta,
                                                 pxg, (1.0f-theta)*(1.0f-ALPHA),
                                                 ph0, (1.0f-theta)*ALPHA,
                                                 px,  1.0f,
                                                 px, nullptr, pxb, pxs2);
    }

    yhat_k<<<N_/256, 256>>>(px, cgW, cgb);

    const float* xyz_cur = xyz_in;
    float* xyz_buf[2] = { pxyz0, pxyz1 };
    for (int l = 0; l < 4; l++) {
        qkv_tc<<<dim3(768/64, N_/128), 256>>>(pxb, pxs2,
                                              pqkvWtb + (size_t)l*768*HID_,
                                              pqkvWts + (size_t)l*768*HID_,
                                              pqkvb + l*768,
                                              pqb2, pqs2, pkb2, pks2, pvtb2, pvts2);
        scores_mma<<<dim3(N_/128, N_/128), 256>>>(pqb2, pqs2, pkb2, pks2,
                                                  xyz_cur, dmask, bmask, pS);
        xyz2soa<<<N_/256, 256>>>(xyz_cur, pxs, pys, pzs);
        softmax_xyz<<<N_, 256>>>(pS, psb2, pss2, pxs, pys, pzs, xyz_buf[l & 1]);
        attnv_mma<<<dim3(HID_/128, N_/128, KZ_), 256>>>(psb2, pss2, pvtb2, pvts2, ppart);
        combine_parts<<<(N_*HID_/4)/256, 256>>>(ppart, phmsb, phmss);
        gemm_tc64<<<dim3(HID_/64, N_/64), 256>>>(phmsb, phmss, poWtb + (size_t)l*HID_*HID_,
                                                 poWts + (size_t)l*HID_*HID_, HID_, HID_,
                                                 ob + l*HID_, 0, 1.0f,
                                                 px, 1.0f, nullptr,0.f, nullptr,0.f,
                                                 px, nullptr, pxb, pxs2);
        xyz_cur = xyz_buf[l & 1];
    }

    cls_k<<<N_/256, 256>>>(px, clsW, clsb, (float*)d_out);
}

// round 12
// speedup vs baseline: 1.8618x; 1.2088x over previous
#include <cuda_runtime.h>
#include <cuda_fp16.h>
#include <math.h>
#include <stdint.h>

#define N_    4096
#define E_    131072
#define FEAT_ 64
#define HID_  256
#define NEG_  (-1e9f)
#define KZ_   4

typedef __half hf;

// ---------------- scratch ----------------
__device__ float g_h0 [N_*HID_];
__device__ float g_x  [N_*HID_];
__device__ float g_hl_[N_*HID_];
__device__ float g_xg [N_*HID_];
__device__ float g_part[(size_t)KZ_*N_*HID_];
__device__ float g_S  [(size_t)N_*N_];
__device__ hf g_xh[N_*HID_], g_xl[N_*HID_];
__device__ hf g_feath[N_*FEAT_], g_featl[N_*FEAT_];
__device__ hf g_suph[N_*2*HID_], g_supl[N_*2*HID_];
__device__ hf g_hmsh[N_*HID_], g_hmsl[N_*HID_];
__device__ hf g_qh[N_*HID_], g_ql[N_*HID_];
__device__ hf g_kh[N_*HID_];
__device__ hf g_vth[HID_*N_];
__device__ hf g_sh[(size_t)N_*N_], g_sl[(size_t)N_*N_];
__device__ hf g_fcWth[HID_*FEAT_];
__device__ hf g_gatWth[4*HID_*HID_];
__device__ hf g_gcWth[4*HID_*2*HID_];
__device__ hf g_qkvWth[4*768*HID_];
__device__ float g_qkvb[4*768];
__device__ hf g_oWth[4*HID_*HID_];
__device__ float g_el [N_*4];
__device__ float g_er [N_*4];
__device__ float g_y  [N_];
__device__ float g_xyz0[N_*3];
__device__ float g_xyz1[N_*3];
__device__ float g_xs_[N_], g_ys_[N_], g_zs_[N_];
__device__ int   g_cnt[N_];
__device__ int   g_rowptr[N_+1];
__device__ int   g_cur[N_];
__device__ int   g_psrc[E_];
__device__ int   g_maskmode;

// ---------------- helpers ----------------
__device__ __forceinline__ uint32_t smem_u32(const void* p) {
    uint32_t a;
    asm("{ .reg .u64 t; cvta.to.shared.u64 t, %1; cvt.u32.u64 %0, t; }" : "=r"(a) : "l"(p));
    return a;
}
#define LDMX4(r, a) \
    asm volatile("ldmatrix.sync.aligned.m8n8.x4.shared.b16 {%0,%1,%2,%3}, [%4];" \
        : "=r"((r)[0]), "=r"((r)[1]), "=r"((r)[2]), "=r"((r)[3]) : "r"(a))
#define MMA16816(c, a, b0, b1) \
    asm volatile("mma.sync.aligned.m16n8k16.row.col.f32.f16.f16.f32 " \
        "{%0,%1,%2,%3}, {%4,%5,%6,%7}, {%8,%9}, {%0,%1,%2,%3};" \
        : "+f"((c)[0]), "+f"((c)[1]), "+f"((c)[2]), "+f"((c)[3]) \
        : "r"((a)[0]), "r"((a)[1]), "r"((a)[2]), "r"((a)[3]), "r"(b0), "r"(b1))

__device__ __forceinline__ void split1h(float v, hf& h, hf& l) {
    h = __float2half_rn(v);
    l = __float2half_rn(v - __half2float(h));
}

__device__ __forceinline__ float fast_exp(float x) {
    float t = x * 1.4426950408889634f;
    t = fmaxf(t, -126.0f);
    float z = t + 12582912.0f;
    float n = z - 12582912.0f;
    float f = t - n;
    float p = 1.5404e-4f;
    p = fmaf(p, f, 1.33336e-3f);
    p = fmaf(p, f, 9.61813e-3f);
    p = fmaf(p, f, 5.550411e-2f);
    p = fmaf(p, f, 2.4022651e-1f);
    p = fmaf(p, f, 6.9314718e-1f);
    p = fmaf(p, f, 1.0f);
    int ni = __float_as_int(z) - 0x4B400000;
    float sc = __int_as_float((ni + 127) << 23);
    return p * sc;
}

__global__ void detect_mask_mode(const unsigned int* __restrict__ m) {
    bool allbin = true, anyfloat = false;
    for (int i = 0; i < 1024; i++) {
        unsigned int w = m[i];
        if (w == 0x3f800000u) anyfloat = true;
        if (w > 1u) allbin = false;
    }
    g_maskmode = anyfloat ? 2 : (allbin ? 1 : 0);
}
__device__ __forceinline__ bool mask_at(const void* p, size_t i, int mode) {
    if (mode == 0) return ((const unsigned char*)p)[i] != 0;
    if (mode == 1) return ((const int*)p)[i] != 0;
    return ((const float*)p)[i] != 0.0f;
}

__global__ void split_hf(const float* __restrict__ X, hf* __restrict__ Xh, hf* __restrict__ Xl)
{
    int i = blockIdx.x * blockDim.x + threadIdx.x;
    float4 x = *(const float4*)&X[(size_t)i*4];
    float xv[4] = {x.x, x.y, x.z, x.w};
    __align__(8) hf h[4], l[4];
#pragma unroll
    for (int e = 0; e < 4; e++) split1h(xv[e], h[e], l[e]);
    *(uint2*)&Xh[(size_t)i*4] = *(uint2*)h;
    *(uint2*)&Xl[(size_t)i*4] = *(uint2*)l;
}

// W [nmat][K,N] fp32 -> Wt [nmat][N,K] fp16 (single)
__global__ void wsplit(const float* __restrict__ W, hf* __restrict__ Wth,
                       int K, int N, int KN)
{
    int idx = blockIdx.x * 256 + threadIdx.x;
    int mat = idx / KN;
    int rem = idx - mat * KN;
    int k = rem / N;
    int n = rem - k * N;
    Wth[mat * KN + n * K + k] = __float2half_rn(W[idx]);
}

__global__ void wsplit_ro(const float* __restrict__ W, hf* __restrict__ Wth, int ro)
{
    int idx = blockIdx.x * 256 + threadIdx.x;
    int l = idx >> 16;
    int rem = idx & 65535;
    int k = rem >> 8, n = rem & 255;
    Wth[(size_t)l * 768 * HID_ + (size_t)(ro + n) * HID_ + k] = __float2half_rn(W[idx]);
}

__global__ void qkvbias(const float* __restrict__ qb, const float* __restrict__ kb,
                        const float* __restrict__ vb, float* __restrict__ out)
{
    int idx = blockIdx.x * 256 + threadIdx.x;
    if (idx >= 4*768) return;
    int l = idx / 768, c = idx % 768;
    int sect = c >> 8, cc = c & 255;
    out[idx] = (sect == 0) ? qb[l*256+cc] : (sect == 1) ? kb[l*256+cc] : vb[l*256+cc];
}

// ================= gemm_tc64: 64x64 tile fp16-mma, 2-pass (A split, B single) ===========
__global__ __launch_bounds__(256) void gemm_tc64(
    const hf* __restrict__ Ah, const hf* __restrict__ Al,
    const hf* __restrict__ Bh,
    int K, int Nc,
    const float* __restrict__ bias, int relu, float cacc,
    const float* __restrict__ X1, float c1,
    const float* __restrict__ X2, float c2,
    const float* __restrict__ X3, float c3,
    float* __restrict__ C, float* __restrict__ C2,
    hf* __restrict__ Ch, hf* __restrict__ Cl)
{
    __shared__ __align__(16) char Ash[2][64*80];
    __shared__ __align__(16) char Bsh[2][64*80];
    const int t = threadIdx.x, lane = t & 31, wid = t >> 5;
    const int wr32 = (wid >> 2) * 32, wc16 = (wid & 3) * 16;
    const int g = lane >> 2, tg = lane & 3;
    const int a_r = ((lane >> 3) & 1) * 8 + (lane & 7);
    const int a_c = (lane >> 4) * 16;
    const int b_r = ((lane >> 4) & 1) * 8 + (lane & 7);
    const int b_c = ((lane >> 3) & 1) * 16;
    const int m0 = blockIdx.y * 64, n0 = blockIdx.x * 64;
    const int lrow = t >> 2, lq = t & 3;

    uint32_t aS[2] = { smem_u32(Ash[0]), smem_u32(Ash[1]) };
    uint32_t bS[2] = { smem_u32(Bsh[0]), smem_u32(Bsh[1]) };
    float acc[2][2][4] = {};

    const hf* APs[2] = { Ah, Al };
    const int chunks = K >> 5;
    const int NC = 2 * chunks;

    uint4 va = *(const uint4*)(APs[0] + (size_t)(m0+lrow)*K + lq*8);
    uint4 vb = *(const uint4*)(Bh + (size_t)(n0+lrow)*K + lq*8);
    *(uint4*)(Ash[0] + lrow*80 + lq*16) = va;
    *(uint4*)(Bsh[0] + lrow*80 + lq*16) = vb;
    __syncthreads();

    int pn = 0, kn = 0;
    for (int c = 0; c < NC; c++) {
        const int buf = c & 1;
        const bool more = (c + 1 < NC);
        if (more) {
            kn++; if (kn == chunks) { kn = 0; pn++; }
            va = *(const uint4*)(APs[pn] + (size_t)(m0+lrow)*K + kn*32 + lq*8);
            vb = *(const uint4*)(Bh + (size_t)(n0+lrow)*K + kn*32 + lq*8);
        }
#pragma unroll
        for (int kk = 0; kk < 2; kk++) {
            uint32_t af[2][4], bfr[4];
#pragma unroll
            for (int mt = 0; mt < 2; mt++) {
                uint32_t ad = aS[buf] + (uint32_t)((wr32 + mt*16 + a_r)*80 + kk*32 + a_c);
                LDMX4(af[mt], ad);
            }
            {
                uint32_t bd = bS[buf] + (uint32_t)((wc16 + b_r)*80 + kk*32 + b_c);
                LDMX4(bfr, bd);
            }
#pragma unroll
            for (int mt = 0; mt < 2; mt++)
#pragma unroll
                for (int nt = 0; nt < 2; nt++)
                    MMA16816(acc[mt][nt], af[mt], bfr[nt*2], bfr[nt*2+1]);
        }
        if (more) {
            const int nb = buf ^ 1;
            *(uint4*)(Ash[nb] + lrow*80 + lq*16) = va;
            *(uint4*)(Bsh[nb] + lrow*80 + lq*16) = vb;
            __syncthreads();
        }
    }

#pragma unroll
    for (int mt = 0; mt < 2; mt++) {
#pragma unroll
        for (int h = 0; h < 2; h++) {
            const int m = m0 + wr32 + mt*16 + g + 8*h;
            const size_t rb = (size_t)m * Nc;
#pragma unroll
            for (int nt = 0; nt < 2; nt++) {
                const int n = n0 + wc16 + nt*8 + 2*tg;
                float2 r = { acc[mt][nt][h*2], acc[mt][nt][h*2+1] };
                r.x *= cacc; r.y *= cacc;
                if (bias) { r.x += bias[n]; r.y += bias[n+1]; }
                if (X1) { float2 q = *(const float2*)&X1[rb+n];
                          r.x = fmaf(c1,q.x,r.x); r.y = fmaf(c1,q.y,r.y); }
                if (X2) { float2 q = *(const float2*)&X2[rb+n];
                          r.x = fmaf(c2,q.x,r.x); r.y = fmaf(c2,q.y,r.y); }
                if (X3) { float2 q = *(const float2*)&X3[rb+n];
                          r.x = fmaf(c3,q.x,r.x); r.y = fmaf(c3,q.y,r.y); }
                if (relu) { r.x = fmaxf(r.x, 0.f); r.y = fmaxf(r.y, 0.f); }
                if (C)  *(float2*)&C[rb+n]  = r;
                if (C2) *(float2*)&C2[rb+n] = r;
                if (Ch) {
                    __align__(4) hf h2[2], l2[2];
                    split1h(r.x, h2[0], l2[0]); split1h(r.y, h2[1], l2[1]);
                    *(uint32_t*)&Ch[rb+n] = *(uint32_t*)h2;
                    *(uint32_t*)&Cl[rb+n] = *(uint32_t*)l2;
                }
            }
        }
    }
}

// ================= qkv_tc: fused QKV GEMM, tile 128x64, Nc=768 routed =================
__global__ __launch_bounds__(256) void qkv_tc(
    const hf* __restrict__ Ah, const hf* __restrict__ Al,
    const hf* __restrict__ Bh,
    const float* __restrict__ bias,
    hf* __restrict__ Qh, hf* __restrict__ Ql,
    hf* __restrict__ Kh, hf* __restrict__ Vth)
{
    __shared__ __align__(16) char Ash[2][128*80];
    __shared__ __align__(16) char Bsh[2][64*80];
    const int t = threadIdx.x, lane = t & 31, wid = t >> 5;
    const int wr32 = (wid >> 1) * 32, wc32 = (wid & 1) * 32;
    const int g = lane >> 2, tg = lane & 3;
    const int a_r = ((lane >> 3) & 1) * 8 + (lane & 7);
    const int a_c = (lane >> 4) * 16;
    const int b_r = ((lane >> 4) & 1) * 8 + (lane & 7);
    const int b_c = ((lane >> 3) & 1) * 16;
    const int m0 = blockIdx.y * 128, n0 = blockIdx.x * 64;
    const int K = HID_;

    uint32_t aS[2] = { smem_u32(Ash[0]), smem_u32(Ash[1]) };
    uint32_t bS[2] = { smem_u32(Bsh[0]), smem_u32(Bsh[1]) };
    float acc[2][4][4] = {};

    const hf* APs[2] = { Ah, Al };
    const int chunks = K >> 5;
    const int NC = 2 * chunks;

    uint4 va[2], vb;
#pragma unroll
    for (int i = 0; i < 2; i++) {
        int idx = t + i*256, row = idx >> 2, q = idx & 3;
        va[i] = *(const uint4*)(APs[0] + (size_t)(m0+row)*K + q*8);
    }
    { int row = t >> 2, q = t & 3;
      vb = *(const uint4*)(Bh + (size_t)(n0+row)*K + q*8); }
#pragma unroll
    for (int i = 0; i < 2; i++) {
        int idx = t + i*256, row = idx >> 2, q = idx & 3;
        *(uint4*)(Ash[0] + row*80 + q*16) = va[i];
    }
    { int row = t >> 2, q = t & 3;
      *(uint4*)(Bsh[0] + row*80 + q*16) = vb; }
    __syncthreads();

    int pn = 0, kn = 0;
    for (int c = 0; c < NC; c++) {
        const int buf = c & 1;
        const bool more = (c + 1 < NC);
        if (more) {
            kn++; if (kn == chunks) { kn = 0; pn++; }
#pragma unroll
            for (int i = 0; i < 2; i++) {
                int idx = t + i*256, row = idx >> 2, q = idx & 3;
                va[i] = *(const uint4*)(APs[pn] + (size_t)(m0+row)*K + kn*32 + q*8);
            }
            { int row = t >> 2, q = t & 3;
              vb = *(const uint4*)(Bh + (size_t)(n0+row)*K + kn*32 + q*8); }
        }
#pragma unroll
        for (int kk = 0; kk < 2; kk++) {
            uint32_t af[2][4], bfr[2][4];
#pragma unroll
            for (int mt = 0; mt < 2; mt++) {
                uint32_t ad = aS[buf] + (uint32_t)((wr32 + mt*16 + a_r)*80 + kk*32 + a_c);
                LDMX4(af[mt], ad);
            }
#pragma unroll
            for (int np = 0; np < 2; np++) {
                uint32_t bd = bS[buf] + (uint32_t)((wc32 + np*16 + b_r)*80 + kk*32 + b_c);
                LDMX4(bfr[np], bd);
            }
#pragma unroll
            for (int mt = 0; mt < 2; mt++)
#pragma unroll
                for (int nt = 0; nt < 4; nt++)
                    MMA16816(acc[mt][nt], af[mt], bfr[nt>>1][(nt&1)*2], bfr[nt>>1][(nt&1)*2+1]);
        }
        if (more) {
            const int nb = buf ^ 1;
#pragma unroll
            for (int i = 0; i < 2; i++) {
                int idx = t + i*256, row = idx >> 2, q = idx & 3;
                *(uint4*)(Ash[nb] + row*80 + q*16) = va[i];
            }
            { int row = t >> 2, q = t & 3;
              *(uint4*)(Bsh[nb] + row*80 + q*16) = vb; }
            __syncthreads();
        }
    }

#pragma unroll
    for (int mt = 0; mt < 2; mt++) {
#pragma unroll
        for (int h = 0; h < 2; h++) {
            const int m = m0 + wr32 + mt*16 + g + 8*h;
#pragma unroll
            for (int nt = 0; nt < 4; nt++) {
                const int n = n0 + wc32 + nt*8 + 2*tg;
                float2 r = { acc[mt][nt][h*2], acc[mt][nt][h*2+1] };
                r.x += bias[n]; r.y += bias[n+1];
                const int sect = n >> 8, cc = n & 255;
                if (sect == 0) {
                    __align__(4) hf hh[2], ll[2];
                    split1h(r.x, hh[0], ll[0]); split1h(r.y, hh[1], ll[1]);
                    *(uint32_t*)&Qh[(size_t)m*HID_ + cc] = *(uint32_t*)hh;
                    *(uint32_t*)&Ql[(size_t)m*HID_ + cc] = *(uint32_t*)ll;
                } else if (sect == 1) {
                    __align__(4) hf hh[2] = { __float2half_rn(r.x), __float2half_rn(r.y) };
                    *(uint32_t*)&Kh[(size_t)m*HID_ + cc] = *(uint32_t*)hh;
                } else {
                    Vth[(size_t)cc * N_ + m]     = __float2half_rn(r.x);
                    Vth[(size_t)(cc+1) * N_ + m] = __float2half_rn(r.y);
                }
            }
        }
    }
}

// ---- shared mma-core macro (128x128 kernels) ----
#define COMPUTE32(abase, bbase)                                                     \
    _Pragma("unroll")                                                               \
    for (int kk = 0; kk < 2; kk++) {                                                \
        uint32_t af[4][4], bfr[2][4];                                               \
        _Pragma("unroll")                                                           \
        for (int mt = 0; mt < 4; mt++) {                                            \
            uint32_t ad = (abase) + (uint32_t)((wr64 + mt*16 + a_r)*80 + kk*32 + a_c); \
            LDMX4(af[mt], ad);                                                      \
        }                                                                           \
        _Pragma("unroll")                                                           \
        for (int np = 0; np < 2; np++) {                                            \
            uint32_t bd = (bbase) + (uint32_t)((wc32 + np*16 + b_r)*80 + kk*32 + b_c); \
            LDMX4(bfr[np], bd);                                                     \
        }                                                                           \
        _Pragma("unroll")                                                           \
        for (int mt = 0; mt < 4; mt++)                                              \
            _Pragma("unroll")                                                       \
            for (int nt = 0; nt < 4; nt++)                                          \
                MMA16816(acc[mt][nt], af[mt], bfr[nt>>1][(nt&1)*2], bfr[nt>>1][(nt&1)*2+1]); \
    }

// ================= scores via fp16 mma, 2-pass (q split, k single) =================
__global__ __launch_bounds__(256) void scores_mma(
    const hf* __restrict__ qh, const hf* __restrict__ ql,
    const hf* __restrict__ kh,
    const float* __restrict__ xyz,
    const void* __restrict__ dmask, const void* __restrict__ bmask,
    float* __restrict__ S)
{
    __shared__ __align__(16) char Ash[2][128*80];
    __shared__ __align__(16) char Bsh[2][128*80];
    __shared__ float gix[128*3], gisq[128], giy[128];
    __shared__ float gjx[128*3], gjsq[128], gjy[128];
    const int t = threadIdx.x, lane = t & 31, wid = t >> 5;
    const int wr64 = (wid >> 2) * 64, wc32 = (wid & 3) * 32;
    const int g = lane >> 2, tg = lane & 3;
    const int a_r = ((lane >> 3) & 1) * 8 + (lane & 7);
    const int a_c = (lane >> 4) * 16;
    const int b_r = ((lane >> 4) & 1) * 8 + (lane & 7);
    const int b_c = ((lane >> 3) & 1) * 16;
    const int i0 = blockIdx.y * 128, j0 = blockIdx.x * 128;
    const int lrow = t >> 2, lq = t & 3;

    if (t < 128) {
        float a = xyz[(i0+t)*3+0], b = xyz[(i0+t)*3+1], c = xyz[(i0+t)*3+2];
        gix[t*3+0]=a; gix[t*3+1]=b; gix[t*3+2]=c;
        gisq[t] = fmaf(c,c,fmaf(b,b,a*a));
        giy[t]  = g_y[i0+t];
    } else {
        int u = t - 128;
        float a = xyz[(j0+u)*3+0], b = xyz[(j0+u)*3+1], c = xyz[(j0+u)*3+2];
        gjx[u*3+0]=a; gjx[u*3+1]=b; gjx[u*3+2]=c;
        gjsq[u] = fmaf(c,c,fmaf(b,b,a*a));
        gjy[u]  = g_y[j0+u];
    }

    uint32_t aS[2] = { smem_u32(Ash[0]), smem_u32(Ash[1]) };
    uint32_t bS[2] = { smem_u32(Bsh[0]), smem_u32(Bsh[1]) };
    float acc[4][4][4] = {};

    const hf* APs[2] = { qh, ql };

    uint4 va[2], vb[2];
#pragma unroll
    for (int r = 0; r < 2; r++) {
        int row = lrow + r*64;
        va[r] = *(const uint4*)(APs[0] + (size_t)(i0+row)*HID_ + lq*8);
        vb[r] = *(const uint4*)(kh + (size_t)(j0+row)*HID_ + lq*8);
    }
#pragma unroll
    for (int r = 0; r < 2; r++) {
        int row = lrow + r*64;
        *(uint4*)(Ash[0] + row*80 + lq*16) = va[r];
        *(uint4*)(Bsh[0] + row*80 + lq*16) = vb[r];
    }
    __syncthreads();

    const int NC = 16;   // 2 passes x 8 chunks
    for (int c = 0; c < NC; c++) {
        const int buf = c & 1;
        if (c + 1 < NC) {
            const int p = (c+1) >> 3, kc = (c+1) & 7;
            const hf* A = APs[p];
#pragma unroll
            for (int r = 0; r < 2; r++) {
                int row = lrow + r*64;
                va[r] = *(const uint4*)(A + (size_t)(i0+row)*HID_ + kc*32 + lq*8);
                vb[r] = *(const uint4*)(kh + (size_t)(j0+row)*HID_ + kc*32 + lq*8);
            }
        }
        COMPUTE32(aS[buf], bS[buf]);
        if (c + 1 < NC) {
            const int nb = buf ^ 1;
#pragma unroll
            for (int r = 0; r < 2; r++) {
                int row = lrow + r*64;
                *(uint4*)(Ash[nb] + row*80 + lq*16) = va[r];
                *(uint4*)(Bsh[nb] + row*80 + lq*16) = vb[r];
            }
            __syncthreads();
        }
    }

    const int mode = g_maskmode;
#pragma unroll
    for (int mt = 0; mt < 4; mt++) {
#pragma unroll
        for (int h = 0; h < 2; h++) {
            const int li = wr64 + mt*16 + g + 8*h;
            const int gi = i0 + li;
            const float xa = gix[li*3], xbv = gix[li*3+1], xc = gix[li*3+2];
            const float sqa = gisq[li], ya = giy[li];
            const size_t rb = (size_t)gi * N_;
#pragma unroll
            for (int nt = 0; nt < 4; nt++) {
                const int lj0 = wc32 + nt*8 + 2*tg;
                float2 r;
#pragma unroll
                for (int e = 0; e < 2; e++) {
                    const int lj = lj0 + e;
                    const size_t gidx = rb + j0 + lj;
                    float dot = fmaf(xc, gjx[lj*3+2], fmaf(xbv, gjx[lj*3+1], xa * gjx[lj*3]));
                    float dist2 = (sqa + gjsq[lj]) - 2.0f * dot;
                    bool ok = mask_at(dmask, gidx, mode) && mask_at(bmask, gidx, mode) && (dist2 <= 100.0f);
                    float av = acc[mt][nt][h*2 + e];
                    ((float*)&r)[e] = ok ? (av * 0.0625f - fabsf(ya - gjy[lj])) : NEG_;
                }
                *(float2*)&S[rb + j0 + lj0] = r;
            }
        }
    }
}

// ================= attn@V via fp16 mma, 2-pass (S split, V single), split-K z ==========
__global__ __launch_bounds__(256) void attnv_mma(
    const hf* __restrict__ Sh, const hf* __restrict__ Sl,
    const hf* __restrict__ Vth,
    float* __restrict__ Cpart)
{
    __shared__ __align__(16) char Ash[2][128*80];
    __shared__ __align__(16) char Bsh[2][128*80];
    const int t = threadIdx.x, lane = t & 31, wid = t >> 5;
    const int wr64 = (wid >> 2) * 64, wc32 = (wid & 3) * 32;
    const int g = lane >> 2, tg = lane & 3;
    const int a_r = ((lane >> 3) & 1) * 8 + (lane & 7);
    const int a_c = (lane >> 4) * 16;
    const int b_r = ((lane >> 4) & 1) * 8 + (lane & 7);
    const int b_c = ((lane >> 3) & 1) * 16;
    const int m0 = blockIdx.y * 128, n0 = blockIdx.x * 128;
    const int kbase = blockIdx.z * (N_ / KZ_);
    const int lrow = t >> 2, lq = t & 3;

    uint32_t aS[2] = { smem_u32(Ash[0]), smem_u32(Ash[1]) };
    uint32_t bS[2] = { smem_u32(Bsh[0]), smem_u32(Bsh[1]) };
    float acc[4][4][4] = {};

    const hf* APs[2] = { Sh, Sl };
    const int CPP = (N_ / KZ_) / 32;       // 32
    const int NC = 2 * CPP;

    uint4 va[2], vb[2];
#pragma unroll
    for (int r = 0; r < 2; r++) {
        int row = lrow + r*64;
        va[r] = *(const uint4*)(APs[0] + (size_t)(m0+row)*N_ + kbase + lq*8);
        vb[r] = *(const uint4*)(Vth + (size_t)(n0+row)*N_ + kbase + lq*8);
    }
#pragma unroll
    for (int r = 0; r < 2; r++) {
        int row = lrow + r*64;
        *(uint4*)(Ash[0] + row*80 + lq*16) = va[r];
        *(uint4*)(Bsh[0] + row*80 + lq*16) = vb[r];
    }
    __syncthreads();

    for (int c = 0; c < NC; c++) {
        const int buf = c & 1;
        if (c + 1 < NC) {
            const int p = (c+1) / CPP, kc = (c+1) % CPP;
            const hf* A = APs[p];
#pragma unroll
            for (int r = 0; r < 2; r++) {
                int row = lrow + r*64;
                va[r] = *(const uint4*)(A + (size_t)(m0+row)*N_ + kbase + kc*32 + lq*8);
                vb[r] = *(const uint4*)(Vth + (size_t)(n0+row)*N_ + kbase + kc*32 + lq*8);
            }
        }
        COMPUTE32(aS[buf], bS[buf]);
        if (c + 1 < NC) {
            const int nb = buf ^ 1;
#pragma unroll
            for (int r = 0; r < 2; r++) {
                int row = lrow + r*64;
                *(uint4*)(Ash[nb] + row*80 + lq*16) = va[r];
                *(uint4*)(Bsh[nb] + row*80 + lq*16) = vb[r];
            }
            __syncthreads();
        }
    }

    float* Cz = Cpart + (size_t)blockIdx.z * N_ * HID_;
#pragma unroll
    for (int mt = 0; mt < 4; mt++) {
#pragma unroll
        for (int h = 0; h < 2; h++) {
            const int m = m0 + wr64 + mt*16 + g + 8*h;
            const size_t rb = (size_t)m * HID_;
#pragma unroll
            for (int nt = 0; nt < 4; nt++) {
                const int n = n0 + wc32 + nt*8 + 2*tg;
                float2 r = { acc[mt][nt][h*2], acc[mt][nt][h*2 + 1] };
                *(float2*)&Cz[rb + n] = r;
            }
        }
    }
}

__global__ void combine_parts(const float* __restrict__ P,
                              hf* __restrict__ Hh, hf* __restrict__ Hl)
{
    int i = blockIdx.x * blockDim.x + threadIdx.x;
    const size_t n = (size_t)N_ * HID_;
    float4 a = *(const float4*)&P[(size_t)i*4];
    float4 b = *(const float4*)&P[n + (size_t)i*4];
    float4 c = *(const float4*)&P[2*n + (size_t)i*4];
    float4 d = *(const float4*)&P[3*n + (size_t)i*4];
    float rv[4] = { a.x+b.x+c.x+d.x, a.y+b.y+c.y+d.y, a.z+b.z+c.z+d.z, a.w+b.w+c.w+d.w };
    __align__(8) hf hh[4], ll[4];
#pragma unroll
    for (int e = 0; e < 4; e++) split1h(rv[e], hh[e], ll[e]);
    *(uint2*)&Hh[(size_t)i*4] = *(uint2*)hh;
    *(uint2*)&Hl[(size_t)i*4] = *(uint2*)ll;
}

// ---------------- softmax + attn@xyz + fp16 split of attn ----------------
__global__ void softmax_xyz(const float* __restrict__ S,
                            hf* __restrict__ Sh, hf* __restrict__ Sl,
                            const float* __restrict__ xs, const float* __restrict__ ys,
                            const float* __restrict__ zs, float* __restrict__ out)
{
    __shared__ float r0[256], r1[256], r2[256];
    const int row = blockIdx.x, t = threadIdx.x;
    const float* p = S + (size_t)row * N_;
    float4 v[4];
    float mx = -1e30f;
#pragma unroll
    for (int c = 0; c < 4; c++) {
        v[c] = *(const float4*)&p[c*1024 + t*4];
        mx = fmaxf(mx, fmaxf(fmaxf(v[c].x, v[c].y), fmaxf(v[c].z, v[c].w)));
    }
    r0[t] = mx; __syncthreads();
    for (int s = 128; s > 0; s >>= 1) { if (t < s) r0[t] = fmaxf(r0[t], r0[t+s]); __syncthreads(); }
    mx = r0[0]; __syncthreads();
    float sum = 0.0f;
#pragma unroll
    for (int c = 0; c < 4; c++) {
        v[c].x = fast_exp(v[c].x - mx); v[c].y = fast_exp(v[c].y - mx);
        v[c].z = fast_exp(v[c].z - mx); v[c].w = fast_exp(v[c].w - mx);
        sum += v[c].x + v[c].y + v[c].z + v[c].w;
    }
    r0[t] = sum; __syncthreads();
    for (int s = 128; s > 0; s >>= 1) { if (t < s) r0[t] += r0[t+s]; __syncthreads(); }
    const float inv = 1.0f / r0[0];
    __syncthreads();
    float a0 = 0.f, a1 = 0.f, a2 = 0.f;
#pragma unroll
    for (int c = 0; c < 4; c++) {
        v[c].x *= inv; v[c].y *= inv; v[c].z *= inv; v[c].w *= inv;
        float vv[4] = { v[c].x, v[c].y, v[c].z, v[c].w };
        __align__(8) hf vh[4], vl[4];
#pragma unroll
        for (int e = 0; e < 4; e++) split1h(vv[e], vh[e], vl[e]);
        const size_t off = (size_t)row * N_ + c*1024 + t*4;
        *(uint2*)&Sh[off] = *(uint2*)vh;
        *(uint2*)&Sl[off] = *(uint2*)vl;
        const int j = c*1024 + t*4;
        a0 = fmaf(v[c].x, xs[j], fmaf(v[c].y, xs[j+1], fmaf(v[c].z, xs[j+2], fmaf(v[c].w, xs[j+3], a0))));
        a1 = fmaf(v[c].x, ys[j], fmaf(v[c].y, ys[j+1], fmaf(v[c].z, ys[j+2], fmaf(v[c].w, ys[j+3], a1))));
        a2 = fmaf(v[c].x, zs[j], fmaf(v[c].y, zs[j+1], fmaf(v[c].z, zs[j+2], fmaf(v[c].w, zs[j+3], a2))));
    }
    r0[t]=a0; r1[t]=a1; r2[t]=a2; __syncthreads();
    for (int s = 128; s > 0; s >>= 1) {
        if (t < s) { r0[t]+=r0[t+s]; r1[t]+=r1[t+s]; r2[t]+=r2[t+s]; }
        __syncthreads();
    }
    if (t == 0) { out[row*3+0]=r0[0]; out[row*3+1]=r1[0]; out[row*3+2]=r2[0]; }
}

__global__ void xyz2soa(const float* __restrict__ xyz, float* __restrict__ xs,
                        float* __restrict__ ys, float* __restrict__ zs)
{
    int i = blockIdx.x * blockDim.x + threadIdx.x;
    if (i < N_) { xs[i] = xyz[3*i]; ys[i] = xyz[3*i+1]; zs[i] = xyz[3*i+2]; }
}

// ---------------- GAT pieces ----------------
__global__ void compute_elr(const float* __restrict__ hl, const float* __restrict__ al,
                            const float* __restrict__ ar)
{
    int idx = blockIdx.x * blockDim.x + threadIdx.x;
    if (idx >= N_*4) return;
    int node = idx >> 2, h = idx & 3;
    const float* row = hl + (size_t)node * HID_ + h * 64;
    float sl = 0.f, sr = 0.f;
#pragma unroll 8
    for (int d = 0; d < 64; d++) {
        float v = row[d];
        sl = fmaf(v, al[h*64+d], sl);
        sr = fmaf(v, ar[h*64+d], sr);
    }
    g_el[idx] = sl; g_er[idx] = sr;
}

__global__ void zero_cnt() { int i = blockIdx.x*blockDim.x + threadIdx.x; if (i < N_) g_cnt[i] = 0; }
__global__ void count_edges(const int* __restrict__ dst) {
    int e = blockIdx.x*blockDim.x + threadIdx.x; if (e < E_) atomicAdd(&g_cnt[dst[e]], 1);
}
__global__ void scan4096() {
    __shared__ int part[1024];
    int t = threadIdx.x, base = t * 4;
    int a0 = g_cnt[base], a1 = g_cnt[base+1], a2 = g_cnt[base+2], a3 = g_cnt[base+3];
    int s = a0 + a1 + a2 + a3;
    part[t] = s; __syncthreads();
    for (int off = 1; off < 1024; off <<= 1) {
        int v = (t >= off) ? part[t-off] : 0;
        __syncthreads();
        part[t] += v;
        __syncthreads();
    }
    int excl = part[t] - s;
    g_rowptr[base+0] = excl;           g_cur[base+0] = excl;
    g_rowptr[base+1] = excl+a0;        g_cur[base+1] = excl+a0;
    g_rowptr[base+2] = excl+a0+a1;     g_cur[base+2] = excl+a0+a1;
    g_rowptr[base+3] = excl+a0+a1+a2;  g_cur[base+3] = excl+a0+a1+a2;
    if (t == 1023) g_rowptr[4096] = part[1023];
}
__global__ void scatter_edges(const int* __restrict__ src, const int* __restrict__ dst) {
    int e = blockIdx.x*blockDim.x + threadIdx.x;
    if (e < E_) { int p = atomicAdd(&g_cur[dst[e]], 1); g_psrc[p] = src[e]; }
}

__global__ void gat_aggregate(const float* __restrict__ hl, float* __restrict__ xg)
{
    const int node = (blockIdx.x * blockDim.x + threadIdx.x) >> 5;
    const int lane = threadIdx.x & 31;
    if (node >= N_) return;
    const int beg = g_rowptr[node], end = g_rowptr[node+1];
    const float er_i = (lane < 4) ? g_er[node*4 + lane] : 0.f;
    float m = -1e30f;
    for (int p = beg; p < end; p++) {
        int s = g_psrc[p];
        if (lane < 4) {
            float v = g_el[s*4 + lane] + er_i;
            float e = (v > 0.f) ? v : 0.2f * v;
            m = fmaxf(m, e);
        }
    }
    float m0 = __shfl_sync(0xffffffffu, m, 0), m1 = __shfl_sync(0xffffffffu, m, 1);
    float m2 = __shfl_sync(0xffffffffu, m, 2), m3 = __shfl_sync(0xffffffffu, m, 3);
    const int myh = lane >> 3;
    float4 acc0 = {0,0,0,0}, acc1 = {0,0,0,0};
    float z = 0.f;
    for (int p = beg; p < end; p++) {
        int s = g_psrc[p];
        float w = 0.f;
        if (lane < 4) {
            float v = g_el[s*4 + lane] + er_i;
            float e = (v > 0.f) ? v : 0.2f * v;
            float mm = (lane==0)?m0:(lane==1)?m1:(lane==2)?m2:m3;
            w = fast_exp(e - mm);
            z += w;
        }
        float w0 = __shfl_sync(0xffffffffu, w, 0), w1 = __shfl_sync(0xffffffffu, w, 1);
        float w2 = __shfl_sync(0xffffffffu, w, 2), w3 = __shfl_sync(0xffffffffu, w, 3);
        float wm = (myh==0)?w0:(myh==1)?w1:(myh==2)?w2:w3;
        const float4* hp = (const float4*)(hl + (size_t)s * HID_ + lane * 8);
        float4 hv0 = hp[0], hv1 = hp[1];
        acc0.x=fmaf(wm,hv0.x,acc0.x); acc0.y=fmaf(wm,hv0.y,acc0.y);
        acc0.z=fmaf(wm,hv0.z,acc0.z); acc0.w=fmaf(wm,hv0.w,acc0.w);
        acc1.x=fmaf(wm,hv1.x,acc1.x); acc1.y=fmaf(wm,hv1.y,acc1.y);
        acc1.z=fmaf(wm,hv1.z,acc1.z); acc1.w=fmaf(wm,hv1.w,acc1.w);
    }
    float z0 = __shfl_sync(0xffffffffu, z, 0), z1 = __shfl_sync(0xffffffffu, z, 1);
    float z2 = __shfl_sync(0xffffffffu, z, 2), z3 = __shfl_sync(0xffffffffu, z, 3);
    float zm = (myh==0)?z0:(myh==1)?z1:(myh==2)?z2:z3;
    float inv = 1.0f / (zm + 1e-9f);
    acc0.x*=inv; acc0.y*=inv; acc0.z*=inv; acc0.w*=inv;
    acc1.x*=inv; acc1.y*=inv; acc1.z*=inv; acc1.w*=inv;
    float4* op = (float4*)(xg + (size_t)node * HID_ + lane * 8);
    op[0] = acc0; op[1] = acc1;
}

__global__ void pack_support(const float* __restrict__ xg, const float* __restrict__ h0,
                             hf* __restrict__ suph, hf* __restrict__ supl)
{
    int i = blockIdx.x * blockDim.x + threadIdx.x;
    if (i >= N_ * 512) return;
    int r = i >> 9, c = i & 511;
    float v = (c < 256) ? xg[(size_t)r*256 + c] : h0[(size_t)r*256 + (c-256)];
    hf h, l; split1h(v, h, l);
    suph[i] = h; supl[i] = l;
}

__global__ void yhat_k(const float* __restrict__ x, const float* __restrict__ W,
                       const float* __restrict__ b)
{
    int i = blockIdx.x * blockDim.x + threadIdx.x;
    if (i >= N_) return;
    const float* r = x + (size_t)i * HID_;
    float l0 = b[0], l1 = b[1];
#pragma unroll 8
    for (int d = 0; d < HID_; d++) {
        float v = r[d];
        l0 = fmaf(v, W[2*d+0], l0);
        l1 = fmaf(v, W[2*d+1], l1);
    }
    g_y[i] = 1.0f / (1.0f + expf(l0 - l1));
}

__global__ void cls_k(const float* __restrict__ x, const float* __restrict__ W,
                      const float* __restrict__ b, float* __restrict__ out)
{
    int i = blockIdx.x * blockDim.x + threadIdx.x;
    if (i >= N_) return;
    const float* r = x + (size_t)i * HID_;
    float l0 = b[0], l1 = b[1];
#pragma unroll 8
    for (int d = 0; d < HID_; d++) {
        float v = r[d];
        l0 = fmaf(v, W[2*d+0], l0);
        l1 = fmaf(v, W[2*d+1], l1);
    }
    out[2*i+0] = l0;
    out[2*i+1] = l1;
}

// ---------------- host orchestration ----------------
extern "C" void kernel_launch(void* const* d_in, const int* in_sizes, int n_in,
                              void* d_out, int out_size)
{
    const float* feat   = (const float*)d_in[0];
    const float* xyz_in = (const float*)d_in[1];
    const int*   src    = (const int*)  d_in[2];
    const int*   dst    = (const int*)  d_in[3];
    const void*  dmask  = d_in[4];
    const void*  bmask  = d_in[5];
    const float* fcW  = (const float*)d_in[6];
    const float* fcb  = (const float*)d_in[7];
    const float* gatW = (const float*)d_in[8];
    const float* al   = (const float*)d_in[9];
    const float* ar   = (const float*)d_in[10];
    const float* gcW  = (const float*)d_in[11];
    const float* cgW  = (const float*)d_in[12];
    const float* cgb  = (const float*)d_in[13];
    const float* qW   = (const float*)d_in[14];
    const float* qb_  = (const float*)d_in[15];
    const float* kW   = (const float*)d_in[16];
    const float* kb_  = (const float*)d_in[17];
    const float* vW   = (const float*)d_in[18];
    const float* vb_  = (const float*)d_in[19];
    const float* oW   = (const float*)d_in[20];
    const float* ob   = (const float*)d_in[21];
    const float* clsW = (const float*)d_in[22];
    const float* clsb = (const float*)d_in[23];

    float *px, *ph0, *phl, *pxg, *pS, *pxyz0, *pxyz1, *pxs, *pys, *pzs, *ppart, *pqkvb;
    hf *pxh, *pxl, *pfeath, *pfeatl, *psuph, *psupl, *phmsh, *phmsl;
    hf *pqh, *pql, *pkh, *pvth, *psh, *psl;
    hf *pfcWth, *pgatWth, *pgcWth, *pqkvWth, *poWth;
    cudaGetSymbolAddress((void**)&px,    g_x);
    cudaGetSymbolAddress((void**)&ph0,   g_h0);
    cudaGetSymbolAddress((void**)&phl,   g_hl_);
    cudaGetSymbolAddress((void**)&pxg,   g_xg);
    cudaGetSymbolAddress((void**)&pS,    g_S);
    cudaGetSymbolAddress((void**)&pxyz0, g_xyz0);
    cudaGetSymbolAddress((void**)&pxyz1, g_xyz1);
    cudaGetSymbolAddress((void**)&pxs,   g_xs_);
    cudaGetSymbolAddress((void**)&pys,   g_ys_);
    cudaGetSymbolAddress((void**)&pzs,   g_zs_);
    cudaGetSymbolAddress((void**)&ppart, g_part);
    cudaGetSymbolAddress((void**)&pqkvb, g_qkvb);
    cudaGetSymbolAddress((void**)&pxh,   g_xh);
    cudaGetSymbolAddress((void**)&pxl,   g_xl);
    cudaGetSymbolAddress((void**)&pfeath,g_feath);
    cudaGetSymbolAddress((void**)&pfeatl,g_featl);
    cudaGetSymbolAddress((void**)&psuph, g_suph);
    cudaGetSymbolAddress((void**)&psupl, g_supl);
    cudaGetSymbolAddress((void**)&phmsh, g_hmsh);
    cudaGetSymbolAddress((void**)&phmsl, g_hmsl);
    cudaGetSymbolAddress((void**)&pqh,   g_qh);
    cudaGetSymbolAddress((void**)&pql,   g_ql);
    cudaGetSymbolAddress((void**)&pkh,   g_kh);
    cudaGetSymbolAddress((void**)&pvth,  g_vth);
    cudaGetSymbolAddress((void**)&psh,   g_sh);
    cudaGetSymbolAddress((void**)&psl,   g_sl);
    cudaGetSymbolAddress((void**)&pfcWth,  g_fcWth);
    cudaGetSymbolAddress((void**)&pgatWth, g_gatWth);
    cudaGetSymbolAddress((void**)&pgcWth,  g_gcWth);
    cudaGetSymbolAddress((void**)&pqkvWth, g_qkvWth);
    cudaGetSymbolAddress((void**)&poWth,   g_oWth);

    detect_mask_mode<<<1, 1>>>((const unsigned int*)dmask);

    wsplit<<<(FEAT_*HID_)/256, 256>>>(fcW, pfcWth, FEAT_, HID_, FEAT_*HID_);
    wsplit<<<(4*HID_*HID_)/256, 256>>>(gatW, pgatWth, HID_, HID_, HID_*HID_);
    wsplit<<<(4*2*HID_*HID_)/256, 256>>>(gcW, pgcWth, 2*HID_, HID_, 2*HID_*HID_);
    wsplit<<<(4*HID_*HID_)/256, 256>>>(oW, poWth, HID_, HID_, HID_*HID_);
    wsplit_ro<<<(4*HID_*HID_)/256, 256>>>(qW, pqkvWth, 0);
    wsplit_ro<<<(4*HID_*HID_)/256, 256>>>(kW, pqkvWth, 256);
    wsplit_ro<<<(4*HID_*HID_)/256, 256>>>(vW, pqkvWth, 512);
    qkvbias<<<12, 256>>>(qb_, kb_, vb_, pqkvb);
    split_hf<<<(N_*FEAT_/4)/256, 256>>>(feat, pfeath, pfeatl);

    gemm_tc64<<<dim3(HID_/64, N_/64), 256>>>(pfeath, pfeatl, pfcWth, FEAT_, HID_,
                                             fcb, 1, 1.0f, nullptr,0.f, nullptr,0.f, nullptr,0.f,
                                             px, ph0, pxh, pxl);

    zero_cnt<<<N_/256, 256>>>();
    count_edges<<<E_/256, 256>>>(dst);
    scan4096<<<1, 1024>>>();
    scatter_edges<<<E_/256, 256>>>(src, dst);

    const float ALPHA = 0.1f, LAMDA = 0.5f;
    for (int l = 0; l < 4; l++) {
        gemm_tc64<<<dim3(HID_/64, N_/64), 256>>>(pxh, pxl, pgatWth + (size_t)l*HID_*HID_,
                                                 HID_, HID_,
                                                 nullptr, 0, 1.0f, nullptr,0.f, nullptr,0.f, nullptr,0.f,
                                                 phl, nullptr, nullptr, nullptr);
        compute_elr<<<(N_*4)/256, 256>>>(phl, al + l*4*64, ar + l*4*64);
        gat_aggregate<<<N_/8, 256>>>(phl, pxg);
        pack_support<<<(N_*512)/256, 256>>>(pxg, ph0, psuph, psupl);
        float theta = fminf(1.0f, logf(LAMDA / (float)(l + 1) + 1.0f));
        gemm_tc64<<<dim3(HID_/64, N_/64), 256>>>(psuph, psupl, pgcWth + (size_t)l*2*HID_*HID_,
                                                 2*HID_, HID_,
                                                 nullptr, 0, theta,
                                                 pxg, (1.0f-theta)*(1.0f-ALPHA),
                                                 ph0, (1.0f-theta)*ALPHA,
                                                 px,  1.0f,
                                                 px, nullptr, pxh, pxl);
    }

    yhat_k<<<N_/256, 256>>>(px, cgW, cgb);

    const float* xyz_cur = xyz_in;
    float* xyz_buf[2] = { pxyz0, pxyz1 };
    for (int l = 0; l < 4; l++) {
        qkv_tc<<<dim3(768/64, N_/128), 256>>>(pxh, pxl,
                                              pqkvWth + (size_t)l*768*HID_,
                                              pqkvb + l*768,
                                              pqh, pql, pkh, pvth);
        scores_mma<<<dim3(N_/128, N_/128), 256>>>(pqh, pql, pkh,
                                                  xyz_cur, dmask, bmask, pS);
        xyz2soa<<<N_/256, 256>>>(xyz_cur, pxs, pys, pzs);
        softmax_xyz<<<N_, 256>>>(pS, psh, psl, pxs, pys, pzs, xyz_buf[l & 1]);
        attnv_mma<<<dim3(HID_/128, N_/128, KZ_), 256>>>(psh, psl, pvth, ppart);
        combine_parts<<<(N_*HID_/4)/256, 256>>>(ppart, phmsh, phmsl);
        gemm_tc64<<<dim3(HID_/64, N_/64), 256>>>(phmsh, phmsl, poWth + (size_t)l*HID_*HID_,
                                                 HID_, HID_,
                                                 ob + l*HID_, 0, 1.0f,
                                                 px, 1.0f, nullptr,0.f, nullptr,0.f,
                                                 px, nullptr, pxh, pxl);
        xyz_cur = xyz_buf[l & 1];
    }

    cls_k<<<N_/256, 256>>>(px, clsW, clsb, (float*)d_out);
}

// round 13
// speedup vs baseline: 2.0780x; 1.1162x over previous
#include <cuda_runtime.h>
#include <cuda_fp16.h>
#include <math.h>
#include <stdint.h>

#define N_    4096
#define E_    131072
#define FEAT_ 64
#define HID_  256
#define NEG_  (-1e9f)
#define KZ_   4

typedef __half hf;

// ---------------- scratch ----------------
__device__ float g_h0 [N_*HID_];
__device__ float g_x  [N_*HID_];
__device__ float g_hl_[N_*HID_];
__device__ float g_xg [N_*HID_];
__device__ float g_part[(size_t)KZ_*N_*HID_];
__device__ float g_S  [(size_t)N_*N_];
__device__ hf g_xh[N_*HID_], g_xl[N_*HID_];
__device__ hf g_feath[N_*FEAT_], g_featl[N_*FEAT_];
__device__ hf g_suph[N_*2*HID_], g_supl[N_*2*HID_];
__device__ hf g_hmsh[N_*HID_], g_hmsl[N_*HID_];
__device__ hf g_qh[N_*HID_], g_ql[N_*HID_];
__device__ hf g_kh[N_*HID_];
__device__ hf g_vth[HID_*N_];
__device__ hf g_sh[(size_t)N_*N_];
__device__ hf g_fcWth[HID_*FEAT_];
__device__ hf g_gatWth[4*HID_*HID_];
__device__ hf g_gcWth[4*HID_*2*HID_];
__device__ hf g_qkvWth[4*768*HID_];
__device__ float g_qkvb[4*768];
__device__ hf g_oWth[4*HID_*HID_];
__device__ float g_el [N_*4];
__device__ float g_er [N_*4];
__device__ float g_y  [N_];
__device__ float g_xyz0[N_*3];
__device__ float g_xyz1[N_*3];
__device__ float g_xs_[N_], g_ys_[N_], g_zs_[N_];
__device__ int   g_cnt[N_];
__device__ int   g_rowptr[N_+1];
__device__ int   g_cur[N_];
__device__ int   g_psrc[E_];
__device__ int   g_maskmode;

// ---------------- helpers ----------------
__device__ __forceinline__ uint32_t smem_u32(const void* p) {
    uint32_t a;
    asm("{ .reg .u64 t; cvta.to.shared.u64 t, %1; cvt.u32.u64 %0, t; }" : "=r"(a) : "l"(p));
    return a;
}
#define LDMX4(r, a) \
    asm volatile("ldmatrix.sync.aligned.m8n8.x4.shared.b16 {%0,%1,%2,%3}, [%4];" \
        : "=r"((r)[0]), "=r"((r)[1]), "=r"((r)[2]), "=r"((r)[3]) : "r"(a))
#define MMA16816(c, a, b0, b1) \
    asm volatile("mma.sync.aligned.m16n8k16.row.col.f32.f16.f16.f32 " \
        "{%0,%1,%2,%3}, {%4,%5,%6,%7}, {%8,%9}, {%0,%1,%2,%3};" \
        : "+f"((c)[0]), "+f"((c)[1]), "+f"((c)[2]), "+f"((c)[3]) \
        : "r"((a)[0]), "r"((a)[1]), "r"((a)[2]), "r"((a)[3]), "r"(b0), "r"(b1))

__device__ __forceinline__ void split1h(float v, hf& h, hf& l) {
    h = __float2half_rn(v);
    l = __float2half_rn(v - __half2float(h));
}

__device__ __forceinline__ float fast_exp(float x) {
    float t = x * 1.4426950408889634f;
    t = fmaxf(t, -126.0f);
    float z = t + 12582912.0f;
    float n = z - 12582912.0f;
    float f = t - n;
    float p = 1.5404e-4f;
    p = fmaf(p, f, 1.33336e-3f);
    p = fmaf(p, f, 9.61813e-3f);
    p = fmaf(p, f, 5.550411e-2f);
    p = fmaf(p, f, 2.4022651e-1f);
    p = fmaf(p, f, 6.9314718e-1f);
    p = fmaf(p, f, 1.0f);
    int ni = __float_as_int(z) - 0x4B400000;
    float sc = __int_as_float((ni + 127) << 23);
    return p * sc;
}

__global__ void detect_mask_mode(const unsigned int* __restrict__ m) {
    bool allbin = true, anyfloat = false;
    for (int i = 0; i < 1024; i++) {
        unsigned int w = m[i];
        if (w == 0x3f800000u) anyfloat = true;
        if (w > 1u) allbin = false;
    }
    g_maskmode = anyfloat ? 2 : (allbin ? 1 : 0);
}
__device__ __forceinline__ bool mask_at(const void* p, size_t i, int mode) {
    if (mode == 0) return ((const unsigned char*)p)[i] != 0;
    if (mode == 1) return ((const int*)p)[i] != 0;
    return ((const float*)p)[i] != 0.0f;
}

__global__ void split_hf(const float* __restrict__ X, hf* __restrict__ Xh, hf* __restrict__ Xl)
{
    int i = blockIdx.x * blockDim.x + threadIdx.x;
    float4 x = *(const float4*)&X[(size_t)i*4];
    float xv[4] = {x.x, x.y, x.z, x.w};
    __align__(8) hf h[4], l[4];
#pragma unroll
    for (int e = 0; e < 4; e++) split1h(xv[e], h[e], l[e]);
    *(uint2*)&Xh[(size_t)i*4] = *(uint2*)h;
    *(uint2*)&Xl[(size_t)i*4] = *(uint2*)l;
}

__global__ void wsplit(const float* __restrict__ W, hf* __restrict__ Wth,
                       int K, int N, int KN)
{
    int idx = blockIdx.x * 256 + threadIdx.x;
    int mat = idx / KN;
    int rem = idx - mat * KN;
    int k = rem / N;
    int n = rem - k * N;
    Wth[mat * KN + n * K + k] = __float2half_rn(W[idx]);
}

__global__ void wsplit_ro(const float* __restrict__ W, hf* __restrict__ Wth, int ro)
{
    int idx = blockIdx.x * 256 + threadIdx.x;
    int l = idx >> 16;
    int rem = idx & 65535;
    int k = rem >> 8, n = rem & 255;
    Wth[(size_t)l * 768 * HID_ + (size_t)(ro + n) * HID_ + k] = __float2half_rn(W[idx]);
}

__global__ void qkvbias(const float* __restrict__ qb, const float* __restrict__ kb,
                        const float* __restrict__ vb, float* __restrict__ out)
{
    int idx = blockIdx.x * 256 + threadIdx.x;
    if (idx >= 4*768) return;
    int l = idx / 768, c = idx % 768;
    int sect = c >> 8, cc = c & 255;
    out[idx] = (sect == 0) ? qb[l*256+cc] : (sect == 1) ? kb[l*256+cc] : vb[l*256+cc];
}

// ================= gemm_tc64: 64x64 tile fp16-mma, 2-pass (A split, B single) ===========
__global__ __launch_bounds__(256) void gemm_tc64(
    const hf* __restrict__ Ah, const hf* __restrict__ Al,
    const hf* __restrict__ Bh,
    int K, int Nc,
    const float* __restrict__ bias, int relu, float cacc,
    const float* __restrict__ X1, float c1,
    const float* __restrict__ X2, float c2,
    const float* __restrict__ X3, float c3,
    float* __restrict__ C, float* __restrict__ C2,
    hf* __restrict__ Ch, hf* __restrict__ Cl)
{
    __shared__ __align__(16) char Ash[2][64*80];
    __shared__ __align__(16) char Bsh[2][64*80];
    const int t = threadIdx.x, lane = t & 31, wid = t >> 5;
    const int wr32 = (wid >> 2) * 32, wc16 = (wid & 3) * 16;
    const int g = lane >> 2, tg = lane & 3;
    const int a_r = ((lane >> 3) & 1) * 8 + (lane & 7);
    const int a_c = (lane >> 4) * 16;
    const int b_r = ((lane >> 4) & 1) * 8 + (lane & 7);
    const int b_c = ((lane >> 3) & 1) * 16;
    const int m0 = blockIdx.y * 64, n0 = blockIdx.x * 64;
    const int lrow = t >> 2, lq = t & 3;

    uint32_t aS[2] = { smem_u32(Ash[0]), smem_u32(Ash[1]) };
    uint32_t bS[2] = { smem_u32(Bsh[0]), smem_u32(Bsh[1]) };
    float acc[2][2][4] = {};

    const hf* APs[2] = { Ah, Al };
    const int chunks = K >> 5;
    const int NC = 2 * chunks;

    uint4 va = *(const uint4*)(APs[0] + (size_t)(m0+lrow)*K + lq*8);
    uint4 vb = *(const uint4*)(Bh + (size_t)(n0+lrow)*K + lq*8);
    *(uint4*)(Ash[0] + lrow*80 + lq*16) = va;
    *(uint4*)(Bsh[0] + lrow*80 + lq*16) = vb;
    __syncthreads();

    int pn = 0, kn = 0;
    for (int c = 0; c < NC; c++) {
        const int buf = c & 1;
        const bool more = (c + 1 < NC);
        if (more) {
            kn++; if (kn == chunks) { kn = 0; pn++; }
            va = *(const uint4*)(APs[pn] + (size_t)(m0+lrow)*K + kn*32 + lq*8);
            vb = *(const uint4*)(Bh + (size_t)(n0+lrow)*K + kn*32 + lq*8);
        }
#pragma unroll
        for (int kk = 0; kk < 2; kk++) {
            uint32_t af[2][4], bfr[4];
#pragma unroll
            for (int mt = 0; mt < 2; mt++) {
                uint32_t ad = aS[buf] + (uint32_t)((wr32 + mt*16 + a_r)*80 + kk*32 + a_c);
                LDMX4(af[mt], ad);
            }
            {
                uint32_t bd = bS[buf] + (uint32_t)((wc16 + b_r)*80 + kk*32 + b_c);
                LDMX4(bfr, bd);
            }
#pragma unroll
            for (int mt = 0; mt < 2; mt++)
#pragma unroll
                for (int nt = 0; nt < 2; nt++)
                    MMA16816(acc[mt][nt], af[mt], bfr[nt*2], bfr[nt*2+1]);
        }
        if (more) {
            const int nb = buf ^ 1;
            *(uint4*)(Ash[nb] + lrow*80 + lq*16) = va;
            *(uint4*)(Bsh[nb] + lrow*80 + lq*16) = vb;
            __syncthreads();
        }
    }

#pragma unroll
    for (int mt = 0; mt < 2; mt++) {
#pragma unroll
        for (int h = 0; h < 2; h++) {
            const int m = m0 + wr32 + mt*16 + g + 8*h;
            const size_t rb = (size_t)m * Nc;
#pragma unroll
            for (int nt = 0; nt < 2; nt++) {
                const int n = n0 + wc16 + nt*8 + 2*tg;
                float2 r = { acc[mt][nt][h*2], acc[mt][nt][h*2+1] };
                r.x *= cacc; r.y *= cacc;
                if (bias) { r.x += bias[n]; r.y += bias[n+1]; }
                if (X1) { float2 q = *(const float2*)&X1[rb+n];
                          r.x = fmaf(c1,q.x,r.x); r.y = fmaf(c1,q.y,r.y); }
                if (X2) { float2 q = *(const float2*)&X2[rb+n];
                          r.x = fmaf(c2,q.x,r.x); r.y = fmaf(c2,q.y,r.y); }
                if (X3) { float2 q = *(const float2*)&X3[rb+n];
                          r.x = fmaf(c3,q.x,r.x); r.y = fmaf(c3,q.y,r.y); }
                if (relu) { r.x = fmaxf(r.x, 0.f); r.y = fmaxf(r.y, 0.f); }
                if (C)  *(float2*)&C[rb+n]  = r;
                if (C2) *(float2*)&C2[rb+n] = r;
                if (Ch) {
                    __align__(4) hf h2[2], l2[2];
                    split1h(r.x, h2[0], l2[0]); split1h(r.y, h2[1], l2[1]);
                    *(uint32_t*)&Ch[rb+n] = *(uint32_t*)h2;
                    *(uint32_t*)&Cl[rb+n] = *(uint32_t*)l2;
                }
            }
        }
    }
}

// ================= qkv_tc: fused QKV GEMM, tile 128x64, Nc=768 routed =================
__global__ __launch_bounds__(256) void qkv_tc(
    const hf* __restrict__ Ah, const hf* __restrict__ Al,
    const hf* __restrict__ Bh,
    const float* __restrict__ bias,
    hf* __restrict__ Qh, hf* __restrict__ Ql,
    hf* __restrict__ Kh, hf* __restrict__ Vth)
{
    __shared__ __align__(16) char Ash[2][128*80];
    __shared__ __align__(16) char Bsh[2][64*80];
    const int t = threadIdx.x, lane = t & 31, wid = t >> 5;
    const int wr32 = (wid >> 1) * 32, wc32 = (wid & 1) * 32;
    const int g = lane >> 2, tg = lane & 3;
    const int a_r = ((lane >> 3) & 1) * 8 + (lane & 7);
    const int a_c = (lane >> 4) * 16;
    const int b_r = ((lane >> 4) & 1) * 8 + (lane & 7);
    const int b_c = ((lane >> 3) & 1) * 16;
    const int m0 = blockIdx.y * 128, n0 = blockIdx.x * 64;
    const int K = HID_;

    uint32_t aS[2] = { smem_u32(Ash[0]), smem_u32(Ash[1]) };
    uint32_t bS[2] = { smem_u32(Bsh[0]), smem_u32(Bsh[1]) };
    float acc[2][4][4] = {};

    const hf* APs[2] = { Ah, Al };
    const int chunks = K >> 5;
    const int NC = 2 * chunks;

    uint4 va[2], vb;
#pragma unroll
    for (int i = 0; i < 2; i++) {
        int idx = t + i*256, row = idx >> 2, q = idx & 3;
        va[i] = *(const uint4*)(APs[0] + (size_t)(m0+row)*K + q*8);
    }
    { int row = t >> 2, q = t & 3;
      vb = *(const uint4*)(Bh + (size_t)(n0+row)*K + q*8); }
#pragma unroll
    for (int i = 0; i < 2; i++) {
        int idx = t + i*256, row = idx >> 2, q = idx & 3;
        *(uint4*)(Ash[0] + row*80 + q*16) = va[i];
    }
    { int row = t >> 2, q = t & 3;
      *(uint4*)(Bsh[0] + row*80 + q*16) = vb; }
    __syncthreads();

    int pn = 0, kn = 0;
    for (int c = 0; c < NC; c++) {
        const int buf = c & 1;
        const bool more = (c + 1 < NC);
        if (more) {
            kn++; if (kn == chunks) { kn = 0; pn++; }
#pragma unroll
            for (int i = 0; i < 2; i++) {
                int idx = t + i*256, row = idx >> 2, q = idx & 3;
                va[i] = *(const uint4*)(APs[pn] + (size_t)(m0+row)*K + kn*32 + q*8);
            }
            { int row = t >> 2, q = t & 3;
              vb = *(const uint4*)(Bh + (size_t)(n0+row)*K + kn*32 + q*8); }
        }
#pragma unroll
        for (int kk = 0; kk < 2; kk++) {
            uint32_t af[2][4], bfr[2][4];
#pragma unroll
            for (int mt = 0; mt < 2; mt++) {
                uint32_t ad = aS[buf] + (uint32_t)((wr32 + mt*16 + a_r)*80 + kk*32 + a_c);
                LDMX4(af[mt], ad);
            }
#pragma unroll
            for (int np = 0; np < 2; np++) {
                uint32_t bd = bS[buf] + (uint32_t)((wc32 + np*16 + b_r)*80 + kk*32 + b_c);
                LDMX4(bfr[np], bd);
            }
#pragma unroll
            for (int mt = 0; mt < 2; mt++)
#pragma unroll
                for (int nt = 0; nt < 4; nt++)
                    MMA16816(acc[mt][nt], af[mt], bfr[nt>>1][(nt&1)*2], bfr[nt>>1][(nt&1)*2+1]);
        }
        if (more) {
            const int nb = buf ^ 1;
#pragma unroll
            for (int i = 0; i < 2; i++) {
                int idx = t + i*256, row = idx >> 2, q = idx & 3;
                *(uint4*)(Ash[nb] + row*80 + q*16) = va[i];
            }
            { int row = t >> 2, q = t & 3;
              *(uint4*)(Bsh[nb] + row*80 + q*16) = vb; }
            __syncthreads();
        }
    }

#pragma unroll
    for (int mt = 0; mt < 2; mt++) {
#pragma unroll
        for (int h = 0; h < 2; h++) {
            const int m = m0 + wr32 + mt*16 + g + 8*h;
#pragma unroll
            for (int nt = 0; nt < 4; nt++) {
                const int n = n0 + wc32 + nt*8 + 2*tg;
                float2 r = { acc[mt][nt][h*2], acc[mt][nt][h*2+1] };
                r.x += bias[n]; r.y += bias[n+1];
                const int sect = n >> 8, cc = n & 255;
                if (sect == 0) {
                    __align__(4) hf hh[2], ll[2];
                    split1h(r.x, hh[0], ll[0]); split1h(r.y, hh[1], ll[1]);
                    *(uint32_t*)&Qh[(size_t)m*HID_ + cc] = *(uint32_t*)hh;
                    *(uint32_t*)&Ql[(size_t)m*HID_ + cc] = *(uint32_t*)ll;
                } else if (sect == 1) {
                    __align__(4) hf hh[2] = { __float2half_rn(r.x), __float2half_rn(r.y) };
                    *(uint32_t*)&Kh[(size_t)m*HID_ + cc] = *(uint32_t*)hh;
                } else {
                    Vth[(size_t)cc * N_ + m]     = __float2half_rn(r.x);
                    Vth[(size_t)(cc+1) * N_ + m] = __float2half_rn(r.y);
                }
            }
        }
    }
}

// ---- shared mma-core macro (128x128 kernels) ----
#define COMPUTE32(abase, bbase)                                                     \
    _Pragma("unroll")                                                               \
    for (int kk = 0; kk < 2; kk++) {                                                \
        uint32_t af[4][4], bfr[2][4];                                               \
        _Pragma("unroll")                                                           \
        for (int mt = 0; mt < 4; mt++) {                                            \
            uint32_t ad = (abase) + (uint32_t)((wr64 + mt*16 + a_r)*80 + kk*32 + a_c); \
            LDMX4(af[mt], ad);                                                      \
        }                                                                           \
        _Pragma("unroll")                                                           \
        for (int np = 0; np < 2; np++) {                                            \
            uint32_t bd = (bbase) + (uint32_t)((wc32 + np*16 + b_r)*80 + kk*32 + b_c); \
            LDMX4(bfr[np], bd);                                                     \
        }                                                                           \
        _Pragma("unroll")                                                           \
        for (int mt = 0; mt < 4; mt++)                                              \
            _Pragma("unroll")                                                       \
            for (int nt = 0; nt < 4; nt++)                                          \
                MMA16816(acc[mt][nt], af[mt], bfr[nt>>1][(nt&1)*2], bfr[nt>>1][(nt&1)*2+1]); \
    }

// ================= scores via fp16 mma, 2-pass (q split, k single) =================
__global__ __launch_bounds__(256) void scores_mma(
    const hf* __restrict__ qh, const hf* __restrict__ ql,
    const hf* __restrict__ kh,
    const float* __restrict__ xyz,
    const void* __restrict__ dmask, const void* __restrict__ bmask,
    float* __restrict__ S)
{
    __shared__ __align__(16) char Ash[2][128*80];
    __shared__ __align__(16) char Bsh[2][128*80];
    __shared__ float gix[128*3], gisq[128], giy[128];
    __shared__ float gjx[128*3], gjsq[128], gjy[128];
    const int t = threadIdx.x, lane = t & 31, wid = t >> 5;
    const int wr64 = (wid >> 2) * 64, wc32 = (wid & 3) * 32;
    const int g = lane >> 2, tg = lane & 3;
    const int a_r = ((lane >> 3) & 1) * 8 + (lane & 7);
    const int a_c = (lane >> 4) * 16;
    const int b_r = ((lane >> 4) & 1) * 8 + (lane & 7);
    const int b_c = ((lane >> 3) & 1) * 16;
    const int i0 = blockIdx.y * 128, j0 = blockIdx.x * 128;
    const int lrow = t >> 2, lq = t & 3;

    if (t < 128) {
        float a = xyz[(i0+t)*3+0], b = xyz[(i0+t)*3+1], c = xyz[(i0+t)*3+2];
        gix[t*3+0]=a; gix[t*3+1]=b; gix[t*3+2]=c;
        gisq[t] = fmaf(c,c,fmaf(b,b,a*a));
        giy[t]  = g_y[i0+t];
    } else {
        int u = t - 128;
        float a = xyz[(j0+u)*3+0], b = xyz[(j0+u)*3+1], c = xyz[(j0+u)*3+2];
        gjx[u*3+0]=a; gjx[u*3+1]=b; gjx[u*3+2]=c;
        gjsq[u] = fmaf(c,c,fmaf(b,b,a*a));
        gjy[u]  = g_y[j0+u];
    }

    uint32_t aS[2] = { smem_u32(Ash[0]), smem_u32(Ash[1]) };
    uint32_t bS[2] = { smem_u32(Bsh[0]), smem_u32(Bsh[1]) };
    float acc[4][4][4] = {};

    const hf* APs[2] = { qh, ql };

    uint4 va[2], vb[2];
#pragma unroll
    for (int r = 0; r < 2; r++) {
        int row = lrow + r*64;
        va[r] = *(const uint4*)(APs[0] + (size_t)(i0+row)*HID_ + lq*8);
        vb[r] = *(const uint4*)(kh + (size_t)(j0+row)*HID_ + lq*8);
    }
#pragma unroll
    for (int r = 0; r < 2; r++) {
        int row = lrow + r*64;
        *(uint4*)(Ash[0] + row*80 + lq*16) = va[r];
        *(uint4*)(Bsh[0] + row*80 + lq*16) = vb[r];
    }
    __syncthreads();

    const int NC = 16;
    for (int c = 0; c < NC; c++) {
        const int buf = c & 1;
        if (c + 1 < NC) {
            const int p = (c+1) >> 3, kc = (c+1) & 7;
            const hf* A = APs[p];
#pragma unroll
            for (int r = 0; r < 2; r++) {
                int row = lrow + r*64;
                va[r] = *(const uint4*)(A + (size_t)(i0+row)*HID_ + kc*32 + lq*8);
                vb[r] = *(const uint4*)(kh + (size_t)(j0+row)*HID_ + kc*32 + lq*8);
            }
        }
        COMPUTE32(aS[buf], bS[buf]);
        if (c + 1 < NC) {
            const int nb = buf ^ 1;
#pragma unroll
            for (int r = 0; r < 2; r++) {
                int row = lrow + r*64;
                *(uint4*)(Ash[nb] + row*80 + lq*16) = va[r];
                *(uint4*)(Bsh[nb] + row*80 + lq*16) = vb[r];
            }
            __syncthreads();
        }
    }

    const int mode = g_maskmode;
#pragma unroll
    for (int mt = 0; mt < 4; mt++) {
#pragma unroll
        for (int h = 0; h < 2; h++) {
            const int li = wr64 + mt*16 + g + 8*h;
            const int gi = i0 + li;
            const float xa = gix[li*3], xbv = gix[li*3+1], xc = gix[li*3+2];
            const float sqa = gisq[li], ya = giy[li];
            const size_t rb = (size_t)gi * N_;
#pragma unroll
            for (int nt = 0; nt < 4; nt++) {
                const int lj0 = wc32 + nt*8 + 2*tg;
                float2 r;
#pragma unroll
                for (int e = 0; e < 2; e++) {
                    const int lj = lj0 + e;
                    const size_t gidx = rb + j0 + lj;
                    float dot = fmaf(xc, gjx[lj*3+2], fmaf(xbv, gjx[lj*3+1], xa * gjx[lj*3]));
                    float dist2 = (sqa + gjsq[lj]) - 2.0f * dot;
                    bool ok = mask_at(dmask, gidx, mode) && mask_at(bmask, gidx, mode) && (dist2 <= 100.0f);
                    float av = acc[mt][nt][h*2 + e];
                    ((float*)&r)[e] = ok ? (av * 0.0625f - fabsf(ya - gjy[lj])) : NEG_;
                }
                *(float2*)&S[rb + j0 + lj0] = r;
            }
        }
    }
}

// ================= attn@V via fp16 mma, single-pass (Sh only, V single), split-K z ======
__global__ __launch_bounds__(256) void attnv_mma(
    const hf* __restrict__ Sh,
    const hf* __restrict__ Vth,
    float* __restrict__ Cpart)
{
    __shared__ __align__(16) char Ash[2][128*80];
    __shared__ __align__(16) char Bsh[2][128*80];
    const int t = threadIdx.x, lane = t & 31, wid = t >> 5;
    const int wr64 = (wid >> 2) * 64, wc32 = (wid & 3) * 32;
    const int g = lane >> 2, tg = lane & 3;
    const int a_r = ((lane >> 3) & 1) * 8 + (lane & 7);
    const int a_c = (lane >> 4) * 16;
    const int b_r = ((lane >> 4) & 1) * 8 + (lane & 7);
    const int b_c = ((lane >> 3) & 1) * 16;
    const int m0 = blockIdx.y * 128, n0 = blockIdx.x * 128;
    const int kbase = blockIdx.z * (N_ / KZ_);
    const int lrow = t >> 2, lq = t & 3;

    uint32_t aS[2] = { smem_u32(Ash[0]), smem_u32(Ash[1]) };
    uint32_t bS[2] = { smem_u32(Bsh[0]), smem_u32(Bsh[1]) };
    float acc[4][4][4] = {};

    const int NC = (N_ / KZ_) / 32;     // 32 chunks, single pass

    uint4 va[2], vb[2];
#pragma unroll
    for (int r = 0; r < 2; r++) {
        int row = lrow + r*64;
        va[r] = *(const uint4*)(Sh + (size_t)(m0+row)*N_ + kbase + lq*8);
        vb[r] = *(const uint4*)(Vth + (size_t)(n0+row)*N_ + kbase + lq*8);
    }
#pragma unroll
    for (int r = 0; r < 2; r++) {
        int row = lrow + r*64;
        *(uint4*)(Ash[0] + row*80 + lq*16) = va[r];
        *(uint4*)(Bsh[0] + row*80 + lq*16) = vb[r];
    }
    __syncthreads();

    for (int c = 0; c < NC; c++) {
        const int buf = c & 1;
        if (c + 1 < NC) {
            const int kc = c + 1;
#pragma unroll
            for (int r = 0; r < 2; r++) {
                int row = lrow + r*64;
                va[r] = *(const uint4*)(Sh + (size_t)(m0+row)*N_ + kbase + kc*32 + lq*8);
                vb[r] = *(const uint4*)(Vth + (size_t)(n0+row)*N_ + kbase + kc*32 + lq*8);
            }
        }
        COMPUTE32(aS[buf], bS[buf]);
        if (c + 1 < NC) {
            const int nb = buf ^ 1;
#pragma unroll
            for (int r = 0; r < 2; r++) {
                int row = lrow + r*64;
                *(uint4*)(Ash[nb] + row*80 + lq*16) = va[r];
                *(uint4*)(Bsh[nb] + row*80 + lq*16) = vb[r];
            }
            __syncthreads();
        }
    }

    float* Cz = Cpart + (size_t)blockIdx.z * N_ * HID_;
#pragma unroll
    for (int mt = 0; mt < 4; mt++) {
#pragma unroll
        for (int h = 0; h < 2; h++) {
            const int m = m0 + wr64 + mt*16 + g + 8*h;
            const size_t rb = (size_t)m * HID_;
#pragma unroll
            for (int nt = 0; nt < 4; nt++) {
                const int n = n0 + wc32 + nt*8 + 2*tg;
                float2 r = { acc[mt][nt][h*2], acc[mt][nt][h*2 + 1] };
                *(float2*)&Cz[rb + n] = r;
            }
        }
    }
}

__global__ void combine_parts(const float* __restrict__ P,
                              hf* __restrict__ Hh, hf* __restrict__ Hl)
{
    int i = blockIdx.x * blockDim.x + threadIdx.x;
    const size_t n = (size_t)N_ * HID_;
    float4 a = *(const float4*)&P[(size_t)i*4];
    float4 b = *(const float4*)&P[n + (size_t)i*4];
    float4 c = *(const float4*)&P[2*n + (size_t)i*4];
    float4 d = *(const float4*)&P[3*n + (size_t)i*4];
    float rv[4] = { a.x+b.x+c.x+d.x, a.y+b.y+c.y+d.y, a.z+b.z+c.z+d.z, a.w+b.w+c.w+d.w };
    __align__(8) hf hh[4], ll[4];
#pragma unroll
    for (int e = 0; e < 4; e++) split1h(rv[e], hh[e], ll[e]);
    *(uint2*)&Hh[(size_t)i*4] = *(uint2*)hh;
    *(uint2*)&Hl[(size_t)i*4] = *(uint2*)ll;
}

// ---------------- softmax + attn@xyz + fp16 store of attn ----------------
__global__ void softmax_xyz(const float* __restrict__ S,
                            hf* __restrict__ Sh,
                            const float* __restrict__ xs, const float* __restrict__ ys,
                            const float* __restrict__ zs, float* __restrict__ out)
{
    __shared__ float r0[256], r1[256], r2[256];
    const int row = blockIdx.x, t = threadIdx.x;
    const float* p = S + (size_t)row * N_;
    float4 v[4];
    float mx = -1e30f;
#pragma unroll
    for (int c = 0; c < 4; c++) {
        v[c] = *(const float4*)&p[c*1024 + t*4];
        mx = fmaxf(mx, fmaxf(fmaxf(v[c].x, v[c].y), fmaxf(v[c].z, v[c].w)));
    }
    r0[t] = mx; __syncthreads();
    for (int s = 128; s > 0; s >>= 1) { if (t < s) r0[t] = fmaxf(r0[t], r0[t+s]); __syncthreads(); }
    mx = r0[0]; __syncthreads();
    float sum = 0.0f;
#pragma unroll
    for (int c = 0; c < 4; c++) {
        v[c].x = fast_exp(v[c].x - mx); v[c].y = fast_exp(v[c].y - mx);
        v[c].z = fast_exp(v[c].z - mx); v[c].w = fast_exp(v[c].w - mx);
        sum += v[c].x + v[c].y + v[c].z + v[c].w;
    }
    r0[t] = sum; __syncthreads();
    for (int s = 128; s > 0; s >>= 1) { if (t < s) r0[t] += r0[t+s]; __syncthreads(); }
    const float inv = 1.0f / r0[0];
    __syncthreads();
    float a0 = 0.f, a1 = 0.f, a2 = 0.f;
#pragma unroll
    for (int c = 0; c < 4; c++) {
        v[c].x *= inv; v[c].y *= inv; v[c].z *= inv; v[c].w *= inv;
        float vv[4] = { v[c].x, v[c].y, v[c].z, v[c].w };
        __align__(8) hf vh[4];
#pragma unroll
        for (int e = 0; e < 4; e++) vh[e] = __float2half_rn(vv[e]);
        const size_t off = (size_t)row * N_ + c*1024 + t*4;
        *(uint2*)&Sh[off] = *(uint2*)vh;
        const int j = c*1024 + t*4;
        a0 = fmaf(v[c].x, xs[j], fmaf(v[c].y, xs[j+1], fmaf(v[c].z, xs[j+2], fmaf(v[c].w, xs[j+3], a0))));
        a1 = fmaf(v[c].x, ys[j], fmaf(v[c].y, ys[j+1], fmaf(v[c].z, ys[j+2], fmaf(v[c].w, ys[j+3], a1))));
        a2 = fmaf(v[c].x, zs[j], fmaf(v[c].y, zs[j+1], fmaf(v[c].z, zs[j+2], fmaf(v[c].w, zs[j+3], a2))));
    }
    r0[t]=a0; r1[t]=a1; r2[t]=a2; __syncthreads();
    for (int s = 128; s > 0; s >>= 1) {
        if (t < s) { r0[t]+=r0[t+s]; r1[t]+=r1[t+s]; r2[t]+=r2[t+s]; }
        __syncthreads();
    }
    if (t == 0) { out[row*3+0]=r0[0]; out[row*3+1]=r1[0]; out[row*3+2]=r2[0]; }
}

__global__ void xyz2soa(const float* __restrict__ xyz, float* __restrict__ xs,
                        float* __restrict__ ys, float* __restrict__ zs)
{
    int i = blockIdx.x * blockDim.x + threadIdx.x;
    if (i < N_) { xs[i] = xyz[3*i]; ys[i] = xyz[3*i+1]; zs[i] = xyz[3*i+2]; }
}

// ---------------- GAT pieces ----------------
__global__ void compute_elr(const float* __restrict__ hl, const float* __restrict__ al,
                            const float* __restrict__ ar)
{
    int idx = blockIdx.x * blockDim.x + threadIdx.x;
    if (idx >= N_*4) return;
    int node = idx >> 2, h = idx & 3;
    const float* row = hl + (size_t)node * HID_ + h * 64;
    float sl = 0.f, sr = 0.f;
#pragma unroll 8
    for (int d = 0; d < 64; d++) {
        float v = row[d];
        sl = fmaf(v, al[h*64+d], sl);
        sr = fmaf(v, ar[h*64+d], sr);
    }
    g_el[idx] = sl; g_er[idx] = sr;
}

__global__ void zero_cnt() { int i = blockIdx.x*blockDim.x + threadIdx.x; if (i < N_) g_cnt[i] = 0; }
__global__ void count_edges(const int* __restrict__ dst) {
    int e = blockIdx.x*blockDim.x + threadIdx.x; if (e < E_) atomicAdd(&g_cnt[dst[e]], 1);
}
__global__ void scan4096() {
    __shared__ int part[1024];
    int t = threadIdx.x, base = t * 4;
    int a0 = g_cnt[base], a1 = g_cnt[base+1], a2 = g_cnt[base+2], a3 = g_cnt[base+3];
    int s = a0 + a1 + a2 + a3;
    part[t] = s; __syncthreads();
    for (int off = 1; off < 1024; off <<= 1) {
        int v = (t >= off) ? part[t-off] : 0;
        __syncthreads();
        part[t] += v;
        __syncthreads();
    }
    int excl = part[t] - s;
    g_rowptr[base+0] = excl;           g_cur[base+0] = excl;
    g_rowptr[base+1] = excl+a0;        g_cur[base+1] = excl+a0;
    g_rowptr[base+2] = excl+a0+a1;     g_cur[base+2] = excl+a0+a1;
    g_rowptr[base+3] = excl+a0+a1+a2;  g_cur[base+3] = excl+a0+a1+a2;
    if (t == 1023) g_rowptr[4096] = part[1023];
}
__global__ void scatter_edges(const int* __restrict__ src, const int* __restrict__ dst) {
    int e = blockIdx.x*blockDim.x + threadIdx.x;
    if (e < E_) { int p = atomicAdd(&g_cur[dst[e]], 1); g_psrc[p] = src[e]; }
}

__global__ void gat_aggregate(const float* __restrict__ hl, float* __restrict__ xg)
{
    const int node = (blockIdx.x * blockDim.x + threadIdx.x) >> 5;
    const int lane = threadIdx.x & 31;
    if (node >= N_) return;
    const int beg = g_rowptr[node], end = g_rowptr[node+1];
    const float er_i = (lane < 4) ? g_er[node*4 + lane] : 0.f;
    float m = -1e30f;
    for (int p = beg; p < end; p++) {
        int s = g_psrc[p];
        if (lane < 4) {
            float v = g_el[s*4 + lane] + er_i;
            float e = (v > 0.f) ? v : 0.2f * v;
            m = fmaxf(m, e);
        }
    }
    float m0 = __shfl_sync(0xffffffffu, m, 0), m1 = __shfl_sync(0xffffffffu, m, 1);
    float m2 = __shfl_sync(0xffffffffu, m, 2), m3 = __shfl_sync(0xffffffffu, m, 3);
    const int myh = lane >> 3;
    float4 acc0 = {0,0,0,0}, acc1 = {0,0,0,0};
    float z = 0.f;
    for (int p = beg; p < end; p++) {
        int s = g_psrc[p];
        float w = 0.f;
        if (lane < 4) {
            float v = g_el[s*4 + lane] + er_i;
            float e = (v > 0.f) ? v : 0.2f * v;
            float mm = (lane==0)?m0:(lane==1)?m1:(lane==2)?m2:m3;
            w = fast_exp(e - mm);
            z += w;
        }
        float w0 = __shfl_sync(0xffffffffu, w, 0), w1 = __shfl_sync(0xffffffffu, w, 1);
        float w2 = __shfl_sync(0xffffffffu, w, 2), w3 = __shfl_sync(0xffffffffu, w, 3);
        float wm = (myh==0)?w0:(myh==1)?w1:(myh==2)?w2:w3;
        const float4* hp = (const float4*)(hl + (size_t)s * HID_ + lane * 8);
        float4 hv0 = hp[0], hv1 = hp[1];
        acc0.x=fmaf(wm,hv0.x,acc0.x); acc0.y=fmaf(wm,hv0.y,acc0.y);
        acc0.z=fmaf(wm,hv0.z,acc0.z); acc0.w=fmaf(wm,hv0.w,acc0.w);
        acc1.x=fmaf(wm,hv1.x,acc1.x); acc1.y=fmaf(wm,hv1.y,acc1.y);
        acc1.z=fmaf(wm,hv1.z,acc1.z); acc1.w=fmaf(wm,hv1.w,acc1.w);
    }
    float z0 = __shfl_sync(0xffffffffu, z, 0), z1 = __shfl_sync(0xffffffffu, z, 1);
    float z2 = __shfl_sync(0xffffffffu, z, 2), z3 = __shfl_sync(0xffffffffu, z, 3);
    float zm = (myh==0)?z0:(myh==1)?z1:(myh==2)?z2:z3;
    float inv = 1.0f / (zm + 1e-9f);
    acc0.x*=inv; acc0.y*=inv; acc0.z*=inv; acc0.w*=inv;
    acc1.x*=inv; acc1.y*=inv; acc1.z*=inv; acc1.w*=inv;
    float4* op = (float4*)(xg + (size_t)node * HID_ + lane * 8);
    op[0] = acc0; op[1] = acc1;
}

__global__ void pack_support(const float* __restrict__ xg, const float* __restrict__ h0,
                             hf* __restrict__ suph, hf* __restrict__ supl)
{
    int i = blockIdx.x * blockDim.x + threadIdx.x;
    if (i >= N_ * 512) return;
    int r = i >> 9, c = i & 511;
    float v = (c < 256) ? xg[(size_t)r*256 + c] : h0[(size_t)r*256 + (c-256)];
    hf h, l; split1h(v, h, l);
    suph[i] = h; supl[i] = l;
}

__global__ void yhat_k(const float* __restrict__ x, const float* __restrict__ W,
                       const float* __restrict__ b)
{
    int i = blockIdx.x * blockDim.x + threadIdx.x;
    if (i >= N_) return;
    const float* r = x + (size_t)i * HID_;
    float l0 = b[0], l1 = b[1];
#pragma unroll 8
    for (int d = 0; d < HID_; d++) {
        float v = r[d];
        l0 = fmaf(v, W[2*d+0], l0);
        l1 = fmaf(v, W[2*d+1], l1);
    }
    g_y[i] = 1.0f / (1.0f + expf(l0 - l1));
}

__global__ void cls_k(const float* __restrict__ x, const float* __restrict__ W,
                      const float* __restrict__ b, float* __restrict__ out)
{
    int i = blockIdx.x * blockDim.x + threadIdx.x;
    if (i >= N_) return;
    const float* r = x + (size_t)i * HID_;
    float l0 = b[0], l1 = b[1];
#pragma unroll 8
    for (int d = 0; d < HID_; d++) {
        float v = r[d];
        l0 = fmaf(v, W[2*d+0], l0);
        l1 = fmaf(v, W[2*d+1], l1);
    }
    out[2*i+0] = l0;
    out[2*i+1] = l1;
}

// ---------------- host orchestration ----------------
extern "C" void kernel_launch(void* const* d_in, const int* in_sizes, int n_in,
                              void* d_out, int out_size)
{
    const float* feat   = (const float*)d_in[0];
    const float* xyz_in = (const float*)d_in[1];
    const int*   src    = (const int*)  d_in[2];
    const int*   dst    = (const int*)  d_in[3];
    const void*  dmask  = d_in[4];
    const void*  bmask  = d_in[5];
    const float* fcW  = (const float*)d_in[6];
    const float* fcb  = (const float*)d_in[7];
    const float* gatW = (const float*)d_in[8];
    const float* al   = (const float*)d_in[9];
    const float* ar   = (const float*)d_in[10];
    const float* gcW  = (const float*)d_in[11];
    const float* cgW  = (const float*)d_in[12];
    const float* cgb  = (const float*)d_in[13];
    const float* qW   = (const float*)d_in[14];
    const float* qb_  = (const float*)d_in[15];
    const float* kW   = (const float*)d_in[16];
    const float* kb_  = (const float*)d_in[17];
    const float* vW   = (const float*)d_in[18];
    const float* vb_  = (const float*)d_in[19];
    const float* oW   = (const float*)d_in[20];
    const float* ob   = (const float*)d_in[21];
    const float* clsW = (const float*)d_in[22];
    const float* clsb = (const float*)d_in[23];

    float *px, *ph0, *phl, *pxg, *pS, *pxyz0, *pxyz1, *pxs, *pys, *pzs, *ppart, *pqkvb;
    hf *pxh, *pxl, *pfeath, *pfeatl, *psuph, *psupl, *phmsh, *phmsl;
    hf *pqh, *pql, *pkh, *pvth, *psh;
    hf *pfcWth, *pgatWth, *pgcWth, *pqkvWth, *poWth;
    cudaGetSymbolAddress((void**)&px,    g_x);
    cudaGetSymbolAddress((void**)&ph0,   g_h0);
    cudaGetSymbolAddress((void**)&phl,   g_hl_);
    cudaGetSymbolAddress((void**)&pxg,   g_xg);
    cudaGetSymbolAddress((void**)&pS,    g_S);
    cudaGetSymbolAddress((void**)&pxyz0, g_xyz0);
    cudaGetSymbolAddress((void**)&pxyz1, g_xyz1);
    cudaGetSymbolAddress((void**)&pxs,   g_xs_);
    cudaGetSymbolAddress((void**)&pys,   g_ys_);
    cudaGetSymbolAddress((void**)&pzs,   g_zs_);
    cudaGetSymbolAddress((void**)&ppart, g_part);
    cudaGetSymbolAddress((void**)&pqkvb, g_qkvb);
    cudaGetSymbolAddress((void**)&pxh,   g_xh);
    cudaGetSymbolAddress((void**)&pxl,   g_xl);
    cudaGetSymbolAddress((void**)&pfeath,g_feath);
    cudaGetSymbolAddress((void**)&pfeatl,g_featl);
    cudaGetSymbolAddress((void**)&psuph, g_suph);
    cudaGetSymbolAddress((void**)&psupl, g_supl);
    cudaGetSymbolAddress((void**)&phmsh, g_hmsh);
    cudaGetSymbolAddress((void**)&phmsl, g_hmsl);
    cudaGetSymbolAddress((void**)&pqh,   g_qh);
    cudaGetSymbolAddress((void**)&pql,   g_ql);
    cudaGetSymbolAddress((void**)&pkh,   g_kh);
    cudaGetSymbolAddress((void**)&pvth,  g_vth);
    cudaGetSymbolAddress((void**)&psh,   g_sh);
    cudaGetSymbolAddress((void**)&pfcWth,  g_fcWth);
    cudaGetSymbolAddress((void**)&pgatWth, g_gatWth);
    cudaGetSymbolAddress((void**)&pgcWth,  g_gcWth);
    cudaGetSymbolAddress((void**)&pqkvWth, g_qkvWth);
    cudaGetSymbolAddress((void**)&poWth,   g_oWth);

    detect_mask_mode<<<1, 1>>>((const unsigned int*)dmask);

    wsplit<<<(FEAT_*HID_)/256, 256>>>(fcW, pfcWth, FEAT_, HID_, FEAT_*HID_);
    wsplit<<<(4*HID_*HID_)/256, 256>>>(gatW, pgatWth, HID_, HID_, HID_*HID_);
    wsplit<<<(4*2*HID_*HID_)/256, 256>>>(gcW, pgcWth, 2*HID_, HID_, 2*HID_*HID_);
    wsplit<<<(4*HID_*HID_)/256, 256>>>(oW, poWth, HID_, HID_, HID_*HID_);
    wsplit_ro<<<(4*HID_*HID_)/256, 256>>>(qW, pqkvWth, 0);
    wsplit_ro<<<(4*HID_*HID_)/256, 256>>>(kW, pqkvWth, 256);
    wsplit_ro<<<(4*HID_*HID_)/256, 256>>>(vW, pqkvWth, 512);
    qkvbias<<<12, 256>>>(qb_, kb_, vb_, pqkvb);
    split_hf<<<(N_*FEAT_/4)/256, 256>>>(feat, pfeath, pfeatl);

    gemm_tc64<<<dim3(HID_/64, N_/64), 256>>>(pfeath, pfeatl, pfcWth, FEAT_, HID_,
                                             fcb, 1, 1.0f, nullptr,0.f, nullptr,0.f, nullptr,0.f,
                                             px, ph0, pxh, pxl);

    zero_cnt<<<N_/256, 256>>>();
    count_edges<<<E_/256, 256>>>(dst);
    scan4096<<<1, 1024>>>();
    scatter_edges<<<E_/256, 256>>>(src, dst);

    const float ALPHA = 0.1f, LAMDA = 0.5f;
    for (int l = 0; l < 4; l++) {
        gemm_tc64<<<dim3(HID_/64, N_/64), 256>>>(pxh, pxl, pgatWth + (size_t)l*HID_*HID_,
                                                 HID_, HID_,
                                                 nullptr, 0, 1.0f, nullptr,0.f, nullptr,0.f, nullptr,0.f,
                                                 phl, nullptr, nullptr, nullptr);
        compute_elr<<<(N_*4)/256, 256>>>(phl, al + l*4*64, ar + l*4*64);
        gat_aggregate<<<N_/8, 256>>>(phl, pxg);
        pack_support<<<(N_*512)/256, 256>>>(pxg, ph0, psuph, psupl);
        float theta = fminf(1.0f, logf(LAMDA / (float)(l + 1) + 1.0f));
        gemm_tc64<<<dim3(HID_/64, N_/64), 256>>>(psuph, psupl, pgcWth + (size_t)l*2*HID_*HID_,
                                                 2*HID_, HID_,
                                                 nullptr, 0, theta,
                                                 pxg, (1.0f-theta)*(1.0f-ALPHA),
                                                 ph0, (1.0f-theta)*ALPHA,
                                                 px,  1.0f,
                                                 px, nullptr, pxh, pxl);
    }

    yhat_k<<<N_/256, 256>>>(px, cgW, cgb);

    const float* xyz_cur = xyz_in;
    float* xyz_buf[2] = { pxyz0, pxyz1 };
    for (int l = 0; l < 4; l++) {
        qkv_tc<<<dim3(768/64, N_/128), 256>>>(pxh, pxl,
                                              pqkvWth + (size_t)l*768*HID_,
                                              pqkvb + l*768,
                                              pqh, pql, pkh, pvth);
        scores_mma<<<dim3(N_/128, N_/128), 256>>>(pqh, pql, pkh,
                                                  xyz_cur, dmask, bmask, pS);
        xyz2soa<<<N_/256, 256>>>(xyz_cur, pxs, pys, pzs);
        softmax_xyz<<<N_, 256>>>(pS, psh, pxs, pys, pzs, xyz_buf[l & 1]);
        attnv_mma<<<dim3(HID_/128, N_/128, KZ_), 256>>>(psh, pvth, ppart);
        combine_parts<<<(N_*HID_/4)/256, 256>>>(ppart, phmsh, phmsl);
        gemm_tc64<<<dim3(HID_/64, N_/64), 256>>>(phmsh, phmsl, poWth + (size_t)l*HID_*HID_,
                                                 HID_, HID_,
                                                 ob + l*HID_, 0, 1.0f,
                                                 px, 1.0f, nullptr,0.f, nullptr,0.f,
                                                 px, nullptr, pxh, pxl);
        xyz_cur = xyz_buf[l & 1];
    }

    cls_k<<<N_/256, 256>>>(px, clsW, clsb, (float*)d_out);
}

// round 14
// speedup vs baseline: 2.6132x; 1.2575x over previous
#include <cuda_runtime.h>
#include <cuda_fp16.h>
#include <math.h>
#include <stdint.h>

#define N_    4096
#define E_    131072
#define FEAT_ 64
#define HID_  256
#define NEG_  (-1e9f)
#define KZ_   4

typedef __half hf;

// ---------------- scratch ----------------
__device__ float g_h0 [N_*HID_];
__device__ float g_x  [N_*HID_];
__device__ float g_hl_[N_*HID_];
__device__ float g_xg [N_*HID_];
__device__ float g_part[(size_t)KZ_*N_*HID_];
__device__ float g_S  [(size_t)N_*N_];
__device__ uint32_t g_mb[(size_t)N_*N_/32];
__device__ hf g_xh[N_*HID_], g_xl[N_*HID_];
__device__ hf g_feath[N_*FEAT_], g_featl[N_*FEAT_];
__device__ hf g_suph[N_*2*HID_], g_supl[N_*2*HID_];
__device__ hf g_hmsh[N_*HID_], g_hmsl[N_*HID_];
__device__ hf g_qh[N_*HID_];
__device__ hf g_kh[N_*HID_];
__device__ hf g_vth[HID_*N_];
__device__ hf g_sh[(size_t)N_*N_];
__device__ hf g_fcWth[HID_*FEAT_];
__device__ hf g_gatWth[4*HID_*HID_];
__device__ hf g_gcWth[4*HID_*2*HID_];
__device__ hf g_qkvWth[4*768*HID_];
__device__ float g_qkvb[4*768];
__device__ hf g_oWth[4*HID_*HID_];
__device__ float g_el [N_*4];
__device__ float g_er [N_*4];
__device__ float g_y  [N_];
__device__ float g_xyz0[N_*3];
__device__ float g_xyz1[N_*3];
__device__ float g_xs_[N_], g_ys_[N_], g_zs_[N_];
__device__ int   g_cnt[N_];
__device__ int   g_rowptr[N_+1];
__device__ int   g_cur[N_];
__device__ int   g_psrc[E_];
__device__ int   g_maskmode;

// ---------------- helpers ----------------
__device__ __forceinline__ uint32_t smem_u32(const void* p) {
    uint32_t a;
    asm("{ .reg .u64 t; cvta.to.shared.u64 t, %1; cvt.u32.u64 %0, t; }" : "=r"(a) : "l"(p));
    return a;
}
#define LDMX4(r, a) \
    asm volatile("ldmatrix.sync.aligned.m8n8.x4.shared.b16 {%0,%1,%2,%3}, [%4];" \
        : "=r"((r)[0]), "=r"((r)[1]), "=r"((r)[2]), "=r"((r)[3]) : "r"(a))
#define MMA16816(c, a, b0, b1) \
    asm volatile("mma.sync.aligned.m16n8k16.row.col.f32.f16.f16.f32 " \
        "{%0,%1,%2,%3}, {%4,%5,%6,%7}, {%8,%9}, {%0,%1,%2,%3};" \
        : "+f"((c)[0]), "+f"((c)[1]), "+f"((c)[2]), "+f"((c)[3]) \
        : "r"((a)[0]), "r"((a)[1]), "r"((a)[2]), "r"((a)[3]), "r"(b0), "r"(b1))

__device__ __forceinline__ void split1h(float v, hf& h, hf& l) {
    h = __float2half_rn(v);
    l = __float2half_rn(v - __half2float(h));
}

__device__ __forceinline__ float fast_exp(float x) {
    float t = x * 1.4426950408889634f;
    t = fmaxf(t, -126.0f);
    float z = t + 12582912.0f;
    float n = z - 12582912.0f;
    float f = t - n;
    float p = 1.5404e-4f;
    p = fmaf(p, f, 1.33336e-3f);
    p = fmaf(p, f, 9.61813e-3f);
    p = fmaf(p, f, 5.550411e-2f);
    p = fmaf(p, f, 2.4022651e-1f);
    p = fmaf(p, f, 6.9314718e-1f);
    p = fmaf(p, f, 1.0f);
    int ni = __float_as_int(z) - 0x4B400000;
    float sc = __int_as_float((ni + 127) << 23);
    return p * sc;
}

__global__ void detect_mask_mode(const unsigned int* __restrict__ m) {
    bool allbin = true, anyfloat = false;
    for (int i = 0; i < 1024; i++) {
        unsigned int w = m[i];
        if (w == 0x3f800000u) anyfloat = true;
        if (w > 1u) allbin = false;
    }
    g_maskmode = anyfloat ? 2 : (allbin ? 1 : 0);
}
__device__ __forceinline__ bool mask_at(const void* p, size_t i, int mode) {
    if (mode == 0) return ((const unsigned char*)p)[i] != 0;
    if (mode == 1) return ((const int*)p)[i] != 0;
    return ((const float*)p)[i] != 0.0f;
}

// pack combined mask into bits (one word = 32 consecutive j for fixed i)
__global__ void maskpack(const void* __restrict__ dmask, const void* __restrict__ bmask,
                         uint32_t* __restrict__ out)
{
    int w = blockIdx.x * 256 + threadIdx.x;
    const int mode = g_maskmode;
    const size_t base = (size_t)w * 32;
    uint32_t bits = 0;
#pragma unroll 4
    for (int e = 0; e < 32; e++)
        if (mask_at(dmask, base + e, mode) && mask_at(bmask, base + e, mode))
            bits |= (1u << e);
    out[w] = bits;
}

__global__ void split_hf(const float* __restrict__ X, hf* __restrict__ Xh, hf* __restrict__ Xl)
{
    int i = blockIdx.x * blockDim.x + threadIdx.x;
    float4 x = *(const float4*)&X[(size_t)i*4];
    float xv[4] = {x.x, x.y, x.z, x.w};
    __align__(8) hf h[4], l[4];
#pragma unroll
    for (int e = 0; e < 4; e++) split1h(xv[e], h[e], l[e]);
    *(uint2*)&Xh[(size_t)i*4] = *(uint2*)h;
    *(uint2*)&Xl[(size_t)i*4] = *(uint2*)l;
}

__global__ void wsplit(const float* __restrict__ W, hf* __restrict__ Wth,
                       int K, int N, int KN)
{
    int idx = blockIdx.x * 256 + threadIdx.x;
    int mat = idx / KN;
    int rem = idx - mat * KN;
    int k = rem / N;
    int n = rem - k * N;
    Wth[mat * KN + n * K + k] = __float2half_rn(W[idx]);
}

__global__ void wsplit_ro(const float* __restrict__ W, hf* __restrict__ Wth, int ro)
{
    int idx = blockIdx.x * 256 + threadIdx.x;
    int l = idx >> 16;
    int rem = idx & 65535;
    int k = rem >> 8, n = rem & 255;
    Wth[(size_t)l * 768 * HID_ + (size_t)(ro + n) * HID_ + k] = __float2half_rn(W[idx]);
}

__global__ void qkvbias(const float* __restrict__ qb, const float* __restrict__ kb,
                        const float* __restrict__ vb, float* __restrict__ out)
{
    int idx = blockIdx.x * 256 + threadIdx.x;
    if (idx >= 4*768) return;
    int l = idx / 768, c = idx % 768;
    int sect = c >> 8, cc = c & 255;
    out[idx] = (sect == 0) ? qb[l*256+cc] : (sect == 1) ? kb[l*256+cc] : vb[l*256+cc];
}

// ================= gemm_tc64: 64x64 tile fp16-mma, 2-pass (A split, B single) ===========
__global__ __launch_bounds__(256) void gemm_tc64(
    const hf* __restrict__ Ah, const hf* __restrict__ Al,
    const hf* __restrict__ Bh,
    int K, int Nc,
    const float* __restrict__ bias, int relu, float cacc,
    const float* __restrict__ X1, float c1,
    const float* __restrict__ X2, float c2,
    const float* __restrict__ X3, float c3,
    float* __restrict__ C, float* __restrict__ C2,
    hf* __restrict__ Ch, hf* __restrict__ Cl)
{
    __shared__ __align__(16) char Ash[2][64*80];
    __shared__ __align__(16) char Bsh[2][64*80];
    const int t = threadIdx.x, lane = t & 31, wid = t >> 5;
    const int wr32 = (wid >> 2) * 32, wc16 = (wid & 3) * 16;
    const int g = lane >> 2, tg = lane & 3;
    const int a_r = ((lane >> 3) & 1) * 8 + (lane & 7);
    const int a_c = (lane >> 4) * 16;
    const int b_r = ((lane >> 4) & 1) * 8 + (lane & 7);
    const int b_c = ((lane >> 3) & 1) * 16;
    const int m0 = blockIdx.y * 64, n0 = blockIdx.x * 64;
    const int lrow = t >> 2, lq = t & 3;

    uint32_t aS[2] = { smem_u32(Ash[0]), smem_u32(Ash[1]) };
    uint32_t bS[2] = { smem_u32(Bsh[0]), smem_u32(Bsh[1]) };
    float acc[2][2][4] = {};

    const hf* APs[2] = { Ah, Al };
    const int chunks = K >> 5;
    const int NC = 2 * chunks;

    uint4 va = *(const uint4*)(APs[0] + (size_t)(m0+lrow)*K + lq*8);
    uint4 vb = *(const uint4*)(Bh + (size_t)(n0+lrow)*K + lq*8);
    *(uint4*)(Ash[0] + lrow*80 + lq*16) = va;
    *(uint4*)(Bsh[0] + lrow*80 + lq*16) = vb;
    __syncthreads();

    int pn = 0, kn = 0;
    for (int c = 0; c < NC; c++) {
        const int buf = c & 1;
        const bool more = (c + 1 < NC);
        if (more) {
            kn++; if (kn == chunks) { kn = 0; pn++; }
            va = *(const uint4*)(APs[pn] + (size_t)(m0+lrow)*K + kn*32 + lq*8);
            vb = *(const uint4*)(Bh + (size_t)(n0+lrow)*K + kn*32 + lq*8);
        }
#pragma unroll
        for (int kk = 0; kk < 2; kk++) {
            uint32_t af[2][4], bfr[4];
#pragma unroll
            for (int mt = 0; mt < 2; mt++) {
                uint32_t ad = aS[buf] + (uint32_t)((wr32 + mt*16 + a_r)*80 + kk*32 + a_c);
                LDMX4(af[mt], ad);
            }
            {
                uint32_t bd = bS[buf] + (uint32_t)((wc16 + b_r)*80 + kk*32 + b_c);
                LDMX4(bfr, bd);
            }
#pragma unroll
            for (int mt = 0; mt < 2; mt++)
#pragma unroll
                for (int nt = 0; nt < 2; nt++)
                    MMA16816(acc[mt][nt], af[mt], bfr[nt*2], bfr[nt*2+1]);
        }
        if (more) {
            const int nb = buf ^ 1;
            *(uint4*)(Ash[nb] + lrow*80 + lq*16) = va;
            *(uint4*)(Bsh[nb] + lrow*80 + lq*16) = vb;
            __syncthreads();
        }
    }

#pragma unroll
    for (int mt = 0; mt < 2; mt++) {
#pragma unroll
        for (int h = 0; h < 2; h++) {
            const int m = m0 + wr32 + mt*16 + g + 8*h;
            const size_t rb = (size_t)m * Nc;
#pragma unroll
            for (int nt = 0; nt < 2; nt++) {
                const int n = n0 + wc16 + nt*8 + 2*tg;
                float2 r = { acc[mt][nt][h*2], acc[mt][nt][h*2+1] };
                r.x *= cacc; r.y *= cacc;
                if (bias) { r.x += bias[n]; r.y += bias[n+1]; }
                if (X1) { float2 q = *(const float2*)&X1[rb+n];
                          r.x = fmaf(c1,q.x,r.x); r.y = fmaf(c1,q.y,r.y); }
                if (X2) { float2 q = *(const float2*)&X2[rb+n];
                          r.x = fmaf(c2,q.x,r.x); r.y = fmaf(c2,q.y,r.y); }
                if (X3) { float2 q = *(const float2*)&X3[rb+n];
                          r.x = fmaf(c3,q.x,r.x); r.y = fmaf(c3,q.y,r.y); }
                if (relu) { r.x = fmaxf(r.x, 0.f); r.y = fmaxf(r.y, 0.f); }
                if (C)  *(float2*)&C[rb+n]  = r;
                if (C2) *(float2*)&C2[rb+n] = r;
                if (Ch) {
                    __align__(4) hf h2[2], l2[2];
                    split1h(r.x, h2[0], l2[0]); split1h(r.y, h2[1], l2[1]);
                    *(uint32_t*)&Ch[rb+n] = *(uint32_t*)h2;
                    *(uint32_t*)&Cl[rb+n] = *(uint32_t*)l2;
                }
            }
        }
    }
}

// ================= qkv_tc: fused QKV GEMM, tile 128x64, Nc=768 routed =================
__global__ __launch_bounds__(256) void qkv_tc(
    const hf* __restrict__ Ah, const hf* __restrict__ Al,
    const hf* __restrict__ Bh,
    const float* __restrict__ bias,
    hf* __restrict__ Qh, hf* __restrict__ Kh, hf* __restrict__ Vth)
{
    __shared__ __align__(16) char Ash[2][128*80];
    __shared__ __align__(16) char Bsh[2][64*80];
    const int t = threadIdx.x, lane = t & 31, wid = t >> 5;
    const int wr32 = (wid >> 1) * 32, wc32 = (wid & 1) * 32;
    const int g = lane >> 2, tg = lane & 3;
    const int a_r = ((lane >> 3) & 1) * 8 + (lane & 7);
    const int a_c = (lane >> 4) * 16;
    const int b_r = ((lane >> 4) & 1) * 8 + (lane & 7);
    const int b_c = ((lane >> 3) & 1) * 16;
    const int m0 = blockIdx.y * 128, n0 = blockIdx.x * 64;
    const int K = HID_;

    uint32_t aS[2] = { smem_u32(Ash[0]), smem_u32(Ash[1]) };
    uint32_t bS[2] = { smem_u32(Bsh[0]), smem_u32(Bsh[1]) };
    float acc[2][4][4] = {};

    const hf* APs[2] = { Ah, Al };
    const int chunks = K >> 5;
    const int NC = 2 * chunks;

    uint4 va[2], vb;
#pragma unroll
    for (int i = 0; i < 2; i++) {
        int idx = t + i*256, row = idx >> 2, q = idx & 3;
        va[i] = *(const uint4*)(APs[0] + (size_t)(m0+row)*K + q*8);
    }
    { int row = t >> 2, q = t & 3;
      vb = *(const uint4*)(Bh + (size_t)(n0+row)*K + q*8); }
#pragma unroll
    for (int i = 0; i < 2; i++) {
        int idx = t + i*256, row = idx >> 2, q = idx & 3;
        *(uint4*)(Ash[0] + row*80 + q*16) = va[i];
    }
    { int row = t >> 2, q = t & 3;
      *(uint4*)(Bsh[0] + row*80 + q*16) = vb; }
    __syncthreads();

    int pn = 0, kn = 0;
    for (int c = 0; c < NC; c++) {
        const int buf = c & 1;
        const bool more = (c + 1 < NC);
        if (more) {
            kn++; if (kn == chunks) { kn = 0; pn++; }
#pragma unroll
            for (int i = 0; i < 2; i++) {
                int idx = t + i*256, row = idx >> 2, q = idx & 3;
                va[i] = *(const uint4*)(APs[pn] + (size_t)(m0+row)*K + kn*32 + q*8);
            }
            { int row = t >> 2, q = t & 3;
              vb = *(const uint4*)(Bh + (size_t)(n0+row)*K + kn*32 + q*8); }
        }
#pragma unroll
        for (int kk = 0; kk < 2; kk++) {
            uint32_t af[2][4], bfr[2][4];
#pragma unroll
            for (int mt = 0; mt < 2; mt++) {
                uint32_t ad = aS[buf] + (uint32_t)((wr32 + mt*16 + a_r)*80 + kk*32 + a_c);
                LDMX4(af[mt], ad);
            }
#pragma unroll
            for (int np = 0; np < 2; np++) {
                uint32_t bd = bS[buf] + (uint32_t)((wc32 + np*16 + b_r)*80 + kk*32 + b_c);
                LDMX4(bfr[np], bd);
            }
#pragma unroll
            for (int mt = 0; mt < 2; mt++)
#pragma unroll
                for (int nt = 0; nt < 4; nt++)
                    MMA16816(acc[mt][nt], af[mt], bfr[nt>>1][(nt&1)*2], bfr[nt>>1][(nt&1)*2+1]);
        }
        if (more) {
            const int nb = buf ^ 1;
#pragma unroll
            for (int i = 0; i < 2; i++) {
                int idx = t + i*256, row = idx >> 2, q = idx & 3;
                *(uint4*)(Ash[nb] + row*80 + q*16) = va[i];
            }
            { int row = t >> 2, q = t & 3;
              *(uint4*)(Bsh[nb] + row*80 + q*16) = vb; }
            __syncthreads();
        }
    }

#pragma unroll
    for (int mt = 0; mt < 2; mt++) {
#pragma unroll
        for (int h = 0; h < 2; h++) {
            const int m = m0 + wr32 + mt*16 + g + 8*h;
#pragma unroll
            for (int nt = 0; nt < 4; nt++) {
                const int n = n0 + wc32 + nt*8 + 2*tg;
                float2 r = { acc[mt][nt][h*2], acc[mt][nt][h*2+1] };
                r.x += bias[n]; r.y += bias[n+1];
                const int sect = n >> 8, cc = n & 255;
                if (sect == 0) {
                    __align__(4) hf hh[2] = { __float2half_rn(r.x), __float2half_rn(r.y) };
                    *(uint32_t*)&Qh[(size_t)m*HID_ + cc] = *(uint32_t*)hh;
                } else if (sect == 1) {
                    __align__(4) hf hh[2] = { __float2half_rn(r.x), __float2half_rn(r.y) };
                    *(uint32_t*)&Kh[(size_t)m*HID_ + cc] = *(uint32_t*)hh;
                } else {
                    Vth[(size_t)cc * N_ + m]     = __float2half_rn(r.x);
                    Vth[(size_t)(cc+1) * N_ + m] = __float2half_rn(r.y);
                }
            }
        }
    }
}

// ---- shared mma-core macro (128x128 kernels) ----
#define COMPUTE32(abase, bbase)                                                     \
    _Pragma("unroll")                                                               \
    for (int kk = 0; kk < 2; kk++) {                                                \
        uint32_t af[4][4], bfr[2][4];                                               \
        _Pragma("unroll")                                                           \
        for (int mt = 0; mt < 4; mt++) {                                            \
            uint32_t ad = (abase) + (uint32_t)((wr64 + mt*16 + a_r)*80 + kk*32 + a_c); \
            LDMX4(af[mt], ad);                                                      \
        }                                                                           \
        _Pragma("unroll")                                                           \
        for (int np = 0; np < 2; np++) {                                            \
            uint32_t bd = (bbase) + (uint32_t)((wc32 + np*16 + b_r)*80 + kk*32 + b_c); \
            LDMX4(bfr[np], bd);                                                     \
        }                                                                           \
        _Pragma("unroll")                                                           \
        for (int mt = 0; mt < 4; mt++)                                              \
            _Pragma("unroll")                                                       \
            for (int nt = 0; nt < 4; nt++)                                          \
                MMA16816(acc[mt][nt], af[mt], bfr[nt>>1][(nt&1)*2], bfr[nt>>1][(nt&1)*2+1]); \
    }

// ================= scores via fp16 mma, single pass (q single, k single) =================
__global__ __launch_bounds__(256) void scores_mma(
    const hf* __restrict__ qh, const hf* __restrict__ kh,
    const float* __restrict__ xyz,
    const uint32_t* __restrict__ Mb,
    float* __restrict__ S)
{
    __shared__ __align__(16) char Ash[2][128*80];
    __shared__ __align__(16) char Bsh[2][128*80];
    __shared__ float gix[128*3], gisq[128], giy[128];
    __shared__ float gjx[128*3], gjsq[128], gjy[128];
    const int t = threadIdx.x, lane = t & 31, wid = t >> 5;
    const int wr64 = (wid >> 2) * 64, wc32 = (wid & 3) * 32;
    const int g = lane >> 2, tg = lane & 3;
    const int a_r = ((lane >> 3) & 1) * 8 + (lane & 7);
    const int a_c = (lane >> 4) * 16;
    const int b_r = ((lane >> 4) & 1) * 8 + (lane & 7);
    const int b_c = ((lane >> 3) & 1) * 16;
    const int i0 = blockIdx.y * 128, j0 = blockIdx.x * 128;
    const int lrow = t >> 2, lq = t & 3;

    if (t < 128) {
        float a = xyz[(i0+t)*3+0], b = xyz[(i0+t)*3+1], c = xyz[(i0+t)*3+2];
        gix[t*3+0]=a; gix[t*3+1]=b; gix[t*3+2]=c;
        gisq[t] = fmaf(c,c,fmaf(b,b,a*a));
        giy[t]  = g_y[i0+t];
    } else {
        int u = t - 128;
        float a = xyz[(j0+u)*3+0], b = xyz[(j0+u)*3+1], c = xyz[(j0+u)*3+2];
        gjx[u*3+0]=a; gjx[u*3+1]=b; gjx[u*3+2]=c;
        gjsq[u] = fmaf(c,c,fmaf(b,b,a*a));
        gjy[u]  = g_y[j0+u];
    }

    uint32_t aS[2] = { smem_u32(Ash[0]), smem_u32(Ash[1]) };
    uint32_t bS[2] = { smem_u32(Bsh[0]), smem_u32(Bsh[1]) };
    float acc[4][4][4] = {};

    uint4 va[2], vb[2];
#pragma unroll
    for (int r = 0; r < 2; r++) {
        int row = lrow + r*64;
        va[r] = *(const uint4*)(qh + (size_t)(i0+row)*HID_ + lq*8);
        vb[r] = *(const uint4*)(kh + (size_t)(j0+row)*HID_ + lq*8);
    }
#pragma unroll
    for (int r = 0; r < 2; r++) {
        int row = lrow + r*64;
        *(uint4*)(Ash[0] + row*80 + lq*16) = va[r];
        *(uint4*)(Bsh[0] + row*80 + lq*16) = vb[r];
    }
    __syncthreads();

    const int NC = 8;   // single pass, K=256
    for (int c = 0; c < NC; c++) {
        const int buf = c & 1;
        if (c + 1 < NC) {
            const int kc = c + 1;
#pragma unroll
            for (int r = 0; r < 2; r++) {
                int row = lrow + r*64;
                va[r] = *(const uint4*)(qh + (size_t)(i0+row)*HID_ + kc*32 + lq*8);
                vb[r] = *(const uint4*)(kh + (size_t)(j0+row)*HID_ + kc*32 + lq*8);
            }
        }
        COMPUTE32(aS[buf], bS[buf]);
        if (c + 1 < NC) {
            const int nb = buf ^ 1;
#pragma unroll
            for (int r = 0; r < 2; r++) {
                int row = lrow + r*64;
                *(uint4*)(Ash[nb] + row*80 + lq*16) = va[r];
                *(uint4*)(Bsh[nb] + row*80 + lq*16) = vb[r];
            }
            __syncthreads();
        }
    }

#pragma unroll
    for (int mt = 0; mt < 4; mt++) {
#pragma unroll
        for (int h = 0; h < 2; h++) {
            const int li = wr64 + mt*16 + g + 8*h;
            const int gi = i0 + li;
            const float xa = gix[li*3], xbv = gix[li*3+1], xc = gix[li*3+2];
            const float sqa = gisq[li], ya = giy[li];
            const size_t rb = (size_t)gi * N_;
            // one 32-bit mask word covers this warp's 32 columns for row gi
            const uint32_t wbits = Mb[(size_t)gi * (N_/32) + ((j0 + wc32) >> 5)];
#pragma unroll
            for (int nt = 0; nt < 4; nt++) {
                const int lj0 = wc32 + nt*8 + 2*tg;
                float2 r;
#pragma unroll
                for (int e = 0; e < 2; e++) {
                    const int lj = lj0 + e;
                    const int bitpos = nt*8 + 2*tg + e;
                    float dot = fmaf(xc, gjx[lj*3+2], fmaf(xbv, gjx[lj*3+1], xa * gjx[lj*3]));
                    float dist2 = (sqa + gjsq[lj]) - 2.0f * dot;
                    bool ok = ((wbits >> bitpos) & 1u) && (dist2 <= 100.0f);
                    float av = acc[mt][nt][h*2 + e];
                    ((float*)&r)[e] = ok ? (av * 0.0625f - fabsf(ya - gjy[lj])) : NEG_;
                }
                *(float2*)&S[rb + j0 + lj0] = r;
            }
        }
    }
}

// ================= attn@V via fp16 mma, single-pass, split-K z ======
__global__ __launch_bounds__(256) void attnv_mma(
    const hf* __restrict__ Sh,
    const hf* __restrict__ Vth,
    float* __restrict__ Cpart)
{
    __shared__ __align__(16) char Ash[2][128*80];
    __shared__ __align__(16) char Bsh[2][128*80];
    const int t = threadIdx.x, lane = t & 31, wid = t >> 5;
    const int wr64 = (wid >> 2) * 64, wc32 = (wid & 3) * 32;
    const int g = lane >> 2, tg = lane & 3;
    const int a_r = ((lane >> 3) & 1) * 8 + (lane & 7);
    const int a_c = (lane >> 4) * 16;
    const int b_r = ((lane >> 4) & 1) * 8 + (lane & 7);
    const int b_c = ((lane >> 3) & 1) * 16;
    const int m0 = blockIdx.y * 128, n0 = blockIdx.x * 128;
    const int kbase = blockIdx.z * (N_ / KZ_);
    const int lrow = t >> 2, lq = t & 3;

    uint32_t aS[2] = { smem_u32(Ash[0]), smem_u32(Ash[1]) };
    uint32_t bS[2] = { smem_u32(Bsh[0]), smem_u32(Bsh[1]) };
    float acc[4][4][4] = {};

    const int NC = (N_ / KZ_) / 32;

    uint4 va[2], vb[2];
#pragma unroll
    for (int r = 0; r < 2; r++) {
        int row = lrow + r*64;
        va[r] = *(const uint4*)(Sh + (size_t)(m0+row)*N_ + kbase + lq*8);
        vb[r] = *(const uint4*)(Vth + (size_t)(n0+row)*N_ + kbase + lq*8);
    }
#pragma unroll
    for (int r = 0; r < 2; r++) {
        int row = lrow + r*64;
        *(uint4*)(Ash[0] + row*80 + lq*16) = va[r];
        *(uint4*)(Bsh[0] + row*80 + lq*16) = vb[r];
    }
    __syncthreads();

    for (int c = 0; c < NC; c++) {
        const int buf = c & 1;
        if (c + 1 < NC) {
            const int kc = c + 1;
#pragma unroll
            for (int r = 0; r < 2; r++) {
                int row = lrow + r*64;
                va[r] = *(const uint4*)(Sh + (size_t)(m0+row)*N_ + kbase + kc*32 + lq*8);
                vb[r] = *(const uint4*)(Vth + (size_t)(n0+row)*N_ + kbase + kc*32 + lq*8);
            }
        }
        COMPUTE32(aS[buf], bS[buf]);
        if (c + 1 < NC) {
            const int nb = buf ^ 1;
#pragma unroll
            for (int r = 0; r < 2; r++) {
                int row = lrow + r*64;
                *(uint4*)(Ash[nb] + row*80 + lq*16) = va[r];
                *(uint4*)(Bsh[nb] + row*80 + lq*16) = vb[r];
            }
            __syncthreads();
        }
    }

    float* Cz = Cpart + (size_t)blockIdx.z * N_ * HID_;
#pragma unroll
    for (int mt = 0; mt < 4; mt++) {
#pragma unroll
        for (int h = 0; h < 2; h++) {
            const int m = m0 + wr64 + mt*16 + g + 8*h;
            const size_t rb = (size_t)m * HID_;
#pragma unroll
            for (int nt = 0; nt < 4; nt++) {
                const int n = n0 + wc32 + nt*8 + 2*tg;
                float2 r = { acc[mt][nt][h*2], acc[mt][nt][h*2 + 1] };
                *(float2*)&Cz[rb + n] = r;
            }
        }
    }
}

__global__ void combine_parts(const float* __restrict__ P,
                              hf* __restrict__ Hh, hf* __restrict__ Hl)
{
    int i = blockIdx.x * blockDim.x + threadIdx.x;
    const size_t n = (size_t)N_ * HID_;
    float4 a = *(const float4*)&P[(size_t)i*4];
    float4 b = *(const float4*)&P[n + (size_t)i*4];
    float4 c = *(const float4*)&P[2*n + (size_t)i*4];
    float4 d = *(const float4*)&P[3*n + (size_t)i*4];
    float rv[4] = { a.x+b.x+c.x+d.x, a.y+b.y+c.y+d.y, a.z+b.z+c.z+d.z, a.w+b.w+c.w+d.w };
    __align__(8) hf hh[4], ll[4];
#pragma unroll
    for (int e = 0; e < 4; e++) split1h(rv[e], hh[e], ll[e]);
    *(uint2*)&Hh[(size_t)i*4] = *(uint2*)hh;
    *(uint2*)&Hl[(size_t)i*4] = *(uint2*)ll;
}

// ---------------- softmax + attn@xyz + fp16 store of attn ----------------
__global__ void softmax_xyz(const float* __restrict__ S,
                            hf* __restrict__ Sh,
                            const float* __restrict__ xs, const float* __restrict__ ys,
                            const float* __restrict__ zs, float* __restrict__ out)
{
    __shared__ float r0[256], r1[256], r2[256];
    const int row = blockIdx.x, t = threadIdx.x;
    const float* p = S + (size_t)row * N_;
    float4 v[4];
    float mx = -1e30f;
#pragma unroll
    for (int c = 0; c < 4; c++) {
        v[c] = *(const float4*)&p[c*1024 + t*4];
        mx = fmaxf(mx, fmaxf(fmaxf(v[c].x, v[c].y), fmaxf(v[c].z, v[c].w)));
    }
    r0[t] = mx; __syncthreads();
    for (int s = 128; s > 0; s >>= 1) { if (t < s) r0[t] = fmaxf(r0[t], r0[t+s]); __syncthreads(); }
    mx = r0[0]; __syncthreads();
    float sum = 0.0f;
#pragma unroll
    for (int c = 0; c < 4; c++) {
        v[c].x = fast_exp(v[c].x - mx); v[c].y = fast_exp(v[c].y - mx);
        v[c].z = fast_exp(v[c].z - mx); v[c].w = fast_exp(v[c].w - mx);
        sum += v[c].x + v[c].y + v[c].z + v[c].w;
    }
    r0[t] = sum; __syncthreads();
    for (int s = 128; s > 0; s >>= 1) { if (t < s) r0[t] += r0[t+s]; __syncthreads(); }
    const float inv = 1.0f / r0[0];
    __syncthreads();
    float a0 = 0.f, a1 = 0.f, a2 = 0.f;
#pragma unroll
    for (int c = 0; c < 4; c++) {
        v[c].x *= inv; v[c].y *= inv; v[c].z *= inv; v[c].w *= inv;
        float vv[4] = { v[c].x, v[c].y, v[c].z, v[c].w };
        __align__(8) hf vh[4];
#pragma unroll
        for (int e = 0; e < 4; e++) vh[e] = __float2half_rn(vv[e]);
        const size_t off = (size_t)row * N_ + c*1024 + t*4;
        *(uint2*)&Sh[off] = *(uint2*)vh;
        const int j = c*1024 + t*4;
        a0 = fmaf(v[c].x, xs[j], fmaf(v[c].y, xs[j+1], fmaf(v[c].z, xs[j+2], fmaf(v[c].w, xs[j+3], a0))));
        a1 = fmaf(v[c].x, ys[j], fmaf(v[c].y, ys[j+1], fmaf(v[c].z, ys[j+2], fmaf(v[c].w, ys[j+3], a1))));
        a2 = fmaf(v[c].x, zs[j], fmaf(v[c].y, zs[j+1], fmaf(v[c].z, zs[j+2], fmaf(v[c].w, zs[j+3], a2))));
    }
    r0[t]=a0; r1[t]=a1; r2[t]=a2; __syncthreads();
    for (int s = 128; s > 0; s >>= 1) {
        if (t < s) { r0[t]+=r0[t+s]; r1[t]+=r1[t+s]; r2[t]+=r2[t+s]; }
        __syncthreads();
    }
    if (t == 0) { out[row*3+0]=r0[0]; out[row*3+1]=r1[0]; out[row*3+2]=r2[0]; }
}

__global__ void xyz2soa(const float* __restrict__ xyz, float* __restrict__ xs,
                        float* __restrict__ ys, float* __restrict__ zs)
{
    int i = blockIdx.x * blockDim.x + threadIdx.x;
    if (i < N_) { xs[i] = xyz[3*i]; ys[i] = xyz[3*i+1]; zs[i] = xyz[3*i+2]; }
}

// ---------------- GAT pieces ----------------
__global__ void compute_elr(const float* __restrict__ hl, const float* __restrict__ al,
                            const float* __restrict__ ar)
{
    int idx = blockIdx.x * blockDim.x + threadIdx.x;
    if (idx >= N_*4) return;
    int node = idx >> 2, h = idx & 3;
    const float* row = hl + (size_t)node * HID_ + h * 64;
    float sl = 0.f, sr = 0.f;
#pragma unroll 8
    for (int d = 0; d < 64; d++) {
        float v = row[d];
        sl = fmaf(v, al[h*64+d], sl);
        sr = fmaf(v, ar[h*64+d], sr);
    }
    g_el[idx] = sl; g_er[idx] = sr;
}

__global__ void zero_cnt() { int i = blockIdx.x*blockDim.x + threadIdx.x; if (i < N_) g_cnt[i] = 0; }
__global__ void count_edges(const int* __restrict__ dst) {
    int e = blockIdx.x*blockDim.x + threadIdx.x; if (e < E_) atomicAdd(&g_cnt[dst[e]], 1);
}
__global__ void scan4096() {
    __shared__ int part[1024];
    int t = threadIdx.x, base = t * 4;
    int a0 = g_cnt[base], a1 = g_cnt[base+1], a2 = g_cnt[base+2], a3 = g_cnt[base+3];
    int s = a0 + a1 + a2 + a3;
    part[t] = s; __syncthreads();
    for (int off = 1; off < 1024; off <<= 1) {
        int v = (t >= off) ? part[t-off] : 0;
        __syncthreads();
        part[t] += v;
        __syncthreads();
    }
    int excl = part[t] - s;
    g_rowptr[base+0] = excl;           g_cur[base+0] = excl;
    g_rowptr[base+1] = excl+a0;        g_cur[base+1] = excl+a0;
    g_rowptr[base+2] = excl+a0+a1;     g_cur[base+2] = excl+a0+a1;
    g_rowptr[base+3] = excl+a0+a1+a2;  g_cur[base+3] = excl+a0+a1+a2;
    if (t == 1023) g_rowptr[4096] = part[1023];
}
__global__ void scatter_edges(const int* __restrict__ src, const int* __restrict__ dst) {
    int e = blockIdx.x*blockDim.x + threadIdx.x;
    if (e < E_) { int p = atomicAdd(&g_cur[dst[e]], 1); g_psrc[p] = src[e]; }
}

__global__ void gat_aggregate(const float* __restrict__ hl, float* __restrict__ xg)
{
    const int node = (blockIdx.x * blockDim.x + threadIdx.x) >> 5;
    const int lane = threadIdx.x & 31;
    if (node >= N_) return;
    const int beg = g_rowptr[node], end = g_rowptr[node+1];
    const float er_i = (lane < 4) ? g_er[node*4 + lane] : 0.f;
    float m = -1e30f;
    for (int p = beg; p < end; p++) {
        int s = g_psrc[p];
        if (lane < 4) {
            float v = g_el[s*4 + lane] + er_i;
            float e = (v > 0.f) ? v : 0.2f * v;
            m = fmaxf(m, e);
        }
    }
    float m0 = __shfl_sync(0xffffffffu, m, 0), m1 = __shfl_sync(0xffffffffu, m, 1);
    float m2 = __shfl_sync(0xffffffffu, m, 2), m3 = __shfl_sync(0xffffffffu, m, 3);
    const int myh = lane >> 3;
    float4 acc0 = {0,0,0,0}, acc1 = {0,0,0,0};
    float z = 0.f;
    for (int p = beg; p < end; p++) {
        int s = g_psrc[p];
        float w = 0.f;
        if (lane < 4) {
            float v = g_el[s*4 + lane] + er_i;
            float e = (v > 0.f) ? v : 0.2f * v;
            float mm = (lane==0)?m0:(lane==1)?m1:(lane==2)?m2:m3;
            w = fast_exp(e - mm);
            z += w;
        }
        float w0 = __shfl_sync(0xffffffffu, w, 0), w1 = __shfl_sync(0xffffffffu, w, 1);
        float w2 = __shfl_sync(0xffffffffu, w, 2), w3 = __shfl_sync(0xffffffffu, w, 3);
        float wm = (myh==0)?w0:(myh==1)?w1:(myh==2)?w2:w3;
        const float4* hp = (const float4*)(hl + (size_t)s * HID_ + lane * 8);
        float4 hv0 = hp[0], hv1 = hp[1];
        acc0.x=fmaf(wm,hv0.x,acc0.x); acc0.y=fmaf(wm,hv0.y,acc0.y);
        acc0.z=fmaf(wm,hv0.z,acc0.z); acc0.w=fmaf(wm,hv0.w,acc0.w);
        acc1.x=fmaf(wm,hv1.x,acc1.x); acc1.y=fmaf(wm,hv1.y,acc1.y);
        acc1.z=fmaf(wm,hv1.z,acc1.z); acc1.w=fmaf(wm,hv1.w,acc1.w);
    }
    float z0 = __shfl_sync(0xffffffffu, z, 0), z1 = __shfl_sync(0xffffffffu, z, 1);
    float z2 = __shfl_sync(0xffffffffu, z, 2), z3 = __shfl_sync(0xffffffffu, z, 3);
    float zm = (myh==0)?z0:(myh==1)?z1:(myh==2)?z2:z3;
    float inv = 1.0f / (zm + 1e-9f);
    acc0.x*=inv; acc0.y*=inv; acc0.z*=inv; acc0.w*=inv;
    acc1.x*=inv; acc1.y*=inv; acc1.z*=inv; acc1.w*=inv;
    float4* op = (float4*)(xg + (size_t)node * HID_ + lane * 8);
    op[0] = acc0; op[1] = acc1;
}

__global__ void pack_support(const float* __restrict__ xg, const float* __restrict__ h0,
                             hf* __restrict__ suph, hf* __restrict__ supl)
{
    int i = blockIdx.x * blockDim.x + threadIdx.x;
    if (i >= N_ * 512) return;
    int r = i >> 9, c = i & 511;
    float v = (c < 256) ? xg[(size_t)r*256 + c] : h0[(size_t)r*256 + (c-256)];
    hf h, l; split1h(v, h, l);
    suph[i] = h; supl[i] = l;
}

__global__ void yhat_k(const float* __restrict__ x, const float* __restrict__ W,
                       const float* __restrict__ b)
{
    int i = blockIdx.x * blockDim.x + threadIdx.x;
    if (i >= N_) return;
    const float* r = x + (size_t)i * HID_;
    float l0 = b[0], l1 = b[1];
#pragma unroll 8
    for (int d = 0; d < HID_; d++) {
        float v = r[d];
        l0 = fmaf(v, W[2*d+0], l0);
        l1 = fmaf(v, W[2*d+1], l1);
    }
    g_y[i] = 1.0f / (1.0f + expf(l0 - l1));
}

__global__ void cls_k(const float* __restrict__ x, const float* __restrict__ W,
                      const float* __restrict__ b, float* __restrict__ out)
{
    int i = blockIdx.x * blockDim.x + threadIdx.x;
    if (i >= N_) return;
    const float* r = x + (size_t)i * HID_;
    float l0 = b[0], l1 = b[1];
#pragma unroll 8
    for (int d = 0; d < HID_; d++) {
        float v = r[d];
        l0 = fmaf(v, W[2*d+0], l0);
        l1 = fmaf(v, W[2*d+1], l1);
    }
    out[2*i+0] = l0;
    out[2*i+1] = l1;
}

// ---------------- host orchestration ----------------
extern "C" void kernel_launch(void* const* d_in, const int* in_sizes, int n_in,
                              void* d_out, int out_size)
{
    const float* feat   = (const float*)d_in[0];
    const float* xyz_in = (const float*)d_in[1];
    const int*   src    = (const int*)  d_in[2];
    const int*   dst    = (const int*)  d_in[3];
    const void*  dmask  = d_in[4];
    const void*  bmask  = d_in[5];
    const float* fcW  = (const float*)d_in[6];
    const float* fcb  = (const float*)d_in[7];
    const float* gatW = (const float*)d_in[8];
    const float* al   = (const float*)d_in[9];
    const float* ar   = (const float*)d_in[10];
    const float* gcW  = (const float*)d_in[11];
    const float* cgW  = (const float*)d_in[12];
    const float* cgb  = (const float*)d_in[13];
    const float* qW   = (const float*)d_in[14];
    const float* qb_  = (const float*)d_in[15];
    const float* kW   = (const float*)d_in[16];
    const float* kb_  = (const float*)d_in[17];
    const float* vW   = (const float*)d_in[18];
    const float* vb_  = (const float*)d_in[19];
    const float* oW   = (const float*)d_in[20];
    const float* ob   = (const float*)d_in[21];
    const float* clsW = (const float*)d_in[22];
    const float* clsb = (const float*)d_in[23];

    float *px, *ph0, *phl, *pxg, *pS, *pxyz0, *pxyz1, *pxs, *pys, *pzs, *ppart, *pqkvb;
    uint32_t *pmb;
    hf *pxh, *pxl, *pfeath, *pfeatl, *psuph, *psupl, *phmsh, *phmsl;
    hf *pqh, *pkh, *pvth, *psh;
    hf *pfcWth, *pgatWth, *pgcWth, *pqkvWth, *poWth;
    cudaGetSymbolAddress((void**)&px,    g_x);
    cudaGetSymbolAddress((void**)&ph0,   g_h0);
    cudaGetSymbolAddress((void**)&phl,   g_hl_);
    cudaGetSymbolAddress((void**)&pxg,   g_xg);
    cudaGetSymbolAddress((void**)&pS,    g_S);
    cudaGetSymbolAddress((void**)&pmb,   g_mb);
    cudaGetSymbolAddress((void**)&pxyz0, g_xyz0);
    cudaGetSymbolAddress((void**)&pxyz1, g_xyz1);
    cudaGetSymbolAddress((void**)&pxs,   g_xs_);
    cudaGetSymbolAddress((void**)&pys,   g_ys_);
    cudaGetSymbolAddress((void**)&pzs,   g_zs_);
    cudaGetSymbolAddress((void**)&ppart, g_part);
    cudaGetSymbolAddress((void**)&pqkvb, g_qkvb);
    cudaGetSymbolAddress((void**)&pxh,   g_xh);
    cudaGetSymbolAddress((void**)&pxl,   g_xl);
    cudaGetSymbolAddress((void**)&pfeath,g_feath);
    cudaGetSymbolAddress((void**)&pfeatl,g_featl);
    cudaGetSymbolAddress((void**)&psuph, g_suph);
    cudaGetSymbolAddress((void**)&psupl, g_supl);
    cudaGetSymbolAddress((void**)&phmsh, g_hmsh);
    cudaGetSymbolAddress((void**)&phmsl, g_hmsl);
    cudaGetSymbolAddress((void**)&pqh,   g_qh);
    cudaGetSymbolAddress((void**)&pkh,   g_kh);
    cudaGetSymbolAddress((void**)&pvth,  g_vth);
    cudaGetSymbolAddress((void**)&psh,   g_sh);
    cudaGetSymbolAddress((void**)&pfcWth,  g_fcWth);
    cudaGetSymbolAddress((void**)&pgatWth, g_gatWth);
    cudaGetSymbolAddress((void**)&pgcWth,  g_gcWth);
    cudaGetSymbolAddress((void**)&pqkvWth, g_qkvWth);
    cudaGetSymbolAddress((void**)&poWth,   g_oWth);

    detect_mask_mode<<<1, 1>>>((const unsigned int*)dmask);
    maskpack<<<(N_*(N_/32))/256, 256>>>(dmask, bmask, pmb);

    wsplit<<<(FEAT_*HID_)/256, 256>>>(fcW, pfcWth, FEAT_, HID_, FEAT_*HID_);
    wsplit<<<(4*HID_*HID_)/256, 256>>>(gatW, pgatWth, HID_, HID_, HID_*HID_);
    wsplit<<<(4*2*HID_*HID_)/256, 256>>>(gcW, pgcWth, 2*HID_, HID_, 2*HID_*HID_);
    wsplit<<<(4*HID_*HID_)/256, 256>>>(oW, poWth, HID_, HID_, HID_*HID_);
    wsplit_ro<<<(4*HID_*HID_)/256, 256>>>(qW, pqkvWth, 0);
    wsplit_ro<<<(4*HID_*HID_)/256, 256>>>(kW, pqkvWth, 256);
    wsplit_ro<<<(4*HID_*HID_)/256, 256>>>(vW, pqkvWth, 512);
    qkvbias<<<12, 256>>>(qb_, kb_, vb_, pqkvb);
    split_hf<<<(N_*FEAT_/4)/256, 256>>>(feat, pfeath, pfeatl);

    gemm_tc64<<<dim3(HID_/64, N_/64), 256>>>(pfeath, pfeatl, pfcWth, FEAT_, HID_,
                                             fcb, 1, 1.0f, nullptr,0.f, nullptr,0.f, nullptr,0.f,
                                             px, ph0, pxh, pxl);

    zero_cnt<<<N_/256, 256>>>();
    count_edges<<<E_/256, 256>>>(dst);
    scan4096<<<1, 1024>>>();
    scatter_edges<<<E_/256, 256>>>(src, dst);

    const float ALPHA = 0.1f, LAMDA = 0.5f;
    for (int l = 0; l < 4; l++) {
        gemm_tc64<<<dim3(HID_/64, N_/64), 256>>>(pxh, pxl, pgatWth + (size_t)l*HID_*HID_,
                                                 HID_, HID_,
                                                 nullptr, 0, 1.0f, nullptr,0.f, nullptr,0.f, nullptr,0.f,
                                                 phl, nullptr, nullptr, nullptr);
        compute_elr<<<(N_*4)/256, 256>>>(phl, al + l*4*64, ar + l*4*64);
        gat_aggregate<<<N_/8, 256>>>(phl, pxg);
        pack_support<<<(N_*512)/256, 256>>>(pxg, ph0, psuph, psupl);
        float theta = fminf(1.0f, logf(LAMDA / (float)(l + 1) + 1.0f));
        gemm_tc64<<<dim3(HID_/64, N_/64), 256>>>(psuph, psupl, pgcWth + (size_t)l*2*HID_*HID_,
                                                 2*HID_, HID_,
                                                 nullptr, 0, theta,
                                                 pxg, (1.0f-theta)*(1.0f-ALPHA),
                                                 ph0, (1.0f-theta)*ALPHA,
                                                 px,  1.0f,
                                                 px, nullptr, pxh, pxl);
    }

    yhat_k<<<N_/256, 256>>>(px, cgW, cgb);

    const float* xyz_cur = xyz_in;
    float* xyz_buf[2] = { pxyz0, pxyz1 };
    for (int l = 0; l < 4; l++) {
        qkv_tc<<<dim3(768/64, N_/128), 256>>>(pxh, pxl,
                                              pqkvWth + (size_t)l*768*HID_,
                                              pqkvb + l*768,
                                              pqh, pkh, pvth);
        scores_mma<<<dim3(N_/128, N_/128), 256>>>(pqh, pkh, xyz_cur, pmb, pS);
        xyz2soa<<<N_/256, 256>>>(xyz_cur, pxs, pys, pzs);
        softmax_xyz<<<N_, 256>>>(pS, psh, pxs, pys, pzs, xyz_buf[l & 1]);
        attnv_mma<<<dim3(HID_/128, N_/128, KZ_), 256>>>(psh, pvth, ppart);
        combine_parts<<<(N_*HID_/4)/256, 256>>>(ppart, phmsh, phmsl);
        gemm_tc64<<<dim3(HID_/64, N_/64), 256>>>(phmsh, phmsl, poWth + (size_t)l*HID_*HID_,
                                                 HID_, HID_,
                                                 ob + l*HID_, 0, 1.0f,
                                                 px, 1.0f, nullptr,0.f, nullptr,0.f,
                                                 px, nullptr, pxh, pxl);
        xyz_cur = xyz_buf[l & 1];
    }

    cls_k<<<N_/256, 256>>>(px, clsW, clsb, (float*)d_out);
}